// round 2
// baseline (speedup 1.0000x reference)
#include <cuda_runtime.h>
#include <math.h>

// ---------------- constants ----------------
#define BB 2
#define SS 1024
#define DD 768
#define HH 12
#define HD 64
#define EE 8
#define FF 2048
#define CIN 512
#define TOK (BB*SS)          // 2048
#define FB 513
#define NFFT 1024
#define HOP 256
#define WINL 1024
#define PADL 384
#define OUTL 262144          // (1024-1)*256+1024 - 2*384
#define TWO_PI_N 0.006135923151542565f   // 2*pi/1024

// ---------------- scratch (device globals; allocation-free) ----------------
__device__ float g_zt[TOK*CIN];
__device__ float g_x [TOK*DD];
__device__ float g_h [TOK*DD];
__device__ float g_q [TOK*DD];
__device__ float g_k [TOK*DD];
__device__ float g_v [TOK*DD];
__device__ float g_ao[TOK*DD];
__device__ float g_scores[24u*1024u*1024u];
__device__ float g_hidden[4096*FF];
__device__ float g_yslot [4096*DD];
__device__ float g_Cb[1026*1024];
__device__ float g_Mt[DD*1024];
__device__ float g_bf[1024];
__device__ float g_frames[TOK*1024];
__device__ int   g_cnt[EE];
__device__ int   g_etok[EE*TOK];
__device__ int   g_easn[EE*TOK];
__device__ float g_wts[2*TOK];

// ---------------- generic tiled SGEMM ----------------
// C[z] = act(alpha * A[z] @ (B or B^T)[z] + bias) + res ; optional row gather/scatter
// z-offsets support a second stride pair (sAz2 applied per (z / zdiv), sAz per (z % zdiv))
template<int ACT, bool TRB>
__global__ void gemm_kernel(const float* __restrict__ A, int lda, long long sAz, long long sAz2,
                            const float* __restrict__ B, int ldb, long long sBz, long long sBz2,
                            float* __restrict__ C, int ldc, long long sCz, long long sCz2,
                            int zdiv,
                            const float* __restrict__ bias, long long sbz,
                            const float* __restrict__ res,
                            int M, int N, int Kd, float alpha,
                            const int* __restrict__ idxA, const int* __restrict__ idxC,
                            const int* __restrict__ cnt, int causal)
{
    int z = blockIdx.z;
    int z1 = z / zdiv, z0 = z - z1 * zdiv;
    if (cnt) M = cnt[z];
    int m0 = blockIdx.y * 64, n0 = blockIdx.x * 64;
    if (m0 >= M) return;
    if (causal && n0 > m0 + 63) return;   // fully-masked tile
    A += (long long)z0 * sAz + (long long)z1 * sAz2;
    B += (long long)z0 * sBz + (long long)z1 * sBz2;
    C += (long long)z0 * sCz + (long long)z1 * sCz2;
    if (bias) bias += (long long)z * sbz;
    if (res)  res  += (long long)z0 * sCz + (long long)z1 * sCz2;
    const int* iA = idxA ? idxA + z * TOK : nullptr;
    const int* iC = idxC ? idxC + z * TOK : nullptr;

    __shared__ float As[16][65];
    __shared__ float Bs[16][65];
    int tid = threadIdx.x;
    int tx = tid & 15, ty = tid >> 4;
    float acc[4][4] = {};

    for (int k0 = 0; k0 < Kd; k0 += 16) {
#pragma unroll
        for (int i = 0; i < 4; i++) {
            int lin = tid + i * 256;
            int mm = lin >> 4, kk = lin & 15;
            int gm = m0 + mm, gk = k0 + kk;
            float v = 0.f;
            if (gm < M && gk < Kd) {
                int ra = iA ? iA[gm] : gm;
                v = A[(long long)ra * lda + gk];
            }
            As[kk][mm] = v;
        }
#pragma unroll
        for (int i = 0; i < 4; i++) {
            int lin = tid + i * 256;
            float v = 0.f;
            if (!TRB) {
                int kk = lin >> 6, nn = lin & 63;
                int gk = k0 + kk, gn = n0 + nn;
                if (gk < Kd && gn < N) v = B[(long long)gk * ldb + gn];
                Bs[kk][nn] = v;
            } else {
                int nn = lin >> 4, kk = lin & 15;
                int gk = k0 + kk, gn = n0 + nn;
                if (gk < Kd && gn < N) v = B[(long long)gn * ldb + gk];
                Bs[kk][nn] = v;
            }
        }
        __syncthreads();
#pragma unroll
        for (int k = 0; k < 16; k++) {
            float a[4], b[4];
#pragma unroll
            for (int i = 0; i < 4; i++) a[i] = As[k][ty * 4 + i];
#pragma unroll
            for (int j = 0; j < 4; j++) b[j] = Bs[k][tx * 4 + j];
#pragma unroll
            for (int i = 0; i < 4; i++)
#pragma unroll
                for (int j = 0; j < 4; j++) acc[i][j] += a[i] * b[j];
        }
        __syncthreads();
    }
#pragma unroll
    for (int i = 0; i < 4; i++) {
        int gm = m0 + ty * 4 + i;
        if (gm >= M) continue;
        int rc = iC ? iC[gm] : gm;
        float* crow = C + (long long)rc * ldc;
        const float* rrow = res ? res + (long long)rc * ldc : nullptr;
#pragma unroll
        for (int j = 0; j < 4; j++) {
            int gn = n0 + tx * 4 + j;
            if (gn >= N) continue;
            float v = acc[i][j] * alpha;
            if (bias) v += bias[gn];
            if (ACT == 1) {
                float x = v;
                float t = tanhf(0.7978845608028654f * (x + 0.044715f * x * x * x));
                v = 0.5f * x * (1.f + t);
            }
            if (rrow) v += rrow[gn];
            crow[gn] = v;
        }
    }
}

// ---------------- small kernels ----------------
__global__ void transpose_z(const float* __restrict__ z, float* __restrict__ zt) {
    __shared__ float tile[32][33];
    int b = blockIdx.z;
    int l0 = blockIdx.x * 32, c0 = blockIdx.y * 32;
    int x = threadIdx.x, y = threadIdx.y;
    for (int i = y; i < 32; i += 8)
        tile[i][x] = z[b * CIN * SS + (c0 + i) * SS + l0 + x];
    __syncthreads();
    for (int i = y; i < 32; i += 8)
        zt[b * SS * CIN + (long long)(l0 + i) * CIN + c0 + x] = tile[x][i];
}

__global__ void ln_kernel(const float* __restrict__ x, float* __restrict__ y,
                          const float* __restrict__ g, const float* __restrict__ b) {
    int row = blockIdx.x;
    const float* xr = x + (long long)row * DD;
    __shared__ float sh[32];
    __shared__ float sh2[32];
    float s = 0.f, s2 = 0.f;
    for (int d = threadIdx.x; d < DD; d += 256) { float v = xr[d]; s += v; s2 += v * v; }
    int lane = threadIdx.x & 31, wid = threadIdx.x >> 5;
    for (int o = 16; o; o >>= 1) { s += __shfl_xor_sync(~0u, s, o); s2 += __shfl_xor_sync(~0u, s2, o); }
    if (lane == 0) { sh[wid] = s; sh2[wid] = s2; }
    __syncthreads();
    if (wid == 0) {
        s  = (lane < 8) ? sh[lane]  : 0.f;
        s2 = (lane < 8) ? sh2[lane] : 0.f;
        for (int o = 16; o; o >>= 1) { s += __shfl_xor_sync(~0u, s, o); s2 += __shfl_xor_sync(~0u, s2, o); }
        if (lane == 0) { sh[0] = s; sh2[0] = s2; }
    }
    __syncthreads();
    float mean = sh[0] / DD;
    float var  = sh2[0] / DD - mean * mean;
    float inv = rsqrtf(var + 1e-5f);
    float* yr = y + (long long)row * DD;
    for (int d = threadIdx.x; d < DD; d += 256)
        yr[d] = (xr[d] - mean) * inv * g[d] + b[d];
}

__global__ void rope_kernel(float* __restrict__ q, float* __restrict__ k) {
    int idx = blockIdx.x * blockDim.x + threadIdx.x;
    if (idx >= TOK * (DD / 2)) return;
    int t = idx / (DD / 2), j = idx - t * (DD / 2);
    int s = t & (SS - 1);
    float freq = __expf(-9.210340371976184f * ((float)j / 384.f));
    float ang = (float)s * freq;
    float c, sn; sincosf(ang, &sn, &c);
    {
        float* p = q + (long long)t * DD + 2 * j;
        float a = p[0], b = p[1];
        p[0] = a * c - b * sn; p[1] = a * sn + b * c;
    }
    {
        float* p = k + (long long)t * DD + 2 * j;
        float a = p[0], b = p[1];
        p[0] = a * c - b * sn; p[1] = a * sn + b * c;
    }
}

__global__ void softmax_causal(float* __restrict__ sc) {
    int z = blockIdx.y, r = blockIdx.x;
    float* row = sc + ((long long)z << 20) + (long long)r * 1024;
    int n = r + 1;
    __shared__ float sh[32];
    int lane = threadIdx.x & 31, wid = threadIdx.x >> 5;
    float mx = -1e30f;
    for (int j = threadIdx.x; j < n; j += 256) mx = fmaxf(mx, row[j]);
    for (int o = 16; o; o >>= 1) mx = fmaxf(mx, __shfl_xor_sync(~0u, mx, o));
    if (lane == 0) sh[wid] = mx;
    __syncthreads();
    if (wid == 0) {
        mx = (lane < 8) ? sh[lane] : -1e30f;
        for (int o = 16; o; o >>= 1) mx = fmaxf(mx, __shfl_xor_sync(~0u, mx, o));
        if (lane == 0) sh[0] = mx;
    }
    __syncthreads();
    mx = sh[0];
    __syncthreads();
    float s = 0.f;
    for (int j = threadIdx.x; j < n; j += 256) s += __expf(row[j] - mx);
    for (int o = 16; o; o >>= 1) s += __shfl_xor_sync(~0u, s, o);
    if (lane == 0) sh[wid] = s;
    __syncthreads();
    if (wid == 0) {
        s = (lane < 8) ? sh[lane] : 0.f;
        for (int o = 16; o; o >>= 1) s += __shfl_xor_sync(~0u, s, o);
        if (lane == 0) sh[0] = s;
    }
    __syncthreads();
    float inv = 1.f / sh[0];
    for (int j = threadIdx.x; j < 1024; j += 256)
        row[j] = (j < n) ? __expf(row[j] - mx) * inv : 0.f;
}

__global__ void zero_cnt(int* c) { if (threadIdx.x < EE) c[threadIdx.x] = 0; }

__global__ void route_kernel(const float* __restrict__ h, const float* __restrict__ gw,
                             int* cnt, int* etok, int* easn, float* wts) {
    int w = (blockIdx.x * blockDim.x + threadIdx.x) >> 5;
    int lane = threadIdx.x & 31;
    if (w >= TOK) return;
    const float* hr = h + (long long)w * DD;
    float lg[EE];
#pragma unroll
    for (int e = 0; e < EE; e++) {
        float s = 0.f;
        for (int d = lane; d < DD; d += 32) s += hr[d] * gw[d * EE + e];
        for (int o = 16; o; o >>= 1) s += __shfl_xor_sync(~0u, s, o);
        lg[e] = s;
    }
    if (lane == 0) {
        int e0 = 0;
        for (int e = 1; e < EE; e++) if (lg[e] > lg[e0]) e0 = e;
        int e1 = -1;
        for (int e = 0; e < EE; e++) { if (e == e0) continue; if (e1 < 0 || lg[e] > lg[e1]) e1 = e; }
        float x1 = __expf(lg[e1] - lg[e0]);
        float den = 1.f + x1;
        float w0 = 1.f / den, w1 = x1 / den;
        int s0 = atomicAdd(&cnt[e0], 1);
        etok[e0 * TOK + s0] = w; easn[e0 * TOK + s0] = 2 * w;
        int s1 = atomicAdd(&cnt[e1], 1);
        etok[e1 * TOK + s1] = w; easn[e1 * TOK + s1] = 2 * w + 1;
        wts[2 * w] = w0; wts[2 * w + 1] = w1;
    }
}

__global__ void combine_kernel(float* __restrict__ x, const float* __restrict__ ys,
                               const float* __restrict__ wts) {
    int idx = blockIdx.x * blockDim.x + threadIdx.x;
    if (idx >= TOK * DD) return;
    int t = idx / DD, d = idx - t * DD;
    x[idx] += wts[2 * t] * ys[(long long)(2 * t) * DD + d]
            + wts[2 * t + 1] * ys[(long long)(2 * t + 1) * DD + d];
}

__global__ void basis_kernel(float* __restrict__ Cb) {
    int idx = blockIdx.x * blockDim.x + threadIdx.x;
    if (idx >= 1026 * 1024) return;
    int j = idx >> 10, n = idx & 1023;
    const float invN = 1.f / 1024.f;
    float v;
    if (j == 0) v = invN;
    else if (j <= 511) { int m = (j * n) & 1023; v = 2.f * invN * cosf(m * TWO_PI_N); }
    else if (j == 512) v = invN * ((n & 1) ? -1.f : 1.f);
    else if (j == 513 || j == 1025) v = 0.f;
    else { int kk = j - 513; int m = (kk * n) & 1023; v = -2.f * invN * sinf(m * TWO_PI_N); }
    Cb[idx] = v;
}

__global__ void bf_kernel(const float* __restrict__ ob, const float* __restrict__ Cb,
                          float* __restrict__ bf) {
    int n = threadIdx.x;
    float s = 0.f;
    for (int j = 0; j < 1026; j++) s += ob[j] * Cb[j * 1024 + n];
    bf[n] = s;
}

__global__ void istft_kernel(const float* __restrict__ frames, float* __restrict__ out) {
    int idx = blockIdx.x * blockDim.x + threadIdx.x;
    if (idx >= BB * OUTL) return;
    int b = idx / OUTL, i = idx - b * OUTL;
    int ip = i + PADL;
    int tmin = (ip >= 1024) ? ((ip - 768) >> 8) : 0;
    int tmax = min(1023, ip >> 8);
    float acc = 0.f, env = 0.f;
    for (int t = tmin; t <= tmax; t++) {
        int n = ip - (t << 8);
        float w = 0.5f * (1.f - cosf(n * TWO_PI_N));
        acc += frames[((long long)(b * 1024 + t) << 10) + n] * w;
        env += w * w;
    }
    out[idx] = acc / env;
}

// ---------------- host side ----------------
static void* symaddr(const void* sym) {
    void* p = nullptr;
    cudaGetSymbolAddress(&p, sym);
    return p;
}

struct GemmArgs {
    const float* A; int lda; long long sAz, sAz2;
    const float* B; int ldb; long long sBz, sBz2;
    float* C; int ldc; long long sCz, sCz2;
    int zdiv;
    const float* bias; long long sbz; const float* res;
    int M, N, Kd; float alpha; int Z;
    const int* idxA; const int* idxC; const int* cnt;
    int causal; int gridM;
};

static void gemm(int act, bool trb, const GemmArgs& a)
{
    dim3 grid((a.N + 63) / 64, a.gridM ? a.gridM : (a.M + 63) / 64, a.Z);
    if (act == 1)
        gemm_kernel<1, false><<<grid, 256>>>(a.A, a.lda, a.sAz, a.sAz2, a.B, a.ldb, a.sBz, a.sBz2,
                                             a.C, a.ldc, a.sCz, a.sCz2, a.zdiv, a.bias, a.sbz, a.res,
                                             a.M, a.N, a.Kd, a.alpha, a.idxA, a.idxC, a.cnt, a.causal);
    else if (trb)
        gemm_kernel<0, true><<<grid, 256>>>(a.A, a.lda, a.sAz, a.sAz2, a.B, a.ldb, a.sBz, a.sBz2,
                                            a.C, a.ldc, a.sCz, a.sCz2, a.zdiv, a.bias, a.sbz, a.res,
                                            a.M, a.N, a.Kd, a.alpha, a.idxA, a.idxC, a.cnt, a.causal);
    else
        gemm_kernel<0, false><<<grid, 256>>>(a.A, a.lda, a.sAz, a.sAz2, a.B, a.ldb, a.sBz, a.sBz2,
                                             a.C, a.ldc, a.sCz, a.sCz2, a.zdiv, a.bias, a.sbz, a.res,
                                             a.M, a.N, a.Kd, a.alpha, a.idxA, a.idxC, a.cnt, a.causal);
}

extern "C" void kernel_launch(void* const* d_in, const int* in_sizes, int n_in,
                              void* d_out, int out_size)
{
    const float* z_in  = (const float*)d_in[0];
    const float* in_w  = (const float*)d_in[1];
    const float* in_b  = (const float*)d_in[2];
    const float* ln1g  = (const float*)d_in[3];
    const float* ln1b  = (const float*)d_in[4];
    const float* wq    = (const float*)d_in[5];
    const float* bq    = (const float*)d_in[6];
    const float* wk    = (const float*)d_in[7];
    const float* bk    = (const float*)d_in[8];
    const float* wv    = (const float*)d_in[9];
    const float* bv    = (const float*)d_in[10];
    const float* wo    = (const float*)d_in[11];
    const float* bo    = (const float*)d_in[12];
    const float* ln2g  = (const float*)d_in[13];
    const float* ln2b  = (const float*)d_in[14];
    const float* gatew = (const float*)d_in[15];
    const float* ew1   = (const float*)d_in[16];
    const float* eb1   = (const float*)d_in[17];
    const float* ew2   = (const float*)d_in[18];
    const float* eb2   = (const float*)d_in[19];
    const float* outw  = (const float*)d_in[20];
    const float* outb  = (const float*)d_in[21];
    float* out = (float*)d_out;

    float* ZT = (float*)symaddr(g_zt);
    float* X  = (float*)symaddr(g_x);
    float* H  = (float*)symaddr(g_h);
    float* Q  = (float*)symaddr(g_q);
    float* Kb = (float*)symaddr(g_k);
    float* V  = (float*)symaddr(g_v);
    float* AO = (float*)symaddr(g_ao);
    float* SC = (float*)symaddr(g_scores);
    float* HID = (float*)symaddr(g_hidden);
    float* YS = (float*)symaddr(g_yslot);
    float* CB = (float*)symaddr(g_Cb);
    float* MT = (float*)symaddr(g_Mt);
    float* BF = (float*)symaddr(g_bf);
    float* FR = (float*)symaddr(g_frames);
    int* CNT = (int*)symaddr(g_cnt);
    int* ETK = (int*)symaddr(g_etok);
    int* EAS = (int*)symaddr(g_easn);
    float* WTS = (float*)symaddr(g_wts);

    // in_projection: zt = z^T, x = zt @ in_w + in_b
    transpose_z<<<dim3(SS / 32, CIN / 32, BB), dim3(32, 8)>>>(z_in, ZT);
    {
        GemmArgs a = {ZT, CIN, 0, 0, in_w, DD, 0, 0, X, DD, 0, 0, 1,
                      in_b, 0, nullptr, TOK, DD, CIN, 1.f, 1, nullptr, nullptr, nullptr, 0, 0};
        gemm(0, false, a);
    }

    for (int L = 0; L < 2; L++) {
        const float* WQ = wq + (long long)L * DD * DD;
        const float* WK = wk + (long long)L * DD * DD;
        const float* WV = wv + (long long)L * DD * DD;
        const float* WO = wo + (long long)L * DD * DD;

        ln_kernel<<<TOK, 256>>>(X, H, ln1g + L * DD, ln1b + L * DD);
        {
            GemmArgs a = {H, DD, 0, 0, WQ, DD, 0, 0, Q, DD, 0, 0, 1,
                          bq + L * DD, 0, nullptr, TOK, DD, DD, 1.f, 1, 0, 0, 0, 0, 0};
            gemm(0, false, a);
            a.B = WK; a.bias = bk + L * DD; a.C = Kb; gemm(0, false, a);
            a.B = WV; a.bias = bv + L * DD; a.C = V;  gemm(0, false, a);
        }
        if (L == 0)
            rope_kernel<<<(TOK * (DD / 2) + 255) / 256, 256>>>(Q, Kb);

        // scores: z = b*HH + h → A off = b*SS*DD + h*HD (zdiv=HH)
        {
            GemmArgs a = {Q, DD, HD, (long long)SS * DD,
                          Kb, DD, HD, (long long)SS * DD,
                          SC, SS, (long long)SS * SS, (long long)HH * SS * SS, HH,
                          nullptr, 0, nullptr, SS, SS, HD, 0.125f, BB * HH, 0, 0, 0, 1, 0};
            gemm(0, true, a);
        }
        softmax_causal<<<dim3(SS, BB * HH), 256>>>(SC);
        {
            GemmArgs a = {SC, SS, (long long)SS * SS, (long long)HH * SS * SS,
                          V, DD, HD, (long long)SS * DD,
                          AO, DD, HD, (long long)SS * DD, HH,
                          nullptr, 0, nullptr, SS, HD, SS, 1.f, BB * HH, 0, 0, 0, 0, 0};
            gemm(0, false, a);
        }
        // out proj + residual
        {
            GemmArgs a = {AO, DD, 0, 0, WO, DD, 0, 0, X, DD, 0, 0, 1,
                          bo + L * DD, 0, X, TOK, DD, DD, 1.f, 1, 0, 0, 0, 0, 0};
            gemm(0, false, a);
        }

        // MoE
        ln_kernel<<<TOK, 256>>>(X, H, ln2g + L * DD, ln2b + L * DD);
        zero_cnt<<<1, 32>>>(CNT);
        route_kernel<<<TOK / 8, 256>>>(H, gatew + (long long)L * DD * EE, CNT, ETK, EAS, WTS);
        {
            GemmArgs a = {H, DD, 0, 0,
                          ew1 + (long long)L * EE * DD * FF, FF, (long long)DD * FF, 0,
                          HID, FF, 0, 0, EE,
                          eb1 + (long long)L * EE * FF, FF, nullptr,
                          TOK, FF, DD, 1.f, EE, ETK, EAS, CNT, 0, TOK / 64};
            gemm(1, false, a);
        }
        {
            GemmArgs a = {HID, FF, 0, 0,
                          ew2 + (long long)L * EE * FF * DD, DD, (long long)FF * DD, 0,
                          YS, DD, 0, 0, EE,
                          eb2 + (long long)L * EE * DD, DD, nullptr,
                          TOK, DD, FF, 1.f, EE, EAS, EAS, CNT, 0, TOK / 64};
            gemm(0, false, a);
        }
        combine_kernel<<<(TOK * DD + 255) / 256, 256>>>(X, YS, WTS);
    }

    // out projection fused with irfft basis: frames = x @ (out_w @ Cb) + out_b @ Cb
    basis_kernel<<<(1026 * 1024 + 255) / 256, 256>>>(CB);
    {
        GemmArgs a = {outw, 2 * FB, 0, 0, CB, 1024, 0, 0, MT, 1024, 0, 0, 1,
                      nullptr, 0, nullptr, DD, 1024, 2 * FB, 1.f, 1, 0, 0, 0, 0, 0};
        gemm(0, false, a);
    }
    bf_kernel<<<1, 1024>>>(outb, CB, BF);
    {
        GemmArgs a = {X, DD, 0, 0, MT, 1024, 0, 0, FR, 1024, 0, 0, 1,
                      BF, 0, nullptr, TOK, 1024, DD, 1.f, 1, 0, 0, 0, 0, 0};
        gemm(0, false, a);
    }

    // windowed overlap-add + env normalize + trim
    istft_kernel<<<(BB * OUTL + 255) / 256, 256>>>(FR, out);
}

// round 4
// speedup vs baseline: 1.2073x; 1.2073x over previous
#include <cuda_runtime.h>
#include <math.h>
#include <stdint.h>

// ---------------- constants ----------------
#define BB 2
#define SS 1024
#define DD 768
#define HH 12
#define HD 64
#define EE 8
#define FF 2048
#define CIN 512
#define TOK (BB*SS)          // 2048
#define FB 513
#define PADL 384
#define OUTL 262144
#define TWO_PI_N 0.006135923151542565f   // 2*pi/1024

// ---------------- scratch (device globals; allocation-free) ----------------
__device__ float g_zt[TOK*CIN];
__device__ float g_x [TOK*DD];
__device__ float g_h [TOK*DD];
__device__ float g_q [TOK*DD];
__device__ float g_k [TOK*DD];
__device__ float g_v [TOK*DD];
__device__ float g_ao[TOK*DD];
__device__ float g_scores[24u*1024u*1024u];
__device__ float g_hidden[4096*FF];
__device__ float g_yslot [4096*DD];
__device__ float g_Cb[1026*1024];
__device__ float g_Mt[DD*1024];
__device__ float g_bf[1024];
__device__ float g_frames[TOK*1024];
__device__ int   g_cnt[EE];
__device__ int   g_etok[EE*TOK];
__device__ int   g_easn[EE*TOK];
__device__ float g_wts[2*TOK];

// ---------------- tf32 helpers ----------------
__device__ __forceinline__ uint32_t f2tf32(float f) {
    uint32_t u;
    asm("cvt.rna.tf32.f32 %0, %1;" : "=r"(u) : "f"(f));
    return u;
}

__device__ __forceinline__ void split_tf32(float f, uint32_t& hi, uint32_t& lo) {
    hi = f2tf32(f);
    lo = f2tf32(f - __uint_as_float(hi));
}

__device__ __forceinline__ void mma_tf32(float* c, const uint32_t* a, const uint32_t* b) {
    asm volatile(
        "mma.sync.aligned.m16n8k8.row.col.f32.tf32.tf32.f32 "
        "{%0,%1,%2,%3}, {%4,%5,%6,%7}, {%8,%9}, {%0,%1,%2,%3};"
        : "+f"(c[0]), "+f"(c[1]), "+f"(c[2]), "+f"(c[3])
        : "r"(a[0]), "r"(a[1]), "r"(a[2]), "r"(a[3]), "r"(b[0]), "r"(b[1]));
}

// ---------------- tensor-core GEMM (3xTF32 split precision) ----------------
// Tile: 128(M) x 64(N), K-step 16. 8 warps as 4(M) x 2(N), warp = 32x32.
// C[z] = act(alpha * A[z] @ (B or B^T)[z] + bias) + res ; row gather/scatter optional.
#define AS_LD 136
#define BS_LD 72

template<int ACT, bool TRB>
__global__ __launch_bounds__(256, 2)
void gemm_kernel(const float* __restrict__ A, int lda, long long sAz, long long sAz2,
                 const float* __restrict__ B, int ldb, long long sBz, long long sBz2,
                 float* __restrict__ C, int ldc, long long sCz, long long sCz2,
                 int zdiv,
                 const float* __restrict__ bias, long long sbz,
                 const float* __restrict__ res,
                 int M, int N, int Kd, float alpha,
                 const int* __restrict__ idxA, const int* __restrict__ idxC,
                 const int* __restrict__ cnt, int causal)
{
    int z = blockIdx.z;
    int z1 = z / zdiv, z0 = z - z1 * zdiv;
    if (cnt) M = cnt[z];
    int m0 = blockIdx.y * 128, n0 = blockIdx.x * 64;
    if (m0 >= M) return;
    if (causal && n0 > m0 + 127) return;   // fully-masked tile
    A += (long long)z0 * sAz + (long long)z1 * sAz2;
    B += (long long)z0 * sBz + (long long)z1 * sBz2;
    C += (long long)z0 * sCz + (long long)z1 * sCz2;
    if (bias) bias += (long long)z * sbz;
    if (res)  res  += (long long)z0 * sCz + (long long)z1 * sCz2;
    const int* iA = idxA ? idxA + z * TOK : nullptr;
    const int* iC = idxC ? idxC + z * TOK : nullptr;

    __shared__ uint32_t As[2][16 * AS_LD];   // [0]=hi, [1]=lo
    __shared__ uint32_t Bs[2][16 * BS_LD];

    int tid = threadIdx.x;
    int lane = tid & 31, wid = tid >> 5;
    int wm = wid >> 1, wn = wid & 1;          // warp tile origin: (wm*32, wn*32)
    int lm = lane >> 2, lk = lane & 3;

    float acc[2][4][4];
#pragma unroll
    for (int i = 0; i < 2; i++)
#pragma unroll
        for (int j = 0; j < 4; j++)
#pragma unroll
            for (int r = 0; r < 4; r++) acc[i][j][r] = 0.f;

    const bool vecA = ((lda & 3) == 0);
    const bool vecB = ((ldb & 3) == 0);

    for (int k0 = 0; k0 < Kd; k0 += 16) {
        bool fullK = (k0 + 16 <= Kd);
        // ---- load A tile: 128 rows x 16 k ----
#pragma unroll
        for (int it = 0; it < 2; it++) {
            int lin = tid + it * 256;
            int mm = lin >> 2, kq = lin & 3;
            int gm = m0 + mm;
            int ra = -1;
            if (gm < M) ra = iA ? iA[gm] : gm;
            int base = (4 * kq) * AS_LD + mm;
            if (ra >= 0 && vecA && fullK) {
                const float4 v = *(const float4*)(A + (long long)ra * lda + k0 + 4 * kq);
                float f[4] = {v.x, v.y, v.z, v.w};
#pragma unroll
                for (int j = 0; j < 4; j++) {
                    uint32_t hi, lo; split_tf32(f[j], hi, lo);
                    As[0][base + j * AS_LD] = hi;
                    As[1][base + j * AS_LD] = lo;
                }
            } else {
#pragma unroll
                for (int j = 0; j < 4; j++) {
                    int gk = k0 + 4 * kq + j;
                    float v = (ra >= 0 && gk < Kd) ? A[(long long)ra * lda + gk] : 0.f;
                    uint32_t hi, lo; split_tf32(v, hi, lo);
                    As[0][base + j * AS_LD] = hi;
                    As[1][base + j * AS_LD] = lo;
                }
            }
        }
        // ---- load B tile: 16 k x 64 n ----
        if (!TRB) {
            int k = tid >> 4, n4 = (tid & 15) * 4;
            int gk = k0 + k;
            int base = k * BS_LD + n4;
            if (gk < Kd && vecB) {
                const float4 v = *(const float4*)(B + (long long)gk * ldb + n0 + n4);
                float f[4] = {v.x, v.y, v.z, v.w};
#pragma unroll
                for (int j = 0; j < 4; j++) {
                    uint32_t hi, lo; split_tf32(f[j], hi, lo);
                    Bs[0][base + j] = hi;
                    Bs[1][base + j] = lo;
                }
            } else {
#pragma unroll
                for (int j = 0; j < 4; j++) {
                    float v = (gk < Kd) ? B[(long long)gk * ldb + n0 + n4 + j] : 0.f;
                    uint32_t hi, lo; split_tf32(v, hi, lo);
                    Bs[0][base + j] = hi;
                    Bs[1][base + j] = lo;
                }
            }
        } else {
            int nn = tid >> 2, kq = tid & 3;
            int gn = n0 + nn;
            int base = (4 * kq) * BS_LD + nn;
            if (vecB && fullK) {
                const float4 v = *(const float4*)(B + (long long)gn * ldb + k0 + 4 * kq);
                float f[4] = {v.x, v.y, v.z, v.w};
#pragma unroll
                for (int j = 0; j < 4; j++) {
                    uint32_t hi, lo; split_tf32(f[j], hi, lo);
                    Bs[0][base + j * BS_LD] = hi;
                    Bs[1][base + j * BS_LD] = lo;
                }
            } else {
#pragma unroll
                for (int j = 0; j < 4; j++) {
                    int gk = k0 + 4 * kq + j;
                    float v = (gk < Kd) ? B[(long long)gn * ldb + gk] : 0.f;
                    uint32_t hi, lo; split_tf32(v, hi, lo);
                    Bs[0][base + j * BS_LD] = hi;
                    Bs[1][base + j * BS_LD] = lo;
                }
            }
        }
        __syncthreads();

        // ---- mma: acc += Ahi*Bhi + Ahi*Blo + Alo*Bhi ----
#pragma unroll
        for (int ks = 0; ks < 2; ks++) {
            int kk = ks * 8;
            uint32_t ah[2][4], al[2][4], bh[4][2], bl[4][2];
#pragma unroll
            for (int i = 0; i < 2; i++) {
                int bm = wm * 32 + i * 16 + lm;
                int r0 = (kk + lk) * AS_LD + bm;
                int r1 = (kk + lk + 4) * AS_LD + bm;
                ah[i][0] = As[0][r0];     ah[i][1] = As[0][r0 + 8];
                ah[i][2] = As[0][r1];     ah[i][3] = As[0][r1 + 8];
                al[i][0] = As[1][r0];     al[i][1] = As[1][r0 + 8];
                al[i][2] = As[1][r1];     al[i][3] = As[1][r1 + 8];
            }
#pragma unroll
            for (int j = 0; j < 4; j++) {
                int bn = wn * 32 + j * 8 + lm;
                bh[j][0] = Bs[0][(kk + lk) * BS_LD + bn];
                bh[j][1] = Bs[0][(kk + lk + 4) * BS_LD + bn];
                bl[j][0] = Bs[1][(kk + lk) * BS_LD + bn];
                bl[j][1] = Bs[1][(kk + lk + 4) * BS_LD + bn];
            }
#pragma unroll
            for (int i = 0; i < 2; i++)
#pragma unroll
                for (int j = 0; j < 4; j++) {
                    mma_tf32(acc[i][j], ah[i], bh[j]);
                    mma_tf32(acc[i][j], ah[i], bl[j]);
                    mma_tf32(acc[i][j], al[i], bh[j]);
                }
        }
        __syncthreads();
    }

    // ---- epilogue ----
#pragma unroll
    for (int i = 0; i < 2; i++) {
#pragma unroll
        for (int r2 = 0; r2 < 2; r2++) {
            int gm = m0 + wm * 32 + i * 16 + lm + r2 * 8;
            if (gm >= M) continue;
            int rc = iC ? iC[gm] : gm;
            float* crow = C + (long long)rc * ldc;
            const float* rrow = res ? res + (long long)rc * ldc : nullptr;
#pragma unroll
            for (int j = 0; j < 4; j++) {
#pragma unroll
                for (int c2 = 0; c2 < 2; c2++) {
                    int gn = n0 + wn * 32 + j * 8 + lk * 2 + c2;
                    if (gn >= N) continue;
                    float v = acc[i][j][r2 * 2 + c2] * alpha;
                    if (bias) v += bias[gn];
                    if (ACT == 1) {
                        float x = v;
                        float t = tanhf(0.7978845608028654f * (x + 0.044715f * x * x * x));
                        v = 0.5f * x * (1.f + t);
                    }
                    if (rrow) v += rrow[gn];
                    crow[gn] = v;
                }
            }
        }
    }
}

// ---------------- small kernels ----------------
__global__ void transpose_z(const float* __restrict__ z, float* __restrict__ zt) {
    __shared__ float tile[32][33];
    int b = blockIdx.z;
    int l0 = blockIdx.x * 32, c0 = blockIdx.y * 32;
    int x = threadIdx.x, y = threadIdx.y;
    for (int i = y; i < 32; i += 8)
        tile[i][x] = z[b * CIN * SS + (c0 + i) * SS + l0 + x];
    __syncthreads();
    for (int i = y; i < 32; i += 8)
        zt[b * SS * CIN + (long long)(l0 + i) * CIN + c0 + x] = tile[x][i];
}

__global__ void ln_kernel(const float* __restrict__ x, float* __restrict__ y,
                          const float* __restrict__ g, const float* __restrict__ b) {
    int row = blockIdx.x;
    const float* xr = x + (long long)row * DD;
    __shared__ float sh[32];
    __shared__ float sh2[32];
    float s = 0.f, s2 = 0.f;
    for (int d = threadIdx.x; d < DD; d += 256) { float v = xr[d]; s += v; s2 += v * v; }
    int lane = threadIdx.x & 31, wid = threadIdx.x >> 5;
    for (int o = 16; o; o >>= 1) { s += __shfl_xor_sync(~0u, s, o); s2 += __shfl_xor_sync(~0u, s2, o); }
    if (lane == 0) { sh[wid] = s; sh2[wid] = s2; }
    __syncthreads();
    if (wid == 0) {
        s  = (lane < 8) ? sh[lane]  : 0.f;
        s2 = (lane < 8) ? sh2[lane] : 0.f;
        for (int o = 16; o; o >>= 1) { s += __shfl_xor_sync(~0u, s, o); s2 += __shfl_xor_sync(~0u, s2, o); }
        if (lane == 0) { sh[0] = s; sh2[0] = s2; }
    }
    __syncthreads();
    float mean = sh[0] / DD;
    float var  = sh2[0] / DD - mean * mean;
    float inv = rsqrtf(var + 1e-5f);
    float* yr = y + (long long)row * DD;
    for (int d = threadIdx.x; d < DD; d += 256)
        yr[d] = (xr[d] - mean) * inv * g[d] + b[d];
}

__global__ void rope_kernel(float* __restrict__ q, float* __restrict__ k) {
    int idx = blockIdx.x * blockDim.x + threadIdx.x;
    if (idx >= TOK * (DD / 2)) return;
    int t = idx / (DD / 2), j = idx - t * (DD / 2);
    int s = t & (SS - 1);
    float freq = __expf(-9.210340371976184f * ((float)j / 384.f));
    float ang = (float)s * freq;
    float c, sn; sincosf(ang, &sn, &c);
    {
        float* p = q + (long long)t * DD + 2 * j;
        float a = p[0], b = p[1];
        p[0] = a * c - b * sn; p[1] = a * sn + b * c;
    }
    {
        float* p = k + (long long)t * DD + 2 * j;
        float a = p[0], b = p[1];
        p[0] = a * c - b * sn; p[1] = a * sn + b * c;
    }
}

__global__ void softmax_causal(float* __restrict__ sc) {
    int z = blockIdx.y, r = blockIdx.x;
    float* row = sc + ((long long)z << 20) + (long long)r * 1024;
    int n = r + 1;
    __shared__ float sh[32];
    int lane = threadIdx.x & 31, wid = threadIdx.x >> 5;
    float mx = -1e30f;
    for (int j = threadIdx.x; j < n; j += 256) mx = fmaxf(mx, row[j]);
    for (int o = 16; o; o >>= 1) mx = fmaxf(mx, __shfl_xor_sync(~0u, mx, o));
    if (lane == 0) sh[wid] = mx;
    __syncthreads();
    if (wid == 0) {
        mx = (lane < 8) ? sh[lane] : -1e30f;
        for (int o = 16; o; o >>= 1) mx = fmaxf(mx, __shfl_xor_sync(~0u, mx, o));
        if (lane == 0) sh[0] = mx;
    }
    __syncthreads();
    mx = sh[0];
    __syncthreads();
    float s = 0.f;
    for (int j = threadIdx.x; j < n; j += 256) s += __expf(row[j] - mx);
    for (int o = 16; o; o >>= 1) s += __shfl_xor_sync(~0u, s, o);
    if (lane == 0) sh[wid] = s;
    __syncthreads();
    if (wid == 0) {
        s = (lane < 8) ? sh[lane] : 0.f;
        for (int o = 16; o; o >>= 1) s += __shfl_xor_sync(~0u, s, o);
        if (lane == 0) sh[0] = s;
    }
    __syncthreads();
    float inv = 1.f / sh[0];
    for (int j = threadIdx.x; j < 1024; j += 256)
        row[j] = (j < n) ? __expf(row[j] - mx) * inv : 0.f;
}

__global__ void zero_cnt(int* c) { if (threadIdx.x < EE) c[threadIdx.x] = 0; }

__global__ void route_kernel(const float* __restrict__ h, const float* __restrict__ gw,
                             int* cnt, int* etok, int* easn, float* wts) {
    int w = (blockIdx.x * blockDim.x + threadIdx.x) >> 5;
    int lane = threadIdx.x & 31;
    if (w >= TOK) return;
    const float* hr = h + (long long)w * DD;
    float lg[EE];
#pragma unroll
    for (int e = 0; e < EE; e++) {
        float s = 0.f;
        for (int d = lane; d < DD; d += 32) s += hr[d] * gw[d * EE + e];
        for (int o = 16; o; o >>= 1) s += __shfl_xor_sync(~0u, s, o);
        lg[e] = s;
    }
    if (lane == 0) {
        int e0 = 0;
        for (int e = 1; e < EE; e++) if (lg[e] > lg[e0]) e0 = e;
        int e1 = -1;
        for (int e = 0; e < EE; e++) { if (e == e0) continue; if (e1 < 0 || lg[e] > lg[e1]) e1 = e; }
        float x1 = __expf(lg[e1] - lg[e0]);
        float den = 1.f + x1;
        float w0 = 1.f / den, w1 = x1 / den;
        int s0 = atomicAdd(&cnt[e0], 1);
        etok[e0 * TOK + s0] = w; easn[e0 * TOK + s0] = 2 * w;
        int s1 = atomicAdd(&cnt[e1], 1);
        etok[e1 * TOK + s1] = w; easn[e1 * TOK + s1] = 2 * w + 1;
        wts[2 * w] = w0; wts[2 * w + 1] = w1;
    }
}

__global__ void combine_kernel(float* __restrict__ x, const float* __restrict__ ys,
                               const float* __restrict__ wts) {
    int idx = blockIdx.x * blockDim.x + threadIdx.x;
    if (idx >= TOK * DD) return;
    int t = idx / DD, d = idx - t * DD;
    x[idx] += wts[2 * t] * ys[(long long)(2 * t) * DD + d]
            + wts[2 * t + 1] * ys[(long long)(2 * t + 1) * DD + d];
}

__global__ void basis_kernel(float* __restrict__ Cb) {
    int idx = blockIdx.x * blockDim.x + threadIdx.x;
    if (idx >= 1026 * 1024) return;
    int j = idx >> 10, n = idx & 1023;
    const float invN = 1.f / 1024.f;
    float v;
    if (j == 0) v = invN;
    else if (j <= 511) { int m = (j * n) & 1023; v = 2.f * invN * cosf(m * TWO_PI_N); }
    else if (j == 512) v = invN * ((n & 1) ? -1.f : 1.f);
    else if (j == 513 || j == 1025) v = 0.f;
    else { int kk = j - 513; int m = (kk * n) & 1023; v = -2.f * invN * sinf(m * TWO_PI_N); }
    Cb[idx] = v;
}

__global__ void bf_kernel(const float* __restrict__ ob, const float* __restrict__ Cb,
                          float* __restrict__ bf) {
    int n = threadIdx.x;
    float s = 0.f;
    for (int j = 0; j < 1026; j++) s += ob[j] * Cb[j * 1024 + n];
    bf[n] = s;
}

__global__ void istft_kernel(const float* __restrict__ frames, float* __restrict__ out) {
    int idx = blockIdx.x * blockDim.x + threadIdx.x;
    if (idx >= BB * OUTL) return;
    int b = idx / OUTL, i = idx - b * OUTL;
    int ip = i + PADL;
    int tmin = (ip >= 1024) ? ((ip - 768) >> 8) : 0;
    int tmax = min(1023, ip >> 8);
    float acc = 0.f, env = 0.f;
    for (int t = tmin; t <= tmax; t++) {
        int n = ip - (t << 8);
        float w = 0.5f * (1.f - cosf(n * TWO_PI_N));
        acc += frames[((long long)(b * 1024 + t) << 10) + n] * w;
        env += w * w;
    }
    out[idx] = acc / env;
}

// ---------------- host side ----------------
static void* symaddr(const void* sym) {
    void* p = nullptr;
    cudaGetSymbolAddress(&p, sym);
    return p;
}

struct GemmArgs {
    const float* A; int lda; long long sAz, sAz2;
    const float* B; int ldb; long long sBz, sBz2;
    float* C; int ldc; long long sCz, sCz2;
    int zdiv;
    const float* bias; long long sbz; const float* res;
    int M, N, Kd; float alpha; int Z;
    const int* idxA; const int* idxC; const int* cnt;
    int causal; int gridM;
};

static void gemm(int act, bool trb, const GemmArgs& a)
{
    dim3 grid((a.N + 63) / 64, a.gridM ? a.gridM : (a.M + 127) / 128, a.Z);
    if (act == 1)
        gemm_kernel<1, false><<<grid, 256>>>(a.A, a.lda, a.sAz, a.sAz2, a.B, a.ldb, a.sBz, a.sBz2,
                                             a.C, a.ldc, a.sCz, a.sCz2, a.zdiv, a.bias, a.sbz, a.res,
                                             a.M, a.N, a.Kd, a.alpha, a.idxA, a.idxC, a.cnt, a.causal);
    else if (trb)
        gemm_kernel<0, true><<<grid, 256>>>(a.A, a.lda, a.sAz, a.sAz2, a.B, a.ldb, a.sBz, a.sBz2,
                                            a.C, a.ldc, a.sCz, a.sCz2, a.zdiv, a.bias, a.sbz, a.res,
                                            a.M, a.N, a.Kd, a.alpha, a.idxA, a.idxC, a.cnt, a.causal);
    else
        gemm_kernel<0, false><<<grid, 256>>>(a.A, a.lda, a.sAz, a.sAz2, a.B, a.ldb, a.sBz, a.sBz2,
                                             a.C, a.ldc, a.sCz, a.sCz2, a.zdiv, a.bias, a.sbz, a.res,
                                             a.M, a.N, a.Kd, a.alpha, a.idxA, a.idxC, a.cnt, a.causal);
}

extern "C" void kernel_launch(void* const* d_in, const int* in_sizes, int n_in,
                              void* d_out, int out_size)
{
    const float* z_in  = (const float*)d_in[0];
    const float* in_w  = (const float*)d_in[1];
    const float* in_b  = (const float*)d_in[2];
    const float* ln1g  = (const float*)d_in[3];
    const float* ln1b  = (const float*)d_in[4];
    const float* wq    = (const float*)d_in[5];
    const float* bq    = (const float*)d_in[6];
    const float* wk    = (const float*)d_in[7];
    const float* bk    = (const float*)d_in[8];
    const float* wv    = (const float*)d_in[9];
    const float* bv    = (const float*)d_in[10];
    const float* wo    = (const float*)d_in[11];
    const float* bo    = (const float*)d_in[12];
    const float* ln2g  = (const float*)d_in[13];
    const float* ln2b  = (const float*)d_in[14];
    const float* gatew = (const float*)d_in[15];
    const float* ew1   = (const float*)d_in[16];
    const float* eb1   = (const float*)d_in[17];
    const float* ew2   = (const float*)d_in[18];
    const float* eb2   = (const float*)d_in[19];
    const float* outw  = (const float*)d_in[20];
    const float* outb  = (const float*)d_in[21];
    float* out = (float*)d_out;

    float* ZT = (float*)symaddr(g_zt);
    float* X  = (float*)symaddr(g_x);
    float* H  = (float*)symaddr(g_h);
    float* Q  = (float*)symaddr(g_q);
    float* Kb = (float*)symaddr(g_k);
    float* V  = (float*)symaddr(g_v);
    float* AO = (float*)symaddr(g_ao);
    float* SC = (float*)symaddr(g_scores);
    float* HID = (float*)symaddr(g_hidden);
    float* YS = (float*)symaddr(g_yslot);
    float* CB = (float*)symaddr(g_Cb);
    float* MT = (float*)symaddr(g_Mt);
    float* BF = (float*)symaddr(g_bf);
    float* FR = (float*)symaddr(g_frames);
    int* CNT = (int*)symaddr(g_cnt);
    int* ETK = (int*)symaddr(g_etok);
    int* EAS = (int*)symaddr(g_easn);
    float* WTS = (float*)symaddr(g_wts);

    // in_projection: zt = z^T, x = zt @ in_w + in_b
    transpose_z<<<dim3(SS / 32, CIN / 32, BB), dim3(32, 8)>>>(z_in, ZT);
    {
        GemmArgs a = {ZT, CIN, 0, 0, in_w, DD, 0, 0, X, DD, 0, 0, 1,
                      in_b, 0, nullptr, TOK, DD, CIN, 1.f, 1, nullptr, nullptr, nullptr, 0, 0};
        gemm(0, false, a);
    }

    for (int L = 0; L < 2; L++) {
        const float* WQ = wq + (long long)L * DD * DD;
        const float* WK = wk + (long long)L * DD * DD;
        const float* WV = wv + (long long)L * DD * DD;
        const float* WO = wo + (long long)L * DD * DD;

        ln_kernel<<<TOK, 256>>>(X, H, ln1g + L * DD, ln1b + L * DD);
        {
            GemmArgs a = {H, DD, 0, 0, WQ, DD, 0, 0, Q, DD, 0, 0, 1,
                          bq + L * DD, 0, nullptr, TOK, DD, DD, 1.f, 1, 0, 0, 0, 0, 0};
            gemm(0, false, a);
            a.B = WK; a.bias = bk + L * DD; a.C = Kb; gemm(0, false, a);
            a.B = WV; a.bias = bv + L * DD; a.C = V;  gemm(0, false, a);
        }
        if (L == 0)
            rope_kernel<<<(TOK * (DD / 2) + 255) / 256, 256>>>(Q, Kb);

        // scores: z = b*HH + h -> A off = h*HD + b*SS*DD (zdiv=HH)
        {
            GemmArgs a = {Q, DD, HD, (long long)SS * DD,
                          Kb, DD, HD, (long long)SS * DD,
                          SC, SS, (long long)SS * SS, (long long)HH * SS * SS, HH,
                          nullptr, 0, nullptr, SS, SS, HD, 0.125f, BB * HH, 0, 0, 0, 1, 0};
            gemm(0, true, a);
        }
        softmax_causal<<<dim3(SS, BB * HH), 256>>>(SC);
        {
            GemmArgs a = {SC, SS, (long long)SS * SS, (long long)HH * SS * SS,
                          V, DD, HD, (long long)SS * DD,
                          AO, DD, HD, (long long)SS * DD, HH,
                          nullptr, 0, nullptr, SS, HD, SS, 1.f, BB * HH, 0, 0, 0, 0, 0};
            gemm(0, false, a);
        }
        // out proj + residual
        {
            GemmArgs a = {AO, DD, 0, 0, WO, DD, 0, 0, X, DD, 0, 0, 1,
                          bo + L * DD, 0, X, TOK, DD, DD, 1.f, 1, 0, 0, 0, 0, 0};
            gemm(0, false, a);
        }

        // MoE
        ln_kernel<<<TOK, 256>>>(X, H, ln2g + L * DD, ln2b + L * DD);
        zero_cnt<<<1, 32>>>(CNT);
        route_kernel<<<TOK / 8, 256>>>(H, gatew + (long long)L * DD * EE, CNT, ETK, EAS, WTS);
        {
            GemmArgs a = {H, DD, 0, 0,
                          ew1 + (long long)L * EE * DD * FF, FF, (long long)DD * FF, 0,
                          HID, FF, 0, 0, EE,
                          eb1 + (long long)L * EE * FF, FF, nullptr,
                          TOK, FF, DD, 1.f, EE, ETK, EAS, CNT, 0, TOK / 128};
            gemm(1, false, a);
        }
        {
            GemmArgs a = {HID, FF, 0, 0,
                          ew2 + (long long)L * EE * FF * DD, DD, (long long)FF * DD, 0,
                          YS, DD, 0, 0, EE,
                          eb2 + (long long)L * EE * DD, DD, nullptr,
                          TOK, DD, FF, 1.f, EE, EAS, EAS, CNT, 0, TOK / 128};
            gemm(0, false, a);
        }
        combine_kernel<<<(TOK * DD + 255) / 256, 256>>>(X, YS, WTS);
    }

    // out projection fused with irfft basis: frames = x @ (out_w @ Cb) + out_b @ Cb
    basis_kernel<<<(1026 * 1024 + 255) / 256, 256>>>(CB);
    {
        GemmArgs a = {outw, 2 * FB, 0, 0, CB, 1024, 0, 0, MT, 1024, 0, 0, 1,
                      nullptr, 0, nullptr, DD, 1024, 2 * FB, 1.f, 1, 0, 0, 0, 0, 0};
        gemm(0, false, a);
    }
    bf_kernel<<<1, 1024>>>(outb, CB, BF);
    {
        GemmArgs a = {X, DD, 0, 0, MT, 1024, 0, 0, FR, 1024, 0, 0, 1,
                      BF, 0, nullptr, TOK, 1024, DD, 1.f, 1, 0, 0, 0, 0, 0};
        gemm(0, false, a);
    }

    // windowed overlap-add + env normalize + trim
    istft_kernel<<<(BB * OUTL + 255) / 256, 256>>>(FR, out);
}

// round 5
// speedup vs baseline: 1.7521x; 1.4512x over previous
#include <cuda_runtime.h>
#include <math.h>
#include <stdint.h>

// ---------------- constants ----------------
#define BB 2
#define SS 1024
#define DD 768
#define HH 12
#define HD 64
#define EE 8
#define FF 2048
#define CIN 512
#define TOK (BB*SS)          // 2048
#define FB 513
#define PADL 384
#define OUTL 262144
#define TWO_PI_N 0.006135923151542565f   // 2*pi/1024

// ---------------- scratch (device globals; allocation-free) ----------------
__device__ float g_zt[TOK*CIN];
__device__ float g_x [TOK*DD];
__device__ float g_h [TOK*DD];
__device__ float g_q [TOK*DD];
__device__ float g_k [TOK*DD];
__device__ float g_v [TOK*DD];
__device__ float g_ao[TOK*DD];
__device__ float g_scores[24u*1024u*1024u];
__device__ float g_hidden[4096*FF];
__device__ float g_yslot [4096*DD];
__device__ float g_Cb[1026*1024];
__device__ float g_Mt[DD*1024];
__device__ float g_bf[1024];
__device__ float g_frames[TOK*1024];
__device__ int   g_cnt[EE];
__device__ int   g_etok[EE*TOK];
__device__ int   g_easn[EE*TOK];
__device__ float g_wts[2*TOK];

// ---------------- tf32 / async helpers ----------------
__device__ __forceinline__ uint32_t f2tf32(float f) {
    uint32_t u;
    asm("cvt.rna.tf32.f32 %0, %1;" : "=r"(u) : "f"(f));
    return u;
}
__device__ __forceinline__ void split_tf32(float f, uint32_t& hi, uint32_t& lo) {
    hi = f2tf32(f);
    lo = f2tf32(f - __uint_as_float(hi));
}
__device__ __forceinline__ void mma_tf32(float* c, const uint32_t* a, const uint32_t* b) {
    asm volatile(
        "mma.sync.aligned.m16n8k8.row.col.f32.tf32.tf32.f32 "
        "{%0,%1,%2,%3}, {%4,%5,%6,%7}, {%8,%9}, {%0,%1,%2,%3};"
        : "+f"(c[0]), "+f"(c[1]), "+f"(c[2]), "+f"(c[3])
        : "r"(a[0]), "r"(a[1]), "r"(a[2]), "r"(a[3]), "r"(b[0]), "r"(b[1]));
}
__device__ __forceinline__ void cpa16(uint32_t dst, const float* src, bool pred) {
    asm volatile("cp.async.ca.shared.global [%0], [%1], 16, %2;"
                 :: "r"(dst), "l"(src), "r"(pred ? 16 : 0));
}
__device__ __forceinline__ void cpa_commit() { asm volatile("cp.async.commit_group;"); }
__device__ __forceinline__ void cpa_wait1() { asm volatile("cp.async.wait_group 1;"); }

// ---------------- pipelined tensor-core GEMM (3xTF32, cp.async 3-stage) ----------------
// Tile: 128(M) x 64(N), K-step 16. 8 warps as 4(M) x 2(N), warp = 32x32.
#define STG 3
#define A_LD 20
#define B_LD 72
#define BT_LD 20
#define ASTG (128 * A_LD)
#define BSTG 1280

template<int ACT, bool TRB>
__global__ __launch_bounds__(256, 2)
void gemm_kernel(const float* __restrict__ A, int lda, long long sAz, long long sAz2,
                 const float* __restrict__ B, int ldb, long long sBz, long long sBz2,
                 float* __restrict__ C, int ldc, long long sCz, long long sCz2,
                 int zdiv,
                 const float* __restrict__ bias, long long sbz,
                 const float* __restrict__ res,
                 int M, int N, int Kd, float alpha,
                 const int* __restrict__ idxA, const int* __restrict__ idxC,
                 const int* __restrict__ cnt, int causal)
{
    int z = blockIdx.z;
    int z1 = z / zdiv, z0 = z - z1 * zdiv;
    if (cnt) M = cnt[z];
    int m0 = blockIdx.y * 128, n0 = blockIdx.x * 64;
    if (m0 >= M) return;
    if (causal && n0 > m0 + 127) return;
    A += (long long)z0 * sAz + (long long)z1 * sAz2;
    B += (long long)z0 * sBz + (long long)z1 * sBz2;
    C += (long long)z0 * sCz + (long long)z1 * sCz2;
    if (bias) bias += (long long)z * sbz;
    if (res)  res  += (long long)z0 * sCz + (long long)z1 * sCz2;
    const int* iA = idxA ? idxA + z * TOK : nullptr;
    const int* iC = idxC ? idxC + z * TOK : nullptr;

    __shared__ float AsF[STG][ASTG];
    __shared__ float BsF[STG][BSTG];
    uint32_t sA = (uint32_t)__cvta_generic_to_shared(&AsF[0][0]);
    uint32_t sB = (uint32_t)__cvta_generic_to_shared(&BsF[0][0]);

    int tid = threadIdx.x;
    int lane = tid & 31, wid = tid >> 5;
    int wm = wid >> 1, wn = wid & 1;
    int lm = lane >> 2, lk = lane & 3;

    float acc[2][4][4];
#pragma unroll
    for (int i = 0; i < 2; i++)
#pragma unroll
        for (int j = 0; j < 4; j++)
#pragma unroll
            for (int r = 0; r < 4; r++) acc[i][j][r] = 0.f;

    const bool fastA = ((lda & 3) == 0) && ((Kd & 15) == 0);
    const bool fastB = ((ldb & 3) == 0) && (TRB ? ((Kd & 15) == 0) : true);

    auto load_stage = [&](int s, int k0) {
        // ---- A: 128 rows x 16 k, smem [m][A_LD] ----
        if (fastA) {
#pragma unroll
            for (int it = 0; it < 2; it++) {
                int lin = tid + it * 256;
                int mm = lin >> 2, q = lin & 3;
                int gm = m0 + mm;
                int ra = (gm < M) ? (iA ? iA[gm] : gm) : -1;
                const float* src = A + (long long)(ra >= 0 ? ra : 0) * lda + k0 + 4 * q;
                cpa16(sA + ((s * ASTG + mm * A_LD + 4 * q) << 2), src, ra >= 0);
            }
        } else {
#pragma unroll
            for (int it = 0; it < 2; it++) {
                int lin = tid + it * 256;
                int mm = lin >> 2, q = lin & 3;
                int gm = m0 + mm;
                int ra = (gm < M) ? (iA ? iA[gm] : gm) : -1;
                float* dst = &AsF[s][mm * A_LD + 4 * q];
#pragma unroll
                for (int j = 0; j < 4; j++) {
                    int gk = k0 + 4 * q + j;
                    dst[j] = (ra >= 0 && gk < Kd) ? A[(long long)ra * lda + gk] : 0.f;
                }
            }
        }
        // ---- B ----
        if (!TRB) {
            int k = tid >> 4, q = tid & 15;
            int gk = k0 + k;
            if (fastB) {
                const float* src = B + (long long)(gk < Kd ? gk : 0) * ldb + n0 + 4 * q;
                cpa16(sB + ((s * BSTG + k * B_LD + 4 * q) << 2), src, gk < Kd);
            } else {
                float* dst = &BsF[s][k * B_LD + 4 * q];
#pragma unroll
                for (int j = 0; j < 4; j++)
                    dst[j] = (gk < Kd) ? B[(long long)gk * ldb + n0 + 4 * q + j] : 0.f;
            }
        } else {
            int nn = tid >> 2, q = tid & 3;
            int gn = n0 + nn;
            if (fastB) {
                const float* src = B + (long long)gn * ldb + k0 + 4 * q;
                cpa16(sB + ((s * BSTG + nn * BT_LD + 4 * q) << 2), src, true);
            } else {
                float* dst = &BsF[s][nn * BT_LD + 4 * q];
#pragma unroll
                for (int j = 0; j < 4; j++) {
                    int gk = k0 + 4 * q + j;
                    dst[j] = (gk < Kd) ? B[(long long)gn * ldb + gk] : 0.f;
                }
            }
        }
    };

    auto compute = [&](int s) {
        const float* As_ = &AsF[s][0];
        const float* Bs_ = &BsF[s][0];
#pragma unroll
        for (int ks = 0; ks < 2; ks++) {
            int kk = ks * 8;
            uint32_t ah[2][4], al[2][4], bh[4][2], bl[4][2];
#pragma unroll
            for (int i = 0; i < 2; i++) {
                const float* r0 = As_ + (wm * 32 + i * 16 + lm) * A_LD;
                const float* r1 = r0 + 8 * A_LD;
                split_tf32(r0[kk + lk],     ah[i][0], al[i][0]);
                split_tf32(r1[kk + lk],     ah[i][1], al[i][1]);
                split_tf32(r0[kk + lk + 4], ah[i][2], al[i][2]);
                split_tf32(r1[kk + lk + 4], ah[i][3], al[i][3]);
            }
#pragma unroll
            for (int j = 0; j < 4; j++) {
                int bn = wn * 32 + j * 8 + lm;
                float f0, f1;
                if (!TRB) {
                    f0 = Bs_[(kk + lk) * B_LD + bn];
                    f1 = Bs_[(kk + lk + 4) * B_LD + bn];
                } else {
                    f0 = Bs_[bn * BT_LD + kk + lk];
                    f1 = Bs_[bn * BT_LD + kk + lk + 4];
                }
                split_tf32(f0, bh[j][0], bl[j][0]);
                split_tf32(f1, bh[j][1], bl[j][1]);
            }
#pragma unroll
            for (int i = 0; i < 2; i++)
#pragma unroll
                for (int j = 0; j < 4; j++) {
                    mma_tf32(acc[i][j], ah[i], bh[j]);
                    mma_tf32(acc[i][j], ah[i], bl[j]);
                    mma_tf32(acc[i][j], al[i], bh[j]);
                }
        }
    };

    int nk = (Kd + 15) >> 4;
    // prologue: fill STG-1 stages
#pragma unroll
    for (int p = 0; p < STG - 1; p++) {
        if (p < nk) load_stage(p, p * 16);
        cpa_commit();
    }
    // steady state
    for (int i = 0; i < nk; i++) {
        cpa_wait1();
        __syncthreads();
        int nx = i + STG - 1;
        if (nx < nk) load_stage(nx % STG, nx * 16);
        cpa_commit();
        compute(i % STG);
    }

    // ---- epilogue ----
#pragma unroll
    for (int i = 0; i < 2; i++) {
#pragma unroll
        for (int r2 = 0; r2 < 2; r2++) {
            int gm = m0 + wm * 32 + i * 16 + lm + r2 * 8;
            if (gm >= M) continue;
            int rc = iC ? iC[gm] : gm;
            float* crow = C + (long long)rc * ldc;
            const float* rrow = res ? res + (long long)rc * ldc : nullptr;
#pragma unroll
            for (int j = 0; j < 4; j++) {
#pragma unroll
                for (int c2 = 0; c2 < 2; c2++) {
                    int gn = n0 + wn * 32 + j * 8 + lk * 2 + c2;
                    if (gn >= N) continue;
                    float v = acc[i][j][r2 * 2 + c2] * alpha;
                    if (bias) v += bias[gn];
                    if (ACT == 1) {
                        float x = v;
                        float t = tanhf(0.7978845608028654f * (x + 0.044715f * x * x * x));
                        v = 0.5f * x * (1.f + t);
                    }
                    if (rrow) v += rrow[gn];
                    crow[gn] = v;
                }
            }
        }
    }
}

// ---------------- small kernels ----------------
__global__ void transpose_z(const float* __restrict__ z, float* __restrict__ zt) {
    __shared__ float tile[32][33];
    int b = blockIdx.z;
    int l0 = blockIdx.x * 32, c0 = blockIdx.y * 32;
    int x = threadIdx.x, y = threadIdx.y;
    for (int i = y; i < 32; i += 8)
        tile[i][x] = z[b * CIN * SS + (c0 + i) * SS + l0 + x];
    __syncthreads();
    for (int i = y; i < 32; i += 8)
        zt[b * SS * CIN + (long long)(l0 + i) * CIN + c0 + x] = tile[x][i];
}

__global__ void ln_kernel(const float* __restrict__ x, float* __restrict__ y,
                          const float* __restrict__ g, const float* __restrict__ b) {
    int row = blockIdx.x;
    const float* xr = x + (long long)row * DD;
    __shared__ float sh[32];
    __shared__ float sh2[32];
    float s = 0.f, s2 = 0.f;
    for (int d = threadIdx.x; d < DD; d += 256) { float v = xr[d]; s += v; s2 += v * v; }
    int lane = threadIdx.x & 31, wid = threadIdx.x >> 5;
    for (int o = 16; o; o >>= 1) { s += __shfl_xor_sync(~0u, s, o); s2 += __shfl_xor_sync(~0u, s2, o); }
    if (lane == 0) { sh[wid] = s; sh2[wid] = s2; }
    __syncthreads();
    if (wid == 0) {
        s  = (lane < 8) ? sh[lane]  : 0.f;
        s2 = (lane < 8) ? sh2[lane] : 0.f;
        for (int o = 16; o; o >>= 1) { s += __shfl_xor_sync(~0u, s, o); s2 += __shfl_xor_sync(~0u, s2, o); }
        if (lane == 0) { sh[0] = s; sh2[0] = s2; }
    }
    __syncthreads();
    float mean = sh[0] / DD;
    float var  = sh2[0] / DD - mean * mean;
    float inv = rsqrtf(var + 1e-5f);
    float* yr = y + (long long)row * DD;
    for (int d = threadIdx.x; d < DD; d += 256)
        yr[d] = (xr[d] - mean) * inv * g[d] + b[d];
}

__global__ void rope_kernel(float* __restrict__ q, float* __restrict__ k) {
    int idx = blockIdx.x * blockDim.x + threadIdx.x;
    if (idx >= TOK * (DD / 2)) return;
    int t = idx / (DD / 2), j = idx - t * (DD / 2);
    int s = t & (SS - 1);
    float freq = __expf(-9.210340371976184f * ((float)j / 384.f));
    float ang = (float)s * freq;
    float c, sn; sincosf(ang, &sn, &c);
    {
        float* p = q + (long long)t * DD + 2 * j;
        float a = p[0], b = p[1];
        p[0] = a * c - b * sn; p[1] = a * sn + b * c;
    }
    {
        float* p = k + (long long)t * DD + 2 * j;
        float a = p[0], b = p[1];
        p[0] = a * c - b * sn; p[1] = a * sn + b * c;
    }
}

__global__ void softmax_causal(float* __restrict__ sc) {
    int z = blockIdx.y, r = blockIdx.x;
    float* row = sc + ((long long)z << 20) + (long long)r * 1024;
    int n = r + 1;
    __shared__ float sh[32];
    int lane = threadIdx.x & 31, wid = threadIdx.x >> 5;
    float mx = -1e30f;
    for (int j = threadIdx.x; j < n; j += 256) mx = fmaxf(mx, row[j]);
    for (int o = 16; o; o >>= 1) mx = fmaxf(mx, __shfl_xor_sync(~0u, mx, o));
    if (lane == 0) sh[wid] = mx;
    __syncthreads();
    if (wid == 0) {
        mx = (lane < 8) ? sh[lane] : -1e30f;
        for (int o = 16; o; o >>= 1) mx = fmaxf(mx, __shfl_xor_sync(~0u, mx, o));
        if (lane == 0) sh[0] = mx;
    }
    __syncthreads();
    mx = sh[0];
    __syncthreads();
    float s = 0.f;
    for (int j = threadIdx.x; j < n; j += 256) s += __expf(row[j] - mx);
    for (int o = 16; o; o >>= 1) s += __shfl_xor_sync(~0u, s, o);
    if (lane == 0) sh[wid] = s;
    __syncthreads();
    if (wid == 0) {
        s = (lane < 8) ? sh[lane] : 0.f;
        for (int o = 16; o; o >>= 1) s += __shfl_xor_sync(~0u, s, o);
        if (lane == 0) sh[0] = s;
    }
    __syncthreads();
    float inv = 1.f / sh[0];
    for (int j = threadIdx.x; j < 1024; j += 256)
        row[j] = (j < n) ? __expf(row[j] - mx) * inv : 0.f;
}

__global__ void zero_cnt(int* c) { if (threadIdx.x < EE) c[threadIdx.x] = 0; }

__global__ void route_kernel(const float* __restrict__ h, const float* __restrict__ gw,
                             int* cnt, int* etok, int* easn, float* wts) {
    int w = (blockIdx.x * blockDim.x + threadIdx.x) >> 5;
    int lane = threadIdx.x & 31;
    if (w >= TOK) return;
    const float* hr = h + (long long)w * DD;
    float lg[EE];
#pragma unroll
    for (int e = 0; e < EE; e++) {
        float s = 0.f;
        for (int d = lane; d < DD; d += 32) s += hr[d] * gw[d * EE + e];
        for (int o = 16; o; o >>= 1) s += __shfl_xor_sync(~0u, s, o);
        lg[e] = s;
    }
    if (lane == 0) {
        int e0 = 0;
        for (int e = 1; e < EE; e++) if (lg[e] > lg[e0]) e0 = e;
        int e1 = -1;
        for (int e = 0; e < EE; e++) { if (e == e0) continue; if (e1 < 0 || lg[e] > lg[e1]) e1 = e; }
        float x1 = __expf(lg[e1] - lg[e0]);
        float den = 1.f + x1;
        float w0 = 1.f / den, w1 = x1 / den;
        int s0 = atomicAdd(&cnt[e0], 1);
        etok[e0 * TOK + s0] = w; easn[e0 * TOK + s0] = 2 * w;
        int s1 = atomicAdd(&cnt[e1], 1);
        etok[e1 * TOK + s1] = w; easn[e1 * TOK + s1] = 2 * w + 1;
        wts[2 * w] = w0; wts[2 * w + 1] = w1;
    }
}

__global__ void combine_kernel(float* __restrict__ x, const float* __restrict__ ys,
                               const float* __restrict__ wts) {
    int idx = blockIdx.x * blockDim.x + threadIdx.x;
    if (idx >= TOK * DD) return;
    int t = idx / DD, d = idx - t * DD;
    x[idx] += wts[2 * t] * ys[(long long)(2 * t) * DD + d]
            + wts[2 * t + 1] * ys[(long long)(2 * t + 1) * DD + d];
}

__global__ void basis_kernel(float* __restrict__ Cb) {
    int idx = blockIdx.x * blockDim.x + threadIdx.x;
    if (idx >= 1026 * 1024) return;
    int j = idx >> 10, n = idx & 1023;
    const float invN = 1.f / 1024.f;
    float v;
    if (j == 0) v = invN;
    else if (j <= 511) { int m = (j * n) & 1023; v = 2.f * invN * cosf(m * TWO_PI_N); }
    else if (j == 512) v = invN * ((n & 1) ? -1.f : 1.f);
    else if (j == 513 || j == 1025) v = 0.f;
    else { int kk = j - 513; int m = (kk * n) & 1023; v = -2.f * invN * sinf(m * TWO_PI_N); }
    Cb[idx] = v;
}

__global__ void bf_kernel(const float* __restrict__ ob, const float* __restrict__ Cb,
                          float* __restrict__ bf) {
    int n = threadIdx.x;
    float s = 0.f;
    for (int j = 0; j < 1026; j++) s += ob[j] * Cb[j * 1024 + n];
    bf[n] = s;
}

__global__ void istft_kernel(const float* __restrict__ frames, float* __restrict__ out) {
    int idx = blockIdx.x * blockDim.x + threadIdx.x;
    if (idx >= BB * OUTL) return;
    int b = idx / OUTL, i = idx - b * OUTL;
    int ip = i + PADL;
    int tmin = (ip >= 1024) ? ((ip - 768) >> 8) : 0;
    int tmax = min(1023, ip >> 8);
    float acc = 0.f, env = 0.f;
    for (int t = tmin; t <= tmax; t++) {
        int n = ip - (t << 8);
        float w = 0.5f * (1.f - cosf(n * TWO_PI_N));
        acc += frames[((long long)(b * 1024 + t) << 10) + n] * w;
        env += w * w;
    }
    out[idx] = acc / env;
}

// ---------------- host side ----------------
static void* symaddr(const void* sym) {
    void* p = nullptr;
    cudaGetSymbolAddress(&p, sym);
    return p;
}

struct GemmArgs {
    const float* A; int lda; long long sAz, sAz2;
    const float* B; int ldb; long long sBz, sBz2;
    float* C; int ldc; long long sCz, sCz2;
    int zdiv;
    const float* bias; long long sbz; const float* res;
    int M, N, Kd; float alpha; int Z;
    const int* idxA; const int* idxC; const int* cnt;
    int causal; int gridM;
};

static void gemm(int act, bool trb, const GemmArgs& a)
{
    dim3 grid((a.N + 63) / 64, a.gridM ? a.gridM : (a.M + 127) / 128, a.Z);
    if (act == 1)
        gemm_kernel<1, false><<<grid, 256>>>(a.A, a.lda, a.sAz, a.sAz2, a.B, a.ldb, a.sBz, a.sBz2,
                                             a.C, a.ldc, a.sCz, a.sCz2, a.zdiv, a.bias, a.sbz, a.res,
                                             a.M, a.N, a.Kd, a.alpha, a.idxA, a.idxC, a.cnt, a.causal);
    else if (trb)
        gemm_kernel<0, true><<<grid, 256>>>(a.A, a.lda, a.sAz, a.sAz2, a.B, a.ldb, a.sBz, a.sBz2,
                                            a.C, a.ldc, a.sCz, a.sCz2, a.zdiv, a.bias, a.sbz, a.res,
                                            a.M, a.N, a.Kd, a.alpha, a.idxA, a.idxC, a.cnt, a.causal);
    else
        gemm_kernel<0, false><<<grid, 256>>>(a.A, a.lda, a.sAz, a.sAz2, a.B, a.ldb, a.sBz, a.sBz2,
                                             a.C, a.ldc, a.sCz, a.sCz2, a.zdiv, a.bias, a.sbz, a.res,
                                             a.M, a.N, a.Kd, a.alpha, a.idxA, a.idxC, a.cnt, a.causal);
}

extern "C" void kernel_launch(void* const* d_in, const int* in_sizes, int n_in,
                              void* d_out, int out_size)
{
    const float* z_in  = (const float*)d_in[0];
    const float* in_w  = (const float*)d_in[1];
    const float* in_b  = (const float*)d_in[2];
    const float* ln1g  = (const float*)d_in[3];
    const float* ln1b  = (const float*)d_in[4];
    const float* wq    = (const float*)d_in[5];
    const float* bq    = (const float*)d_in[6];
    const float* wk    = (const float*)d_in[7];
    const float* bk    = (const float*)d_in[8];
    const float* wv    = (const float*)d_in[9];
    const float* bv    = (const float*)d_in[10];
    const float* wo    = (const float*)d_in[11];
    const float* bo    = (const float*)d_in[12];
    const float* ln2g  = (const float*)d_in[13];
    const float* ln2b  = (const float*)d_in[14];
    const float* gatew = (const float*)d_in[15];
    const float* ew1   = (const float*)d_in[16];
    const float* eb1   = (const float*)d_in[17];
    const float* ew2   = (const float*)d_in[18];
    const float* eb2   = (const float*)d_in[19];
    const float* outw  = (const float*)d_in[20];
    const float* outb  = (const float*)d_in[21];
    float* out = (float*)d_out;

    float* ZT = (float*)symaddr(g_zt);
    float* X  = (float*)symaddr(g_x);
    float* H  = (float*)symaddr(g_h);
    float* Q  = (float*)symaddr(g_q);
    float* Kb = (float*)symaddr(g_k);
    float* V  = (float*)symaddr(g_v);
    float* AO = (float*)symaddr(g_ao);
    float* SC = (float*)symaddr(g_scores);
    float* HID = (float*)symaddr(g_hidden);
    float* YS = (float*)symaddr(g_yslot);
    float* CB = (float*)symaddr(g_Cb);
    float* MT = (float*)symaddr(g_Mt);
    float* BF = (float*)symaddr(g_bf);
    float* FR = (float*)symaddr(g_frames);
    int* CNT = (int*)symaddr(g_cnt);
    int* ETK = (int*)symaddr(g_etok);
    int* EAS = (int*)symaddr(g_easn);
    float* WTS = (float*)symaddr(g_wts);

    // in_projection: zt = z^T, x = zt @ in_w + in_b
    transpose_z<<<dim3(SS / 32, CIN / 32, BB), dim3(32, 8)>>>(z_in, ZT);
    {
        GemmArgs a = {ZT, CIN, 0, 0, in_w, DD, 0, 0, X, DD, 0, 0, 1,
                      in_b, 0, nullptr, TOK, DD, CIN, 1.f, 1, nullptr, nullptr, nullptr, 0, 0};
        gemm(0, false, a);
    }

    for (int L = 0; L < 2; L++) {
        const float* WQ = wq + (long long)L * DD * DD;
        const float* WK = wk + (long long)L * DD * DD;
        const float* WV = wv + (long long)L * DD * DD;
        const float* WO = wo + (long long)L * DD * DD;

        ln_kernel<<<TOK, 256>>>(X, H, ln1g + L * DD, ln1b + L * DD);
        {
            GemmArgs a = {H, DD, 0, 0, WQ, DD, 0, 0, Q, DD, 0, 0, 1,
                          bq + L * DD, 0, nullptr, TOK, DD, DD, 1.f, 1, 0, 0, 0, 0, 0};
            gemm(0, false, a);
            a.B = WK; a.bias = bk + L * DD; a.C = Kb; gemm(0, false, a);
            a.B = WV; a.bias = bv + L * DD; a.C = V;  gemm(0, false, a);
        }
        if (L == 0)
            rope_kernel<<<(TOK * (DD / 2) + 255) / 256, 256>>>(Q, Kb);

        // scores: z = b*HH + h -> A off = h*HD + b*SS*DD (zdiv=HH)
        {
            GemmArgs a = {Q, DD, HD, (long long)SS * DD,
                          Kb, DD, HD, (long long)SS * DD,
                          SC, SS, (long long)SS * SS, (long long)HH * SS * SS, HH,
                          nullptr, 0, nullptr, SS, SS, HD, 0.125f, BB * HH, 0, 0, 0, 1, 0};
            gemm(0, true, a);
        }
        softmax_causal<<<dim3(SS, BB * HH), 256>>>(SC);
        {
            GemmArgs a = {SC, SS, (long long)SS * SS, (long long)HH * SS * SS,
                          V, DD, HD, (long long)SS * DD,
                          AO, DD, HD, (long long)SS * DD, HH,
                          nullptr, 0, nullptr, SS, HD, SS, 1.f, BB * HH, 0, 0, 0, 0, 0};
            gemm(0, false, a);
        }
        // out proj + residual
        {
            GemmArgs a = {AO, DD, 0, 0, WO, DD, 0, 0, X, DD, 0, 0, 1,
                          bo + L * DD, 0, X, TOK, DD, DD, 1.f, 1, 0, 0, 0, 0, 0};
            gemm(0, false, a);
        }

        // MoE
        ln_kernel<<<TOK, 256>>>(X, H, ln2g + L * DD, ln2b + L * DD);
        zero_cnt<<<1, 32>>>(CNT);
        route_kernel<<<TOK / 8, 256>>>(H, gatew + (long long)L * DD * EE, CNT, ETK, EAS, WTS);
        {
            GemmArgs a = {H, DD, 0, 0,
                          ew1 + (long long)L * EE * DD * FF, FF, (long long)DD * FF, 0,
                          HID, FF, 0, 0, EE,
                          eb1 + (long long)L * EE * FF, FF, nullptr,
                          TOK, FF, DD, 1.f, EE, ETK, EAS, CNT, 0, TOK / 128};
            gemm(1, false, a);
        }
        {
            GemmArgs a = {HID, FF, 0, 0,
                          ew2 + (long long)L * EE * FF * DD, DD, (long long)FF * DD, 0,
                          YS, DD, 0, 0, EE,
                          eb2 + (long long)L * EE * DD, DD, nullptr,
                          TOK, DD, FF, 1.f, EE, EAS, EAS, CNT, 0, TOK / 128};
            gemm(0, false, a);
        }
        combine_kernel<<<(TOK * DD + 255) / 256, 256>>>(X, YS, WTS);
    }

    // out projection fused with irfft basis: frames = x @ (out_w @ Cb) + out_b @ Cb
    basis_kernel<<<(1026 * 1024 + 255) / 256, 256>>>(CB);
    {
        GemmArgs a = {outw, 2 * FB, 0, 0, CB, 1024, 0, 0, MT, 1024, 0, 0, 1,
                      nullptr, 0, nullptr, DD, 1024, 2 * FB, 1.f, 1, 0, 0, 0, 0, 0};
        gemm(0, false, a);
    }
    bf_kernel<<<1, 1024>>>(outb, CB, BF);
    {
        GemmArgs a = {X, DD, 0, 0, MT, 1024, 0, 0, FR, 1024, 0, 0, 1,
                      BF, 0, nullptr, TOK, 1024, DD, 1.f, 1, 0, 0, 0, 0, 0};
        gemm(0, false, a);
    }

    // windowed overlap-add + env normalize + trim
    istft_kernel<<<(BB * OUTL + 255) / 256, 256>>>(FR, out);
}

// round 6
// speedup vs baseline: 1.9902x; 1.1359x over previous
#include <cuda_runtime.h>
#include <math.h>
#include <stdint.h>

// ---------------- constants ----------------
#define BB 2
#define SS 1024
#define DD 768
#define HH 12
#define HD 64
#define EE 8
#define FF 2048
#define CIN 512
#define TOK (BB*SS)          // 2048
#define FB 513
#define PADL 384
#define OUTL 262144
#define TWO_PI_N 0.006135923151542565f   // 2*pi/1024

// ---------------- scratch (device globals; allocation-free) ----------------
__device__ float g_zt[TOK*CIN];
__device__ float g_x [TOK*DD];
__device__ float g_h [TOK*DD];
__device__ float g_q [TOK*DD];
__device__ float g_k [TOK*DD];
__device__ float g_v [TOK*DD];
__device__ float g_ao[TOK*DD];
__device__ float g_scores[24u*1024u*1024u];
__device__ float g_hidden[4096*FF];
__device__ float g_yslot [4096*DD];
__device__ float g_Cb[1026*1024];
__device__ float g_Mt[DD*1024];
__device__ float g_bf[1024];
__device__ float g_frames[TOK*1024];
__device__ int   g_cnt[EE];
__device__ int   g_etok[EE*TOK];
__device__ int   g_easn[EE*TOK];
__device__ float g_wts[2*TOK];

// ---------------- tf32 / async helpers ----------------
// tf32 uses fp32 bits [31:13]; masking low 13 bits is exactly the HW-visible hi part.
__device__ __forceinline__ void split2(float f, uint32_t& hi, uint32_t& lo) {
    uint32_t u = __float_as_uint(f);
    hi = u & 0xFFFFE000u;
    lo = __float_as_uint(f - __uint_as_float(hi));
}
__device__ __forceinline__ void mma_tf32(float* c, const uint32_t* a, const uint32_t* b) {
    asm volatile(
        "mma.sync.aligned.m16n8k8.row.col.f32.tf32.tf32.f32 "
        "{%0,%1,%2,%3}, {%4,%5,%6,%7}, {%8,%9}, {%0,%1,%2,%3};"
        : "+f"(c[0]), "+f"(c[1]), "+f"(c[2]), "+f"(c[3])
        : "r"(a[0]), "r"(a[1]), "r"(a[2]), "r"(a[3]), "r"(b[0]), "r"(b[1]));
}
__device__ __forceinline__ void cpa16(uint32_t dst, const float* src, bool pred) {
    asm volatile("cp.async.ca.shared.global [%0], [%1], 16, %2;"
                 :: "r"(dst), "l"(src), "r"(pred ? 16 : 0));
}
__device__ __forceinline__ void cpa_commit() { asm volatile("cp.async.commit_group;"); }
__device__ __forceinline__ void cpa_wait1() { asm volatile("cp.async.wait_group 1;"); }

// ---------------- pipelined tensor-core GEMM (3xTF32, cp.async 3-stage) ----------------
// Tile: 128(M) x BN(N), K-step 16. 8 warps as 4(M) x 2(N); warp = 32 x BN/2.
#define STG 3
#define A_LD 20
#define ASTG 2560   // 128 * A_LD floats

template<int ACT, bool TRB, int BN>
__global__ __launch_bounds__(256, 2)
void gemm_kernel(const float* __restrict__ A, int lda, long long sAz, long long sAz2,
                 const float* __restrict__ B, int ldb, long long sBz, long long sBz2,
                 float* __restrict__ C, int ldc, long long sCz, long long sCz2,
                 int zdiv,
                 const float* __restrict__ bias, long long sbz,
                 const float* __restrict__ res,
                 int M, int N, int Kd, float alpha,
                 const int* __restrict__ idxA, const int* __restrict__ idxC,
                 const int* __restrict__ cnt, int causal)
{
    constexpr int B_LDc = TRB ? A_LD : (BN + 8);
    constexpr int BSTGc = TRB ? (BN * A_LD) : (16 * (BN + 8));
    constexpr int BJ = BN / 16;

    int z = blockIdx.z;
    int z1 = z / zdiv, z0 = z - z1 * zdiv;
    if (cnt) M = cnt[z];
    int m0 = blockIdx.y * 128, n0 = blockIdx.x * BN;
    if (m0 >= M) return;
    if (causal && n0 > m0 + 127) return;
    A += (long long)z0 * sAz + (long long)z1 * sAz2;
    B += (long long)z0 * sBz + (long long)z1 * sBz2;
    C += (long long)z0 * sCz + (long long)z1 * sCz2;
    if (bias) bias += (long long)z * sbz;
    if (res)  res  += (long long)z0 * sCz + (long long)z1 * sCz2;
    const int* iA = idxA ? idxA + z * TOK : nullptr;
    const int* iC = idxC ? idxC + z * TOK : nullptr;

    extern __shared__ float smem[];
    float* AsF = smem;
    float* BsF = smem + STG * ASTG;
    uint32_t sA = (uint32_t)__cvta_generic_to_shared(AsF);
    uint32_t sB = (uint32_t)__cvta_generic_to_shared(BsF);

    int tid = threadIdx.x;
    int lane = tid & 31, wid = tid >> 5;
    int wm = wid >> 1, wn = wid & 1;
    int lm = lane >> 2, lk = lane & 3;

    float acc[2][BJ][4];
#pragma unroll
    for (int i = 0; i < 2; i++)
#pragma unroll
        for (int j = 0; j < BJ; j++)
#pragma unroll
            for (int r = 0; r < 4; r++) acc[i][j][r] = 0.f;

    const bool fastA = ((lda & 3) == 0) && ((Kd & 15) == 0);
    const bool fastB = ((ldb & 3) == 0) && (TRB ? ((Kd & 15) == 0) : true);

    auto load_stage = [&](int s, int k0) {
        // ---- A: 128 rows x 16 k, smem [m][A_LD] ----
        if (fastA) {
#pragma unroll
            for (int it = 0; it < 2; it++) {
                int lin = tid + it * 256;
                int mm = lin >> 2, q = lin & 3;
                int gm = m0 + mm;
                int ra = (gm < M) ? (iA ? iA[gm] : gm) : -1;
                const float* src = A + (long long)(ra >= 0 ? ra : 0) * lda + k0 + 4 * q;
                cpa16(sA + ((s * ASTG + mm * A_LD + 4 * q) << 2), src, ra >= 0);
            }
        } else {
#pragma unroll
            for (int it = 0; it < 2; it++) {
                int lin = tid + it * 256;
                int mm = lin >> 2, q = lin & 3;
                int gm = m0 + mm;
                int ra = (gm < M) ? (iA ? iA[gm] : gm) : -1;
                float* dst = &AsF[s * ASTG + mm * A_LD + 4 * q];
#pragma unroll
                for (int j = 0; j < 4; j++) {
                    int gk = k0 + 4 * q + j;
                    dst[j] = (ra >= 0 && gk < Kd) ? A[(long long)ra * lda + gk] : 0.f;
                }
            }
        }
        // ---- B ----
        if (!TRB) {
#pragma unroll
            for (int it = 0; it < BN / 64; it++) {
                int lin = tid + it * 256;
                int k = lin / (BN / 4), q = lin % (BN / 4);
                int gk = k0 + k;
                if (fastB) {
                    const float* src = B + (long long)(gk < Kd ? gk : 0) * ldb + n0 + 4 * q;
                    cpa16(sB + ((s * BSTGc + k * B_LDc + 4 * q) << 2), src, gk < Kd);
                } else {
                    float* dst = &BsF[s * BSTGc + k * B_LDc + 4 * q];
#pragma unroll
                    for (int j = 0; j < 4; j++)
                        dst[j] = (gk < Kd) ? B[(long long)gk * ldb + n0 + 4 * q + j] : 0.f;
                }
            }
        } else {
#pragma unroll
            for (int it = 0; it < BN / 64; it++) {
                int lin = tid + it * 256;
                int nn = lin >> 2, q = lin & 3;
                int gn = n0 + nn;
                if (fastB) {
                    const float* src = B + (long long)(gn < N ? gn : 0) * ldb + k0 + 4 * q;
                    cpa16(sB + ((s * BSTGc + nn * B_LDc + 4 * q) << 2), src, gn < N);
                } else {
                    float* dst = &BsF[s * BSTGc + nn * B_LDc + 4 * q];
#pragma unroll
                    for (int j = 0; j < 4; j++) {
                        int gk = k0 + 4 * q + j;
                        dst[j] = (gn < N && gk < Kd) ? B[(long long)gn * ldb + gk] : 0.f;
                    }
                }
            }
        }
    };

    auto compute = [&](int s) {
        const float* As_ = AsF + s * ASTG;
        const float* Bs_ = BsF + s * BSTGc;
#pragma unroll
        for (int ks = 0; ks < 2; ks++) {
            int kk = ks * 8;
            uint32_t ah[2][4], al[2][4];
#pragma unroll
            for (int i = 0; i < 2; i++) {
                const float* r0 = As_ + (wm * 32 + i * 16 + lm) * A_LD;
                const float* r1 = r0 + 8 * A_LD;
                split2(r0[kk + lk],     ah[i][0], al[i][0]);
                split2(r1[kk + lk],     ah[i][1], al[i][1]);
                split2(r0[kk + lk + 4], ah[i][2], al[i][2]);
                split2(r1[kk + lk + 4], ah[i][3], al[i][3]);
            }
#pragma unroll
            for (int j = 0; j < BJ; j++) {
                int bn = wn * (BN / 2) + j * 8 + lm;
                float f0, f1;
                if (!TRB) {
                    f0 = Bs_[(kk + lk) * B_LDc + bn];
                    f1 = Bs_[(kk + lk + 4) * B_LDc + bn];
                } else {
                    f0 = Bs_[bn * B_LDc + kk + lk];
                    f1 = Bs_[bn * B_LDc + kk + lk + 4];
                }
                uint32_t bh[2], bl[2];
                split2(f0, bh[0], bl[0]);
                split2(f1, bh[1], bl[1]);
#pragma unroll
                for (int i = 0; i < 2; i++) {
                    mma_tf32(acc[i][j], ah[i], bh);
                    mma_tf32(acc[i][j], ah[i], bl);
                    mma_tf32(acc[i][j], al[i], bh);
                }
            }
        }
    };

    int nk = (Kd + 15) >> 4;
#pragma unroll
    for (int p = 0; p < STG - 1; p++) {
        if (p < nk) load_stage(p, p * 16);
        cpa_commit();
    }
    for (int i = 0; i < nk; i++) {
        cpa_wait1();
        __syncthreads();
        int nx = i + STG - 1;
        if (nx < nk) load_stage(nx % STG, nx * 16);
        cpa_commit();
        compute(i % STG);
    }

    // ---- epilogue ----
#pragma unroll
    for (int i = 0; i < 2; i++) {
#pragma unroll
        for (int r2 = 0; r2 < 2; r2++) {
            int gm = m0 + wm * 32 + i * 16 + lm + r2 * 8;
            if (gm >= M) continue;
            int rc = iC ? iC[gm] : gm;
            float* crow = C + (long long)rc * ldc;
            const float* rrow = res ? res + (long long)rc * ldc : nullptr;
#pragma unroll
            for (int j = 0; j < BJ; j++) {
#pragma unroll
                for (int c2 = 0; c2 < 2; c2++) {
                    int gn = n0 + wn * (BN / 2) + j * 8 + lk * 2 + c2;
                    if (gn >= N) continue;
                    float v = acc[i][j][r2 * 2 + c2] * alpha;
                    if (bias) v += bias[gn];
                    if (ACT == 1) {
                        float x = v;
                        float t = tanhf(0.7978845608028654f * (x + 0.044715f * x * x * x));
                        v = 0.5f * x * (1.f + t);
                    }
                    if (rrow) v += rrow[gn];
                    crow[gn] = v;
                }
            }
        }
    }
}

// ---------------- small kernels ----------------
__global__ void transpose_z(const float* __restrict__ z, float* __restrict__ zt) {
    __shared__ float tile[32][33];
    int b = blockIdx.z;
    int l0 = blockIdx.x * 32, c0 = blockIdx.y * 32;
    int x = threadIdx.x, y = threadIdx.y;
    for (int i = y; i < 32; i += 8)
        tile[i][x] = z[b * CIN * SS + (c0 + i) * SS + l0 + x];
    __syncthreads();
    for (int i = y; i < 32; i += 8)
        zt[b * SS * CIN + (long long)(l0 + i) * CIN + c0 + x] = tile[x][i];
}

__global__ void ln_kernel(const float* __restrict__ x, float* __restrict__ y,
                          const float* __restrict__ g, const float* __restrict__ b) {
    int row = blockIdx.x;
    const float* xr = x + (long long)row * DD;
    __shared__ float sh[32];
    __shared__ float sh2[32];
    float s = 0.f, s2 = 0.f;
    for (int d = threadIdx.x; d < DD; d += 256) { float v = xr[d]; s += v; s2 += v * v; }
    int lane = threadIdx.x & 31, wid = threadIdx.x >> 5;
    for (int o = 16; o; o >>= 1) { s += __shfl_xor_sync(~0u, s, o); s2 += __shfl_xor_sync(~0u, s2, o); }
    if (lane == 0) { sh[wid] = s; sh2[wid] = s2; }
    __syncthreads();
    if (wid == 0) {
        s  = (lane < 8) ? sh[lane]  : 0.f;
        s2 = (lane < 8) ? sh2[lane] : 0.f;
        for (int o = 16; o; o >>= 1) { s += __shfl_xor_sync(~0u, s, o); s2 += __shfl_xor_sync(~0u, s2, o); }
        if (lane == 0) { sh[0] = s; sh2[0] = s2; }
    }
    __syncthreads();
    float mean = sh[0] / DD;
    float var  = sh2[0] / DD - mean * mean;
    float inv = rsqrtf(var + 1e-5f);
    float* yr = y + (long long)row * DD;
    for (int d = threadIdx.x; d < DD; d += 256)
        yr[d] = (xr[d] - mean) * inv * g[d] + b[d];
}

__global__ void rope_kernel(float* __restrict__ q, float* __restrict__ k) {
    int idx = blockIdx.x * blockDim.x + threadIdx.x;
    if (idx >= TOK * (DD / 2)) return;
    int t = idx / (DD / 2), j = idx - t * (DD / 2);
    int s = t & (SS - 1);
    float freq = __expf(-9.210340371976184f * ((float)j / 384.f));
    float ang = (float)s * freq;
    float c, sn; sincosf(ang, &sn, &c);
    {
        float* p = q + (long long)t * DD + 2 * j;
        float a = p[0], b = p[1];
        p[0] = a * c - b * sn; p[1] = a * sn + b * c;
    }
    {
        float* p = k + (long long)t * DD + 2 * j;
        float a = p[0], b = p[1];
        p[0] = a * c - b * sn; p[1] = a * sn + b * c;
    }
}

__global__ void softmax_causal(float* __restrict__ sc) {
    int z = blockIdx.y, r = blockIdx.x;
    float* row = sc + ((long long)z << 20) + (long long)r * 1024;
    int n = r + 1;
    __shared__ float sh[32];
    int lane = threadIdx.x & 31, wid = threadIdx.x >> 5;
    float mx = -1e30f;
    for (int j = threadIdx.x; j < n; j += 256) mx = fmaxf(mx, row[j]);
    for (int o = 16; o; o >>= 1) mx = fmaxf(mx, __shfl_xor_sync(~0u, mx, o));
    if (lane == 0) sh[wid] = mx;
    __syncthreads();
    if (wid == 0) {
        mx = (lane < 8) ? sh[lane] : -1e30f;
        for (int o = 16; o; o >>= 1) mx = fmaxf(mx, __shfl_xor_sync(~0u, mx, o));
        if (lane == 0) sh[0] = mx;
    }
    __syncthreads();
    mx = sh[0];
    __syncthreads();
    float s = 0.f;
    for (int j = threadIdx.x; j < n; j += 256) s += __expf(row[j] - mx);
    for (int o = 16; o; o >>= 1) s += __shfl_xor_sync(~0u, s, o);
    if (lane == 0) sh[wid] = s;
    __syncthreads();
    if (wid == 0) {
        s = (lane < 8) ? sh[lane] : 0.f;
        for (int o = 16; o; o >>= 1) s += __shfl_xor_sync(~0u, s, o);
        if (lane == 0) sh[0] = s;
    }
    __syncthreads();
    float inv = 1.f / sh[0];
    for (int j = threadIdx.x; j < 1024; j += 256)
        row[j] = (j < n) ? __expf(row[j] - mx) * inv : 0.f;
}

__global__ void zero_cnt(int* c) { if (threadIdx.x < EE) c[threadIdx.x] = 0; }

__global__ void route_kernel(const float* __restrict__ h, const float* __restrict__ gw,
                             int* cnt, int* etok, int* easn, float* wts) {
    int w = (blockIdx.x * blockDim.x + threadIdx.x) >> 5;
    int lane = threadIdx.x & 31;
    if (w >= TOK) return;
    const float* hr = h + (long long)w * DD;
    float lg[EE];
#pragma unroll
    for (int e = 0; e < EE; e++) {
        float s = 0.f;
        for (int d = lane; d < DD; d += 32) s += hr[d] * gw[d * EE + e];
        for (int o = 16; o; o >>= 1) s += __shfl_xor_sync(~0u, s, o);
        lg[e] = s;
    }
    if (lane == 0) {
        int e0 = 0;
        for (int e = 1; e < EE; e++) if (lg[e] > lg[e0]) e0 = e;
        int e1 = -1;
        for (int e = 0; e < EE; e++) { if (e == e0) continue; if (e1 < 0 || lg[e] > lg[e1]) e1 = e; }
        float x1 = __expf(lg[e1] - lg[e0]);
        float den = 1.f + x1;
        float w0 = 1.f / den, w1 = x1 / den;
        int s0 = atomicAdd(&cnt[e0], 1);
        etok[e0 * TOK + s0] = w; easn[e0 * TOK + s0] = 2 * w;
        int s1 = atomicAdd(&cnt[e1], 1);
        etok[e1 * TOK + s1] = w; easn[e1 * TOK + s1] = 2 * w + 1;
        wts[2 * w] = w0; wts[2 * w + 1] = w1;
    }
}

__global__ void combine_kernel(float* __restrict__ x, const float* __restrict__ ys,
                               const float* __restrict__ wts) {
    int idx = blockIdx.x * blockDim.x + threadIdx.x;
    if (idx >= TOK * DD) return;
    int t = idx / DD, d = idx - t * DD;
    x[idx] += wts[2 * t] * ys[(long long)(2 * t) * DD + d]
            + wts[2 * t + 1] * ys[(long long)(2 * t + 1) * DD + d];
}

__global__ void basis_kernel(float* __restrict__ Cb) {
    int idx = blockIdx.x * blockDim.x + threadIdx.x;
    if (idx >= 1026 * 1024) return;
    int j = idx >> 10, n = idx & 1023;
    const float invN = 1.f / 1024.f;
    float v;
    if (j == 0) v = invN;
    else if (j <= 511) { int m = (j * n) & 1023; v = 2.f * invN * cosf(m * TWO_PI_N); }
    else if (j == 512) v = invN * ((n & 1) ? -1.f : 1.f);
    else if (j == 513 || j == 1025) v = 0.f;
    else { int kk = j - 513; int m = (kk * n) & 1023; v = -2.f * invN * sinf(m * TWO_PI_N); }
    Cb[idx] = v;
}

__global__ void bf_kernel(const float* __restrict__ ob, const float* __restrict__ Cb,
                          float* __restrict__ bf) {
    int n = threadIdx.x;
    float s = 0.f;
    for (int j = 0; j < 1026; j++) s += ob[j] * Cb[j * 1024 + n];
    bf[n] = s;
}

__global__ void istft_kernel(const float* __restrict__ frames, float* __restrict__ out) {
    int idx = blockIdx.x * blockDim.x + threadIdx.x;
    if (idx >= BB * OUTL) return;
    int b = idx / OUTL, i = idx - b * OUTL;
    int ip = i + PADL;
    int tmin = (ip >= 1024) ? ((ip - 768) >> 8) : 0;
    int tmax = min(1023, ip >> 8);
    float acc = 0.f, env = 0.f;
    for (int t = tmin; t <= tmax; t++) {
        int n = ip - (t << 8);
        float w = 0.5f * (1.f - cosf(n * TWO_PI_N));
        acc += frames[((long long)(b * 1024 + t) << 10) + n] * w;
        env += w * w;
    }
    out[idx] = acc / env;
}

// ---------------- host side ----------------
static void* symaddr(const void* sym) {
    void* p = nullptr;
    cudaGetSymbolAddress(&p, sym);
    return p;
}

struct GemmArgs {
    const float* A; int lda; long long sAz, sAz2;
    const float* B; int ldb; long long sBz, sBz2;
    float* C; int ldc; long long sCz, sCz2;
    int zdiv;
    const float* bias; long long sbz; const float* res;
    int M, N, Kd; float alpha; int Z;
    const int* idxA; const int* idxC; const int* cnt;
    int causal; int gridM;
};

#define SMEM_BYTES(TRB, BN) (4 * STG * (ASTG + ((TRB) ? ((BN) * A_LD) : (16 * ((BN) + 8)))))

static void gemm(int act, bool trb, int BN, const GemmArgs& a)
{
    dim3 grid((a.N + BN - 1) / BN, a.gridM ? a.gridM : (a.M + 127) / 128, a.Z);
    if (act == 1) {
        size_t shm = SMEM_BYTES(false, 128);
        cudaFuncSetAttribute(gemm_kernel<1, false, 128>, cudaFuncAttributeMaxDynamicSharedMemorySize, (int)shm);
        gemm_kernel<1, false, 128><<<grid, 256, shm>>>(a.A, a.lda, a.sAz, a.sAz2, a.B, a.ldb, a.sBz, a.sBz2,
            a.C, a.ldc, a.sCz, a.sCz2, a.zdiv, a.bias, a.sbz, a.res,
            a.M, a.N, a.Kd, a.alpha, a.idxA, a.idxC, a.cnt, a.causal);
    } else if (trb) {
        size_t shm = SMEM_BYTES(true, 128);
        cudaFuncSetAttribute(gemm_kernel<0, true, 128>, cudaFuncAttributeMaxDynamicSharedMemorySize, (int)shm);
        gemm_kernel<0, true, 128><<<grid, 256, shm>>>(a.A, a.lda, a.sAz, a.sAz2, a.B, a.ldb, a.sBz, a.sBz2,
            a.C, a.ldc, a.sCz, a.sCz2, a.zdiv, a.bias, a.sbz, a.res,
            a.M, a.N, a.Kd, a.alpha, a.idxA, a.idxC, a.cnt, a.causal);
    } else if (BN == 128) {
        size_t shm = SMEM_BYTES(false, 128);
        cudaFuncSetAttribute(gemm_kernel<0, false, 128>, cudaFuncAttributeMaxDynamicSharedMemorySize, (int)shm);
        gemm_kernel<0, false, 128><<<grid, 256, shm>>>(a.A, a.lda, a.sAz, a.sAz2, a.B, a.ldb, a.sBz, a.sBz2,
            a.C, a.ldc, a.sCz, a.sCz2, a.zdiv, a.bias, a.sbz, a.res,
            a.M, a.N, a.Kd, a.alpha, a.idxA, a.idxC, a.cnt, a.causal);
    } else {
        size_t shm = SMEM_BYTES(false, 64);
        cudaFuncSetAttribute(gemm_kernel<0, false, 64>, cudaFuncAttributeMaxDynamicSharedMemorySize, (int)shm);
        gemm_kernel<0, false, 64><<<grid, 256, shm>>>(a.A, a.lda, a.sAz, a.sAz2, a.B, a.ldb, a.sBz, a.sBz2,
            a.C, a.ldc, a.sCz, a.sCz2, a.zdiv, a.bias, a.sbz, a.res,
            a.M, a.N, a.Kd, a.alpha, a.idxA, a.idxC, a.cnt, a.causal);
    }
}

extern "C" void kernel_launch(void* const* d_in, const int* in_sizes, int n_in,
                              void* d_out, int out_size)
{
    const float* z_in  = (const float*)d_in[0];
    const float* in_w  = (const float*)d_in[1];
    const float* in_b  = (const float*)d_in[2];
    const float* ln1g  = (const float*)d_in[3];
    const float* ln1b  = (const float*)d_in[4];
    const float* wq    = (const float*)d_in[5];
    const float* bq    = (const float*)d_in[6];
    const float* wk    = (const float*)d_in[7];
    const float* bk    = (const float*)d_in[8];
    const float* wv    = (const float*)d_in[9];
    const float* bv    = (const float*)d_in[10];
    const float* wo    = (const float*)d_in[11];
    const float* bo    = (const float*)d_in[12];
    const float* ln2g  = (const float*)d_in[13];
    const float* ln2b  = (const float*)d_in[14];
    const float* gatew = (const float*)d_in[15];
    const float* ew1   = (const float*)d_in[16];
    const float* eb1   = (const float*)d_in[17];
    const float* ew2   = (const float*)d_in[18];
    const float* eb2   = (const float*)d_in[19];
    const float* outw  = (const float*)d_in[20];
    const float* outb  = (const float*)d_in[21];
    float* out = (float*)d_out;

    float* ZT = (float*)symaddr(g_zt);
    float* X  = (float*)symaddr(g_x);
    float* H  = (float*)symaddr(g_h);
    float* Q  = (float*)symaddr(g_q);
    float* Kb = (float*)symaddr(g_k);
    float* V  = (float*)symaddr(g_v);
    float* AO = (float*)symaddr(g_ao);
    float* SC = (float*)symaddr(g_scores);
    float* HID = (float*)symaddr(g_hidden);
    float* YS = (float*)symaddr(g_yslot);
    float* CB = (float*)symaddr(g_Cb);
    float* MT = (float*)symaddr(g_Mt);
    float* BF = (float*)symaddr(g_bf);
    float* FR = (float*)symaddr(g_frames);
    int* CNT = (int*)symaddr(g_cnt);
    int* ETK = (int*)symaddr(g_etok);
    int* EAS = (int*)symaddr(g_easn);
    float* WTS = (float*)symaddr(g_wts);

    // in_projection: zt = z^T, x = zt @ in_w + in_b
    transpose_z<<<dim3(SS / 32, CIN / 32, BB), dim3(32, 8)>>>(z_in, ZT);
    {
        GemmArgs a = {ZT, CIN, 0, 0, in_w, DD, 0, 0, X, DD, 0, 0, 1,
                      in_b, 0, nullptr, TOK, DD, CIN, 1.f, 1, nullptr, nullptr, nullptr, 0, 0};
        gemm(0, false, 128, a);
    }

    for (int L = 0; L < 2; L++) {
        const float* WQ = wq + (long long)L * DD * DD;
        const float* WK = wk + (long long)L * DD * DD;
        const float* WV = wv + (long long)L * DD * DD;
        const float* WO = wo + (long long)L * DD * DD;

        ln_kernel<<<TOK, 256>>>(X, H, ln1g + L * DD, ln1b + L * DD);
        {
            GemmArgs a = {H, DD, 0, 0, WQ, DD, 0, 0, Q, DD, 0, 0, 1,
                          bq + L * DD, 0, nullptr, TOK, DD, DD, 1.f, 1, 0, 0, 0, 0, 0};
            gemm(0, false, 128, a);
            a.B = WK; a.bias = bk + L * DD; a.C = Kb; gemm(0, false, 128, a);
            a.B = WV; a.bias = bv + L * DD; a.C = V;  gemm(0, false, 128, a);
        }
        if (L == 0)
            rope_kernel<<<(TOK * (DD / 2) + 255) / 256, 256>>>(Q, Kb);

        // scores: z = b*HH + h -> A off = h*HD + b*SS*DD (zdiv=HH)
        {
            GemmArgs a = {Q, DD, HD, (long long)SS * DD,
                          Kb, DD, HD, (long long)SS * DD,
                          SC, SS, (long long)SS * SS, (long long)HH * SS * SS, HH,
                          nullptr, 0, nullptr, SS, SS, HD, 0.125f, BB * HH, 0, 0, 0, 1, 0};
            gemm(0, true, 128, a);
        }
        softmax_causal<<<dim3(SS, BB * HH), 256>>>(SC);
        {
            GemmArgs a = {SC, SS, (long long)SS * SS, (long long)HH * SS * SS,
                          V, DD, HD, (long long)SS * DD,
                          AO, DD, HD, (long long)SS * DD, HH,
                          nullptr, 0, nullptr, SS, HD, SS, 1.f, BB * HH, 0, 0, 0, 0, 0};
            gemm(0, false, 64, a);
        }
        // out proj + residual
        {
            GemmArgs a = {AO, DD, 0, 0, WO, DD, 0, 0, X, DD, 0, 0, 1,
                          bo + L * DD, 0, X, TOK, DD, DD, 1.f, 1, 0, 0, 0, 0, 0};
            gemm(0, false, 128, a);
        }

        // MoE
        ln_kernel<<<TOK, 256>>>(X, H, ln2g + L * DD, ln2b + L * DD);
        zero_cnt<<<1, 32>>>(CNT);
        route_kernel<<<TOK / 8, 256>>>(H, gatew + (long long)L * DD * EE, CNT, ETK, EAS, WTS);
        {
            GemmArgs a = {H, DD, 0, 0,
                          ew1 + (long long)L * EE * DD * FF, FF, (long long)DD * FF, 0,
                          HID, FF, 0, 0, EE,
                          eb1 + (long long)L * EE * FF, FF, nullptr,
                          TOK, FF, DD, 1.f, EE, ETK, EAS, CNT, 0, TOK / 128};
            gemm(1, false, 128, a);
        }
        {
            GemmArgs a = {HID, FF, 0, 0,
                          ew2 + (long long)L * EE * FF * DD, DD, (long long)FF * DD, 0,
                          YS, DD, 0, 0, EE,
                          eb2 + (long long)L * EE * DD, DD, nullptr,
                          TOK, DD, FF, 1.f, EE, EAS, EAS, CNT, 0, TOK / 128};
            gemm(0, false, 128, a);
        }
        combine_kernel<<<(TOK * DD + 255) / 256, 256>>>(X, YS, WTS);
    }

    // out projection fused with irfft basis: frames = x @ (out_w @ Cb) + out_b @ Cb
    basis_kernel<<<(1026 * 1024 + 255) / 256, 256>>>(CB);
    {
        GemmArgs a = {outw, 2 * FB, 0, 0, CB, 1024, 0, 0, MT, 1024, 0, 0, 1,
                      nullptr, 0, nullptr, DD, 1024, 2 * FB, 1.f, 1, 0, 0, 0, 0, 0};
        gemm(0, false, 128, a);
    }
    bf_kernel<<<1, 1024>>>(outb, CB, BF);
    {
        GemmArgs a = {X, DD, 0, 0, MT, 1024, 0, 0, FR, 1024, 0, 0, 1,
                      BF, 0, nullptr, TOK, 1024, DD, 1.f, 1, 0, 0, 0, 0, 0};
        gemm(0, false, 128, a);
    }

    // windowed overlap-add + env normalize + trim
    istft_kernel<<<(BB * OUTL + 255) / 256, 256>>>(FR, out);
}

// round 7
// speedup vs baseline: 2.2692x; 1.1402x over previous
#include <cuda_runtime.h>
#include <math.h>
#include <stdint.h>

// ---------------- constants ----------------
#define BB 2
#define SS 1024
#define DD 768
#define HH 12
#define HD 64
#define EE 8
#define FF 2048
#define CIN 512
#define TOK (BB*SS)          // 2048
#define FB 513
#define PADL 384
#define OUTL 262144
#define TWO_PI_N 0.006135923151542565f   // 2*pi/1024

// ---------------- scratch (device globals; allocation-free) ----------------
__device__ float g_zt[TOK*CIN];
__device__ float g_x [TOK*DD];
__device__ float g_h [TOK*DD];
__device__ float g_qkv[3*TOK*DD];
__device__ float g_wqkv[3*DD*DD];
__device__ float g_bqkv[3*DD];
__device__ float g_ao[TOK*DD];
__device__ float g_scores[24u*1024u*1024u];
__device__ float g_hidden[4096*FF];
__device__ float g_yslot [4096*DD];
__device__ float g_Cb[1026*1024];
__device__ float g_Mt[DD*1024];
__device__ float g_bf[1024];
__device__ float g_frames[TOK*1024];
__device__ int   g_cnt[EE];
__device__ int   g_etok[EE*TOK];
__device__ int   g_easn[EE*TOK];
__device__ float g_wts[2*TOK];

// ---------------- tf32 / async helpers ----------------
__device__ __forceinline__ void split2(float f, uint32_t& hi, uint32_t& lo) {
    uint32_t u = __float_as_uint(f);
    hi = u & 0xFFFFE000u;
    lo = __float_as_uint(f - __uint_as_float(hi));
}
__device__ __forceinline__ void mma_tf32(float* c, const uint32_t* a, const uint32_t* b) {
    asm volatile(
        "mma.sync.aligned.m16n8k8.row.col.f32.tf32.tf32.f32 "
        "{%0,%1,%2,%3}, {%4,%5,%6,%7}, {%8,%9}, {%0,%1,%2,%3};"
        : "+f"(c[0]), "+f"(c[1]), "+f"(c[2]), "+f"(c[3])
        : "r"(a[0]), "r"(a[1]), "r"(a[2]), "r"(a[3]), "r"(b[0]), "r"(b[1]));
}
__device__ __forceinline__ void cpa16(uint32_t dst, const float* src, bool pred) {
    asm volatile("cp.async.ca.shared.global [%0], [%1], 16, %2;"
                 :: "r"(dst), "l"(src), "r"(pred ? 16 : 0));
}
__device__ __forceinline__ void cpa_commit() { asm volatile("cp.async.commit_group;"); }
__device__ __forceinline__ void cpa_wait1() { asm volatile("cp.async.wait_group 1;"); }

// ---------------- pipelined tensor-core GEMM (3xTF32, cp.async 3-stage) ----------------
// Tile: 64(M) x BN(N), K-step 16. 8 warps as 2(M) x 4(N); warp = 32 x BN/4.
#define STG 3
#define A_LD 20
#define ASTG 1280   // 64 * A_LD floats

template<int ACT, bool TRB, int BN>
__global__ __launch_bounds__(256, 2)
void gemm_kernel(const float* __restrict__ A, int lda, long long sAz, long long sAz2,
                 const float* __restrict__ B, int ldb, long long sBz, long long sBz2,
                 float* __restrict__ C, int ldc, long long sCz, long long sCz2,
                 int zdiv,
                 const float* __restrict__ bias, long long sbz,
                 const float* __restrict__ res,
                 int M, int N, int Kd, float alpha,
                 const int* __restrict__ idxA, const int* __restrict__ idxC,
                 const int* __restrict__ cnt, int causal)
{
    constexpr int B_LDc = TRB ? A_LD : (BN + 8);
    constexpr int BSTGc = TRB ? (BN * A_LD) : (16 * (BN + 8));
    constexpr int BJ = BN / 32;      // j-fragments per warp (warp covers BN/4 cols)

    int z = blockIdx.z;
    int z1 = z / zdiv, z0 = z - z1 * zdiv;
    if (cnt) M = cnt[z];
    int m0 = blockIdx.y * 64, n0 = blockIdx.x * BN;
    if (m0 >= M) return;
    if (causal && n0 > m0 + 63) return;
    A += (long long)z0 * sAz + (long long)z1 * sAz2;
    B += (long long)z0 * sBz + (long long)z1 * sBz2;
    C += (long long)z0 * sCz + (long long)z1 * sCz2;
    if (bias) bias += (long long)z * sbz;
    if (res)  res  += (long long)z0 * sCz + (long long)z1 * sCz2;
    const int* iA = idxA ? idxA + z * TOK : nullptr;
    const int* iC = idxC ? idxC + z * TOK : nullptr;

    extern __shared__ float smem[];
    float* AsF = smem;
    float* BsF = smem + STG * ASTG;
    uint32_t sA = (uint32_t)__cvta_generic_to_shared(AsF);
    uint32_t sB = (uint32_t)__cvta_generic_to_shared(BsF);

    int tid = threadIdx.x;
    int lane = tid & 31, wid = tid >> 5;
    int wm = wid >> 2, wn = wid & 3;
    int lm = lane >> 2, lk = lane & 3;

    float acc[2][BJ][4];
#pragma unroll
    for (int i = 0; i < 2; i++)
#pragma unroll
        for (int j = 0; j < BJ; j++)
#pragma unroll
            for (int r = 0; r < 4; r++) acc[i][j][r] = 0.f;

    const bool fastA = ((lda & 3) == 0) && ((Kd & 15) == 0);
    const bool fastB = ((ldb & 3) == 0) && (TRB ? ((Kd & 15) == 0) : true);

    auto load_stage = [&](int s, int k0) {
        // ---- A: 64 rows x 16 k, smem [m][A_LD] ----
        {
            int mm = tid >> 2, q = tid & 3;
            int gm = m0 + mm;
            int ra = (gm < M) ? (iA ? iA[gm] : gm) : -1;
            if (fastA) {
                const float* src = A + (long long)(ra >= 0 ? ra : 0) * lda + k0 + 4 * q;
                cpa16(sA + ((s * ASTG + mm * A_LD + 4 * q) << 2), src, ra >= 0);
            } else {
                float* dst = &AsF[s * ASTG + mm * A_LD + 4 * q];
#pragma unroll
                for (int j = 0; j < 4; j++) {
                    int gk = k0 + 4 * q + j;
                    dst[j] = (ra >= 0 && gk < Kd) ? A[(long long)ra * lda + gk] : 0.f;
                }
            }
        }
        // ---- B ----
        if (!TRB) {
#pragma unroll
            for (int it = 0; it < BN / 64; it++) {
                int lin = tid + it * 256;
                int k = lin / (BN / 4), q = lin % (BN / 4);
                int gk = k0 + k;
                if (fastB) {
                    const float* src = B + (long long)(gk < Kd ? gk : 0) * ldb + n0 + 4 * q;
                    cpa16(sB + ((s * BSTGc + k * B_LDc + 4 * q) << 2), src, gk < Kd);
                } else {
                    float* dst = &BsF[s * BSTGc + k * B_LDc + 4 * q];
#pragma unroll
                    for (int j = 0; j < 4; j++)
                        dst[j] = (gk < Kd) ? B[(long long)gk * ldb + n0 + 4 * q + j] : 0.f;
                }
            }
        } else {
#pragma unroll
            for (int it = 0; it < BN / 64; it++) {
                int lin = tid + it * 256;
                int nn = lin >> 2, q = lin & 3;
                int gn = n0 + nn;
                if (fastB) {
                    const float* src = B + (long long)(gn < N ? gn : 0) * ldb + k0 + 4 * q;
                    cpa16(sB + ((s * BSTGc + nn * B_LDc + 4 * q) << 2), src, gn < N);
                } else {
                    float* dst = &BsF[s * BSTGc + nn * B_LDc + 4 * q];
#pragma unroll
                    for (int j = 0; j < 4; j++) {
                        int gk = k0 + 4 * q + j;
                        dst[j] = (gn < N && gk < Kd) ? B[(long long)gn * ldb + gk] : 0.f;
                    }
                }
            }
        }
    };

    auto compute = [&](int s) {
        const float* As_ = AsF + s * ASTG;
        const float* Bs_ = BsF + s * BSTGc;
#pragma unroll
        for (int ks = 0; ks < 2; ks++) {
            int kk = ks * 8;
            uint32_t ah[2][4], al[2][4];
#pragma unroll
            for (int i = 0; i < 2; i++) {
                const float* r0 = As_ + (wm * 32 + i * 16 + lm) * A_LD;
                const float* r1 = r0 + 8 * A_LD;
                split2(r0[kk + lk],     ah[i][0], al[i][0]);
                split2(r1[kk + lk],     ah[i][1], al[i][1]);
                split2(r0[kk + lk + 4], ah[i][2], al[i][2]);
                split2(r1[kk + lk + 4], ah[i][3], al[i][3]);
            }
#pragma unroll
            for (int j = 0; j < BJ; j++) {
                int bn = wn * (BN / 4) + j * 8 + lm;
                float f0, f1;
                if (!TRB) {
                    f0 = Bs_[(kk + lk) * B_LDc + bn];
                    f1 = Bs_[(kk + lk + 4) * B_LDc + bn];
                } else {
                    f0 = Bs_[bn * B_LDc + kk + lk];
                    f1 = Bs_[bn * B_LDc + kk + lk + 4];
                }
                uint32_t bh[2], bl[2];
                split2(f0, bh[0], bl[0]);
                split2(f1, bh[1], bl[1]);
                // term-major order: same-acc reuse distance 2+ for ILP
                mma_tf32(acc[0][j], ah[0], bh);
                mma_tf32(acc[1][j], ah[1], bh);
                mma_tf32(acc[0][j], ah[0], bl);
                mma_tf32(acc[1][j], ah[1], bl);
                mma_tf32(acc[0][j], al[0], bh);
                mma_tf32(acc[1][j], al[1], bh);
            }
        }
    };

    int nk = (Kd + 15) >> 4;
#pragma unroll
    for (int p = 0; p < STG - 1; p++) {
        if (p < nk) load_stage(p, p * 16);
        cpa_commit();
    }
    for (int i = 0; i < nk; i++) {
        cpa_wait1();
        __syncthreads();
        int nx = i + STG - 1;
        if (nx < nk) load_stage(nx % STG, nx * 16);
        cpa_commit();
        compute(i % STG);
    }

    // ---- epilogue ----
#pragma unroll
    for (int i = 0; i < 2; i++) {
#pragma unroll
        for (int r2 = 0; r2 < 2; r2++) {
            int gm = m0 + wm * 32 + i * 16 + lm + r2 * 8;
            if (gm >= M) continue;
            int rc = iC ? iC[gm] : gm;
            float* crow = C + (long long)rc * ldc;
            const float* rrow = res ? res + (long long)rc * ldc : nullptr;
#pragma unroll
            for (int j = 0; j < BJ; j++) {
#pragma unroll
                for (int c2 = 0; c2 < 2; c2++) {
                    int gn = n0 + wn * (BN / 4) + j * 8 + lk * 2 + c2;
                    if (gn >= N) continue;
                    float v = acc[i][j][r2 * 2 + c2] * alpha;
                    if (bias) v += bias[gn];
                    if (ACT == 1) {
                        float x = v;
                        float t = tanhf(0.7978845608028654f * (x + 0.044715f * x * x * x));
                        v = 0.5f * x * (1.f + t);
                    }
                    if (rrow) v += rrow[gn];
                    crow[gn] = v;
                }
            }
        }
    }
}

// ---------------- small kernels ----------------
__global__ void transpose_z(const float* __restrict__ z, float* __restrict__ zt) {
    __shared__ float tile[32][33];
    int b = blockIdx.z;
    int l0 = blockIdx.x * 32, c0 = blockIdx.y * 32;
    int x = threadIdx.x, y = threadIdx.y;
    for (int i = y; i < 32; i += 8)
        tile[i][x] = z[b * CIN * SS + (c0 + i) * SS + l0 + x];
    __syncthreads();
    for (int i = y; i < 32; i += 8)
        zt[b * SS * CIN + (long long)(l0 + i) * CIN + c0 + x] = tile[x][i];
}

__global__ void ln_kernel(const float* __restrict__ x, float* __restrict__ y,
                          const float* __restrict__ g, const float* __restrict__ b) {
    int row = blockIdx.x;
    const float* xr = x + (long long)row * DD;
    __shared__ float sh[32];
    __shared__ float sh2[32];
    float s = 0.f, s2 = 0.f;
    for (int d = threadIdx.x; d < DD; d += 256) { float v = xr[d]; s += v; s2 += v * v; }
    int lane = threadIdx.x & 31, wid = threadIdx.x >> 5;
    for (int o = 16; o; o >>= 1) { s += __shfl_xor_sync(~0u, s, o); s2 += __shfl_xor_sync(~0u, s2, o); }
    if (lane == 0) { sh[wid] = s; sh2[wid] = s2; }
    __syncthreads();
    if (wid == 0) {
        s  = (lane < 8) ? sh[lane]  : 0.f;
        s2 = (lane < 8) ? sh2[lane] : 0.f;
        for (int o = 16; o; o >>= 1) { s += __shfl_xor_sync(~0u, s, o); s2 += __shfl_xor_sync(~0u, s2, o); }
        if (lane == 0) { sh[0] = s; sh2[0] = s2; }
    }
    __syncthreads();
    float mean = sh[0] / DD;
    float var  = sh2[0] / DD - mean * mean;
    float inv = rsqrtf(var + 1e-5f);
    float* yr = y + (long long)row * DD;
    for (int d = threadIdx.x; d < DD; d += 256)
        yr[d] = (xr[d] - mean) * inv * g[d] + b[d];
}

__global__ void rope_kernel(float* __restrict__ q, float* __restrict__ k) {
    int idx = blockIdx.x * blockDim.x + threadIdx.x;
    if (idx >= TOK * (DD / 2)) return;
    int t = idx / (DD / 2), j = idx - t * (DD / 2);
    int s = t & (SS - 1);
    float freq = __expf(-9.210340371976184f * ((float)j / 384.f));
    float ang = (float)s * freq;
    float c, sn; sincosf(ang, &sn, &c);
    {
        float* p = q + (long long)t * DD + 2 * j;
        float a = p[0], b = p[1];
        p[0] = a * c - b * sn; p[1] = a * sn + b * c;
    }
    {
        float* p = k + (long long)t * DD + 2 * j;
        float a = p[0], b = p[1];
        p[0] = a * c - b * sn; p[1] = a * sn + b * c;
    }
}

__global__ void softmax_causal(float* __restrict__ sc) {
    int z = blockIdx.y, r = blockIdx.x;
    float* row = sc + ((long long)z << 20) + (long long)r * 1024;
    int n = r + 1;
    __shared__ float sh[32];
    int lane = threadIdx.x & 31, wid = threadIdx.x >> 5;
    float mx = -1e30f;
    for (int j = threadIdx.x; j < n; j += 256) mx = fmaxf(mx, row[j]);
    for (int o = 16; o; o >>= 1) mx = fmaxf(mx, __shfl_xor_sync(~0u, mx, o));
    if (lane == 0) sh[wid] = mx;
    __syncthreads();
    if (wid == 0) {
        mx = (lane < 8) ? sh[lane] : -1e30f;
        for (int o = 16; o; o >>= 1) mx = fmaxf(mx, __shfl_xor_sync(~0u, mx, o));
        if (lane == 0) sh[0] = mx;
    }
    __syncthreads();
    mx = sh[0];
    __syncthreads();
    float s = 0.f;
    for (int j = threadIdx.x; j < n; j += 256) s += __expf(row[j] - mx);
    for (int o = 16; o; o >>= 1) s += __shfl_xor_sync(~0u, s, o);
    if (lane == 0) sh[wid] = s;
    __syncthreads();
    if (wid == 0) {
        s = (lane < 8) ? sh[lane] : 0.f;
        for (int o = 16; o; o >>= 1) s += __shfl_xor_sync(~0u, s, o);
        if (lane == 0) sh[0] = s;
    }
    __syncthreads();
    float inv = 1.f / sh[0];
    for (int j = threadIdx.x; j < 1024; j += 256)
        row[j] = (j < n) ? __expf(row[j] - mx) * inv : 0.f;
}

__global__ void zero_cnt(int* c) { if (threadIdx.x < EE) c[threadIdx.x] = 0; }

__global__ void route_kernel(const float* __restrict__ h, const float* __restrict__ gw,
                             int* cnt, int* etok, int* easn, float* wts) {
    int w = (blockIdx.x * blockDim.x + threadIdx.x) >> 5;
    int lane = threadIdx.x & 31;
    if (w >= TOK) return;
    const float* hr = h + (long long)w * DD;
    float lg[EE];
#pragma unroll
    for (int e = 0; e < EE; e++) {
        float s = 0.f;
        for (int d = lane; d < DD; d += 32) s += hr[d] * gw[d * EE + e];
        for (int o = 16; o; o >>= 1) s += __shfl_xor_sync(~0u, s, o);
        lg[e] = s;
    }
    if (lane == 0) {
        int e0 = 0;
        for (int e = 1; e < EE; e++) if (lg[e] > lg[e0]) e0 = e;
        int e1 = -1;
        for (int e = 0; e < EE; e++) { if (e == e0) continue; if (e1 < 0 || lg[e] > lg[e1]) e1 = e; }
        float x1 = __expf(lg[e1] - lg[e0]);
        float den = 1.f + x1;
        float w0 = 1.f / den, w1 = x1 / den;
        int s0 = atomicAdd(&cnt[e0], 1);
        etok[e0 * TOK + s0] = w; easn[e0 * TOK + s0] = 2 * w;
        int s1 = atomicAdd(&cnt[e1], 1);
        etok[e1 * TOK + s1] = w; easn[e1 * TOK + s1] = 2 * w + 1;
        wts[2 * w] = w0; wts[2 * w + 1] = w1;
    }
}

__global__ void combine_kernel(float* __restrict__ x, const float* __restrict__ ys,
                               const float* __restrict__ wts) {
    int idx = blockIdx.x * blockDim.x + threadIdx.x;
    if (idx >= TOK * DD) return;
    int t = idx / DD, d = idx - t * DD;
    x[idx] += wts[2 * t] * ys[(long long)(2 * t) * DD + d]
            + wts[2 * t + 1] * ys[(long long)(2 * t + 1) * DD + d];
}

__global__ void basis_kernel(float* __restrict__ Cb) {
    int idx = blockIdx.x * blockDim.x + threadIdx.x;
    if (idx >= 1026 * 1024) return;
    int j = idx >> 10, n = idx & 1023;
    const float invN = 1.f / 1024.f;
    float v;
    if (j == 0) v = invN;
    else if (j <= 511) { int m = (j * n) & 1023; v = 2.f * invN * cosf(m * TWO_PI_N); }
    else if (j == 512) v = invN * ((n & 1) ? -1.f : 1.f);
    else if (j == 513 || j == 1025) v = 0.f;
    else { int kk = j - 513; int m = (kk * n) & 1023; v = -2.f * invN * sinf(m * TWO_PI_N); }
    Cb[idx] = v;
}

__global__ void bf_kernel(const float* __restrict__ ob, const float* __restrict__ Cb,
                          float* __restrict__ bf) {
    int n = threadIdx.x;
    float s = 0.f;
    for (int j = 0; j < 1026; j++) s += ob[j] * Cb[j * 1024 + n];
    bf[n] = s;
}

__global__ void istft_kernel(const float* __restrict__ frames, float* __restrict__ out) {
    int idx = blockIdx.x * blockDim.x + threadIdx.x;
    if (idx >= BB * OUTL) return;
    int b = idx / OUTL, i = idx - b * OUTL;
    int ip = i + PADL;
    int tmin = (ip >= 1024) ? ((ip - 768) >> 8) : 0;
    int tmax = min(1023, ip >> 8);
    float acc = 0.f, env = 0.f;
    for (int t = tmin; t <= tmax; t++) {
        int n = ip - (t << 8);
        float w = 0.5f * (1.f - cosf(n * TWO_PI_N));
        acc += frames[((long long)(b * 1024 + t) << 10) + n] * w;
        env += w * w;
    }
    out[idx] = acc / env;
}

// ---------------- host side ----------------
static void* symaddr(const void* sym) {
    void* p = nullptr;
    cudaGetSymbolAddress(&p, sym);
    return p;
}

struct GemmArgs {
    const float* A; int lda; long long sAz, sAz2;
    const float* B; int ldb; long long sBz, sBz2;
    float* C; int ldc; long long sCz, sCz2;
    int zdiv;
    const float* bias; long long sbz; const float* res;
    int M, N, Kd; float alpha; int Z;
    const int* idxA; const int* idxC; const int* cnt;
    int causal; int gridM;
};

#define SMEM_BYTES(TRB, BN) (4 * STG * (ASTG + ((TRB) ? ((BN) * A_LD) : (16 * ((BN) + 8)))))

static void gemm(int act, bool trb, int BN, const GemmArgs& a)
{
    dim3 grid((a.N + BN - 1) / BN, a.gridM ? a.gridM : (a.M + 63) / 64, a.Z);
    if (act == 1) {
        size_t shm = SMEM_BYTES(false, 128);
        cudaFuncSetAttribute(gemm_kernel<1, false, 128>, cudaFuncAttributeMaxDynamicSharedMemorySize, (int)shm);
        gemm_kernel<1, false, 128><<<grid, 256, shm>>>(a.A, a.lda, a.sAz, a.sAz2, a.B, a.ldb, a.sBz, a.sBz2,
            a.C, a.ldc, a.sCz, a.sCz2, a.zdiv, a.bias, a.sbz, a.res,
            a.M, a.N, a.Kd, a.alpha, a.idxA, a.idxC, a.cnt, a.causal);
    } else if (trb) {
        size_t shm = SMEM_BYTES(true, 128);
        cudaFuncSetAttribute(gemm_kernel<0, true, 128>, cudaFuncAttributeMaxDynamicSharedMemorySize, (int)shm);
        gemm_kernel<0, true, 128><<<grid, 256, shm>>>(a.A, a.lda, a.sAz, a.sAz2, a.B, a.ldb, a.sBz, a.sBz2,
            a.C, a.ldc, a.sCz, a.sCz2, a.zdiv, a.bias, a.sbz, a.res,
            a.M, a.N, a.Kd, a.alpha, a.idxA, a.idxC, a.cnt, a.causal);
    } else if (BN == 128) {
        size_t shm = SMEM_BYTES(false, 128);
        cudaFuncSetAttribute(gemm_kernel<0, false, 128>, cudaFuncAttributeMaxDynamicSharedMemorySize, (int)shm);
        gemm_kernel<0, false, 128><<<grid, 256, shm>>>(a.A, a.lda, a.sAz, a.sAz2, a.B, a.ldb, a.sBz, a.sBz2,
            a.C, a.ldc, a.sCz, a.sCz2, a.zdiv, a.bias, a.sbz, a.res,
            a.M, a.N, a.Kd, a.alpha, a.idxA, a.idxC, a.cnt, a.causal);
    } else {
        size_t shm = SMEM_BYTES(false, 64);
        cudaFuncSetAttribute(gemm_kernel<0, false, 64>, cudaFuncAttributeMaxDynamicSharedMemorySize, (int)shm);
        gemm_kernel<0, false, 64><<<grid, 256, shm>>>(a.A, a.lda, a.sAz, a.sAz2, a.B, a.ldb, a.sBz, a.sBz2,
            a.C, a.ldc, a.sCz, a.sCz2, a.zdiv, a.bias, a.sbz, a.res,
            a.M, a.N, a.Kd, a.alpha, a.idxA, a.idxC, a.cnt, a.causal);
    }
}

extern "C" void kernel_launch(void* const* d_in, const int* in_sizes, int n_in,
                              void* d_out, int out_size)
{
    const float* z_in  = (const float*)d_in[0];
    const float* in_w  = (const float*)d_in[1];
    const float* in_b  = (const float*)d_in[2];
    const float* ln1g  = (const float*)d_in[3];
    const float* ln1b  = (const float*)d_in[4];
    const float* wq    = (const float*)d_in[5];
    const float* bq    = (const float*)d_in[6];
    const float* wk    = (const float*)d_in[7];
    const float* bk    = (const float*)d_in[8];
    const float* wv    = (const float*)d_in[9];
    const float* bv    = (const float*)d_in[10];
    const float* wo    = (const float*)d_in[11];
    const float* bo    = (const float*)d_in[12];
    const float* ln2g  = (const float*)d_in[13];
    const float* ln2b  = (const float*)d_in[14];
    const float* gatew = (const float*)d_in[15];
    const float* ew1   = (const float*)d_in[16];
    const float* eb1   = (const float*)d_in[17];
    const float* ew2   = (const float*)d_in[18];
    const float* eb2   = (const float*)d_in[19];
    const float* outw  = (const float*)d_in[20];
    const float* outb  = (const float*)d_in[21];
    float* out = (float*)d_out;

    float* ZT = (float*)symaddr(g_zt);
    float* X  = (float*)symaddr(g_x);
    float* H  = (float*)symaddr(g_h);
    float* QKV = (float*)symaddr(g_qkv);
    float* WQKV = (float*)symaddr(g_wqkv);
    float* BQKV = (float*)symaddr(g_bqkv);
    float* Q  = QKV;
    float* Kb = QKV + (long long)TOK * DD;
    float* V  = QKV + 2LL * TOK * DD;
    float* AO = (float*)symaddr(g_ao);
    float* SC = (float*)symaddr(g_scores);
    float* HID = (float*)symaddr(g_hidden);
    float* YS = (float*)symaddr(g_yslot);
    float* CB = (float*)symaddr(g_Cb);
    float* MT = (float*)symaddr(g_Mt);
    float* BF = (float*)symaddr(g_bf);
    float* FR = (float*)symaddr(g_frames);
    int* CNT = (int*)symaddr(g_cnt);
    int* ETK = (int*)symaddr(g_etok);
    int* EAS = (int*)symaddr(g_easn);
    float* WTS = (float*)symaddr(g_wts);

    // in_projection: zt = z^T, x = zt @ in_w + in_b
    transpose_z<<<dim3(SS / 32, CIN / 32, BB), dim3(32, 8)>>>(z_in, ZT);
    {
        GemmArgs a = {ZT, CIN, 0, 0, in_w, DD, 0, 0, X, DD, 0, 0, 1,
                      in_b, 0, nullptr, TOK, DD, CIN, 1.f, 1, nullptr, nullptr, nullptr, 0, 0};
        gemm(0, false, 128, a);
    }

    for (int L = 0; L < 2; L++) {
        const size_t WSZ = (size_t)DD * DD * sizeof(float);
        // fuse QKV weights/biases into contiguous buffers (D2D async copies)
        cudaMemcpyAsync(WQKV,              wq + (long long)L * DD * DD, WSZ, cudaMemcpyDeviceToDevice);
        cudaMemcpyAsync(WQKV + DD * DD,    wk + (long long)L * DD * DD, WSZ, cudaMemcpyDeviceToDevice);
        cudaMemcpyAsync(WQKV + 2 * DD * DD, wv + (long long)L * DD * DD, WSZ, cudaMemcpyDeviceToDevice);
        cudaMemcpyAsync(BQKV,          bq + L * DD, DD * sizeof(float), cudaMemcpyDeviceToDevice);
        cudaMemcpyAsync(BQKV + DD,     bk + L * DD, DD * sizeof(float), cudaMemcpyDeviceToDevice);
        cudaMemcpyAsync(BQKV + 2 * DD, bv + L * DD, DD * sizeof(float), cudaMemcpyDeviceToDevice);

        ln_kernel<<<TOK, 256>>>(X, H, ln1g + L * DD, ln1b + L * DD);
        {
            // fused QKV: Z=3, z selects weight block and output buffer
            GemmArgs a = {H, DD, 0, 0, WQKV, DD, (long long)DD * DD, 0,
                          QKV, DD, (long long)TOK * DD, 0, 3,
                          BQKV, DD, nullptr, TOK, DD, DD, 1.f, 3, 0, 0, 0, 0, 0};
            gemm(0, false, 128, a);
        }
        if (L == 0)
            rope_kernel<<<(TOK * (DD / 2) + 255) / 256, 256>>>(Q, Kb);

        // scores: z = b*HH + h -> A off = h*HD + b*SS*DD (zdiv=HH)
        {
            GemmArgs a = {Q, DD, HD, (long long)SS * DD,
                          Kb, DD, HD, (long long)SS * DD,
                          SC, SS, (long long)SS * SS, (long long)HH * SS * SS, HH,
                          nullptr, 0, nullptr, SS, SS, HD, 0.125f, BB * HH, 0, 0, 0, 1, 0};
            gemm(0, true, 128, a);
        }
        softmax_causal<<<dim3(SS, BB * HH), 256>>>(SC);
        {
            GemmArgs a = {SC, SS, (long long)SS * SS, (long long)HH * SS * SS,
                          V, DD, HD, (long long)SS * DD,
                          AO, DD, HD, (long long)SS * DD, HH,
                          nullptr, 0, nullptr, SS, HD, SS, 1.f, BB * HH, 0, 0, 0, 0, 0};
            gemm(0, false, 64, a);
        }
        // out proj + residual
        {
            GemmArgs a = {AO, DD, 0, 0, wo + (long long)L * DD * DD, DD, 0, 0, X, DD, 0, 0, 1,
                          bo + L * DD, 0, X, TOK, DD, DD, 1.f, 1, 0, 0, 0, 0, 0};
            gemm(0, false, 128, a);
        }

        // MoE
        ln_kernel<<<TOK, 256>>>(X, H, ln2g + L * DD, ln2b + L * DD);
        zero_cnt<<<1, 32>>>(CNT);
        route_kernel<<<TOK / 8, 256>>>(H, gatew + (long long)L * DD * EE, CNT, ETK, EAS, WTS);
        {
            GemmArgs a = {H, DD, 0, 0,
                          ew1 + (long long)L * EE * DD * FF, FF, (long long)DD * FF, 0,
                          HID, FF, 0, 0, EE,
                          eb1 + (long long)L * EE * FF, FF, nullptr,
                          TOK, FF, DD, 1.f, EE, ETK, EAS, CNT, 0, TOK / 64};
            gemm(1, false, 128, a);
        }
        {
            GemmArgs a = {HID, FF, 0, 0,
                          ew2 + (long long)L * EE * FF * DD, DD, (long long)FF * DD, 0,
                          YS, DD, 0, 0, EE,
                          eb2 + (long long)L * EE * DD, DD, nullptr,
                          TOK, DD, FF, 1.f, EE, EAS, EAS, CNT, 0, TOK / 64};
            gemm(0, false, 128, a);
        }
        combine_kernel<<<(TOK * DD + 255) / 256, 256>>>(X, YS, WTS);
    }

    // out projection fused with irfft basis: frames = x @ (out_w @ Cb) + out_b @ Cb
    basis_kernel<<<(1026 * 1024 + 255) / 256, 256>>>(CB);
    {
        GemmArgs a = {outw, 2 * FB, 0, 0, CB, 1024, 0, 0, MT, 1024, 0, 0, 1,
                      nullptr, 0, nullptr, DD, 1024, 2 * FB, 1.f, 1, 0, 0, 0, 0, 0};
        gemm(0, false, 128, a);
    }
    bf_kernel<<<1, 1024>>>(outb, CB, BF);
    {
        GemmArgs a = {X, DD, 0, 0, MT, 1024, 0, 0, FR, 1024, 0, 0, 1,
                      BF, 0, nullptr, TOK, 1024, DD, 1.f, 1, 0, 0, 0, 0, 0};
        gemm(0, false, 128, a);
    }

    // windowed overlap-add + env normalize + trim
    istft_kernel<<<(BB * OUTL + 255) / 256, 256>>>(FR, out);
}

// round 8
// speedup vs baseline: 2.4418x; 1.0761x over previous
#include <cuda_runtime.h>
#include <math.h>
#include <stdint.h>

// ---------------- constants ----------------
#define BB 2
#define SS 1024
#define DD 768
#define HH 12
#define HD 64
#define EE 8
#define FF 2048
#define CIN 512
#define TOK (BB*SS)          // 2048
#define FB 513
#define PADL 384
#define OUTL 262144
#define TWO_PI_N 0.006135923151542565f   // 2*pi/1024

// ---------------- scratch (device globals; allocation-free) ----------------
__device__ float g_zt[TOK*CIN];
__device__ float g_x [TOK*DD];
__device__ float g_h [TOK*DD];
__device__ float g_qkv[3*TOK*DD];
__device__ float g_wqkv[3*DD*DD];
__device__ float g_bqkv[3*DD];
__device__ float g_ao[TOK*DD];
__device__ float g_scores[24u*1024u*1024u];
__device__ float g_hidden[4096*FF];
__device__ float g_yslot [4096*DD];
__device__ float g_Cb[1026*1024];
__device__ float g_Mt[DD*1024];
__device__ float g_bf[1024];
__device__ float g_frames[TOK*1024];
__device__ int   g_cnt[EE];
__device__ int   g_etok[EE*TOK];
__device__ int   g_easn[EE*TOK];
__device__ float g_wts[2*TOK];

// ---------------- bf16x3 / async helpers ----------------
// hi = bf16-truncate(f) (exact residual in fp32); lo = bf16-round(f - hi).
// Packs two consecutive-k values into bf16x2 regs (low half = even k).
__device__ __forceinline__ void pack_bf16pair(float f0, float f1, uint32_t& hi, uint32_t& lo) {
    uint32_t u0 = __float_as_uint(f0);
    uint32_t u1 = __float_as_uint(f1);
    uint32_t h;
    asm("prmt.b32 %0, %1, %2, 0x7632;" : "=r"(h) : "r"(u0), "r"(u1));
    hi = h;
    float l0 = f0 - __uint_as_float(u0 & 0xFFFF0000u);
    float l1 = f1 - __uint_as_float(u1 & 0xFFFF0000u);
    asm("cvt.rn.bf16x2.f32 %0, %1, %2;" : "=r"(lo) : "f"(l1), "f"(l0));
}
__device__ __forceinline__ void mma_bf16(float* c, const uint32_t* a, const uint32_t* b) {
    asm volatile(
        "mma.sync.aligned.m16n8k16.row.col.f32.bf16.bf16.f32 "
        "{%0,%1,%2,%3}, {%4,%5,%6,%7}, {%8,%9}, {%0,%1,%2,%3};"
        : "+f"(c[0]), "+f"(c[1]), "+f"(c[2]), "+f"(c[3])
        : "r"(a[0]), "r"(a[1]), "r"(a[2]), "r"(a[3]), "r"(b[0]), "r"(b[1]));
}
__device__ __forceinline__ void cpa16(uint32_t dst, const float* src, bool pred) {
    asm volatile("cp.async.ca.shared.global [%0], [%1], 16, %2;"
                 :: "r"(dst), "l"(src), "r"(pred ? 16 : 0));
}
__device__ __forceinline__ void cpa_commit() { asm volatile("cp.async.commit_group;"); }
__device__ __forceinline__ void cpa_wait1() { asm volatile("cp.async.wait_group 1;"); }

// ---------------- pipelined tensor-core GEMM (3xBF16, cp.async 3-stage) ----------------
// Tile: 64(M) x BN(N), K-step 16. 8 warps as 2(M) x 4(N); warp = 32 x BN/4.
#define STG 3
#define A_LD 20
#define ASTG 1280   // 64 * A_LD floats
#define APK_LD 12   // packed A row stride (uint32; 8 pairs + pad)

template<int ACT, bool TRB, int BN>
__global__ __launch_bounds__(256, 2)
void gemm_kernel(const float* __restrict__ A, int lda, long long sAz, long long sAz2,
                 const float* __restrict__ B, int ldb, long long sBz, long long sBz2,
                 float* __restrict__ C, int ldc, long long sCz, long long sCz2,
                 int zdiv,
                 const float* __restrict__ bias, long long sbz,
                 const float* __restrict__ res,
                 int M, int N, int Kd, float alpha,
                 const int* __restrict__ idxA, const int* __restrict__ idxC,
                 const int* __restrict__ cnt, int causal)
{
    constexpr int B_LDc = TRB ? A_LD : (BN + 8);
    constexpr int BSTGc = TRB ? (BN * A_LD) : (16 * (BN + 8));
    constexpr int BPK_LD = TRB ? APK_LD : (BN + 8);     // packed B stride (uint32)
    constexpr int BPK_SZ = TRB ? (BN * APK_LD) : (8 * (BN + 8));
    constexpr int BJ = BN / 32;

    int z = blockIdx.z;
    int z1 = z / zdiv, z0 = z - z1 * zdiv;
    if (cnt) M = cnt[z];
    int m0 = blockIdx.y * 64, n0 = blockIdx.x * BN;
    if (m0 >= M) return;
    if (causal == 1 && n0 > m0 + 63) return;
    if (causal == 2) Kd = min(Kd, m0 + 64);   // AV: keys beyond row block are zero
    A += (long long)z0 * sAz + (long long)z1 * sAz2;
    B += (long long)z0 * sBz + (long long)z1 * sBz2;
    C += (long long)z0 * sCz + (long long)z1 * sCz2;
    if (bias) bias += (long long)z * sbz;
    if (res)  res  += (long long)z0 * sCz + (long long)z1 * sCz2;
    const int* iA = idxA ? idxA + z * TOK : nullptr;
    const int* iC = idxC ? idxC + z * TOK : nullptr;

    extern __shared__ float smem[];
    float* AsF = smem;
    float* BsF = smem + STG * ASTG;
    uint32_t* Aph = (uint32_t*)(smem + STG * (ASTG + BSTGc));
    uint32_t* Apl = Aph + 64 * APK_LD;
    uint32_t* Bph = Apl + 64 * APK_LD;
    uint32_t* Bpl = Bph + BPK_SZ;
    uint32_t sA = (uint32_t)__cvta_generic_to_shared(AsF);
    uint32_t sB = (uint32_t)__cvta_generic_to_shared(BsF);

    int tid = threadIdx.x;
    int lane = tid & 31, wid = tid >> 5;
    int wm = wid >> 2, wn = wid & 3;
    int lm = lane >> 2, lk = lane & 3;

    float acc[2][BJ][4];
#pragma unroll
    for (int i = 0; i < 2; i++)
#pragma unroll
        for (int j = 0; j < BJ; j++)
#pragma unroll
            for (int r = 0; r < 4; r++) acc[i][j][r] = 0.f;

    const bool fastA = ((lda & 3) == 0) && ((Kd & 15) == 0);
    const bool fastB = ((ldb & 3) == 0) && (TRB ? ((Kd & 15) == 0) : true);

    auto load_stage = [&](int s, int k0) {
        // ---- A: 64 rows x 16 k, smem [m][A_LD] ----
        {
            int mm = tid >> 2, q = tid & 3;
            int gm = m0 + mm;
            int ra = (gm < M) ? (iA ? iA[gm] : gm) : -1;
            if (fastA) {
                const float* src = A + (long long)(ra >= 0 ? ra : 0) * lda + k0 + 4 * q;
                cpa16(sA + ((s * ASTG + mm * A_LD + 4 * q) << 2), src, ra >= 0);
            } else {
                float* dst = &AsF[s * ASTG + mm * A_LD + 4 * q];
#pragma unroll
                for (int j = 0; j < 4; j++) {
                    int gk = k0 + 4 * q + j;
                    dst[j] = (ra >= 0 && gk < Kd) ? A[(long long)ra * lda + gk] : 0.f;
                }
            }
        }
        // ---- B ----
        if (!TRB) {
#pragma unroll
            for (int it = 0; it < BN / 64; it++) {
                int lin = tid + it * 256;
                int k = lin / (BN / 4), q = lin % (BN / 4);
                int gk = k0 + k;
                if (fastB) {
                    const float* src = B + (long long)(gk < Kd ? gk : 0) * ldb + n0 + 4 * q;
                    cpa16(sB + ((s * BSTGc + k * B_LDc + 4 * q) << 2), src, gk < Kd);
                } else {
                    float* dst = &BsF[s * BSTGc + k * B_LDc + 4 * q];
#pragma unroll
                    for (int j = 0; j < 4; j++)
                        dst[j] = (gk < Kd) ? B[(long long)gk * ldb + n0 + 4 * q + j] : 0.f;
                }
            }
        } else {
#pragma unroll
            for (int it = 0; it < BN / 64; it++) {
                int lin = tid + it * 256;
                int nn = lin >> 2, q = lin & 3;
                int gn = n0 + nn;
                if (fastB) {
                    const float* src = B + (long long)(gn < N ? gn : 0) * ldb + k0 + 4 * q;
                    cpa16(sB + ((s * BSTGc + nn * B_LDc + 4 * q) << 2), src, gn < N);
                } else {
                    float* dst = &BsF[s * BSTGc + nn * B_LDc + 4 * q];
#pragma unroll
                    for (int j = 0; j < 4; j++) {
                        int gk = k0 + 4 * q + j;
                        dst[j] = (gn < N && gk < Kd) ? B[(long long)gn * ldb + gk] : 0.f;
                    }
                }
            }
        }
    };

    // fp32 staged tile -> packed bf16x2 hi/lo smem (done once per CTA per k16)
    auto convert_stage = [&](int s) {
        const float* As_ = AsF + s * ASTG;
        const float* Bs_ = BsF + s * BSTGc;
#pragma unroll
        for (int it = 0; it < 2; it++) {          // A: 512 pairs
            int P = tid + it * 256;
            int m = P >> 3, p = P & 7;
            float f0 = As_[m * A_LD + 2 * p];
            float f1 = As_[m * A_LD + 2 * p + 1];
            uint32_t hi, lo; pack_bf16pair(f0, f1, hi, lo);
            Aph[m * APK_LD + p] = hi;
            Apl[m * APK_LD + p] = lo;
        }
        if (!TRB) {
#pragma unroll
            for (int it = 0; it < BN / 32; it++) { // 8*BN pairs
                int P = tid + it * 256;
                int p = P / BN, n = P % BN;
                float f0 = Bs_[(2 * p) * B_LDc + n];
                float f1 = Bs_[(2 * p + 1) * B_LDc + n];
                uint32_t hi, lo; pack_bf16pair(f0, f1, hi, lo);
                Bph[p * BPK_LD + n] = hi;
                Bpl[p * BPK_LD + n] = lo;
            }
        } else {
#pragma unroll
            for (int it = 0; it < BN / 32; it++) { // BN*8 pairs
                int P = tid + it * 256;
                int n = P >> 3, p = P & 7;
                float f0 = Bs_[n * B_LDc + 2 * p];
                float f1 = Bs_[n * B_LDc + 2 * p + 1];
                uint32_t hi, lo; pack_bf16pair(f0, f1, hi, lo);
                Bph[n * BPK_LD + p] = hi;
                Bpl[n * BPK_LD + p] = lo;
            }
        }
    };

    auto compute = [&]() {
        uint32_t ah[2][4], al[2][4];
#pragma unroll
        for (int i = 0; i < 2; i++) {
            int r0 = wm * 32 + i * 16 + lm;
            ah[i][0] = Aph[r0 * APK_LD + lk];
            ah[i][1] = Aph[(r0 + 8) * APK_LD + lk];
            ah[i][2] = Aph[r0 * APK_LD + lk + 4];
            ah[i][3] = Aph[(r0 + 8) * APK_LD + lk + 4];
            al[i][0] = Apl[r0 * APK_LD + lk];
            al[i][1] = Apl[(r0 + 8) * APK_LD + lk];
            al[i][2] = Apl[r0 * APK_LD + lk + 4];
            al[i][3] = Apl[(r0 + 8) * APK_LD + lk + 4];
        }
#pragma unroll
        for (int j = 0; j < BJ; j++) {
            int bn = wn * (BN / 4) + j * 8 + lm;
            uint32_t bh[2], bl[2];
            if (!TRB) {
                bh[0] = Bph[lk * BPK_LD + bn];
                bh[1] = Bph[(lk + 4) * BPK_LD + bn];
                bl[0] = Bpl[lk * BPK_LD + bn];
                bl[1] = Bpl[(lk + 4) * BPK_LD + bn];
            } else {
                bh[0] = Bph[bn * BPK_LD + lk];
                bh[1] = Bph[bn * BPK_LD + lk + 4];
                bl[0] = Bpl[bn * BPK_LD + lk];
                bl[1] = Bpl[bn * BPK_LD + lk + 4];
            }
            // hh + lh + hl (ll dropped, ~2^-16)
            mma_bf16(acc[0][j], ah[0], bh);
            mma_bf16(acc[1][j], ah[1], bh);
            mma_bf16(acc[0][j], al[0], bh);
            mma_bf16(acc[1][j], al[1], bh);
            mma_bf16(acc[0][j], ah[0], bl);
            mma_bf16(acc[1][j], ah[1], bl);
        }
    };

    int nk = (Kd + 15) >> 4;
#pragma unroll
    for (int p = 0; p < STG - 1; p++) {
        if (p < nk) load_stage(p, p * 16);
        cpa_commit();
    }
    for (int i = 0; i < nk; i++) {
        cpa_wait1();
        __syncthreads();          // stage i fp32 ready; also guards packed reuse
        int nx = i + STG - 1;
        if (nx < nk) load_stage(nx % STG, nx * 16);
        cpa_commit();
        convert_stage(i % STG);
        __syncthreads();          // packed ready
        compute();
    }

    // ---- epilogue ----
#pragma unroll
    for (int i = 0; i < 2; i++) {
#pragma unroll
        for (int r2 = 0; r2 < 2; r2++) {
            int gm = m0 + wm * 32 + i * 16 + lm + r2 * 8;
            if (gm >= M) continue;
            int rc = iC ? iC[gm] : gm;
            float* crow = C + (long long)rc * ldc;
            const float* rrow = res ? res + (long long)rc * ldc : nullptr;
#pragma unroll
            for (int j = 0; j < BJ; j++) {
#pragma unroll
                for (int c2 = 0; c2 < 2; c2++) {
                    int gn = n0 + wn * (BN / 4) + j * 8 + lk * 2 + c2;
                    if (gn >= N) continue;
                    float v = acc[i][j][r2 * 2 + c2] * alpha;
                    if (bias) v += bias[gn];
                    if (ACT == 1) {
                        float x = v;
                        float t = tanhf(0.7978845608028654f * (x + 0.044715f * x * x * x));
                        v = 0.5f * x * (1.f + t);
                    }
                    if (rrow) v += rrow[gn];
                    crow[gn] = v;
                }
            }
        }
    }
}

// ---------------- small kernels ----------------
__global__ void transpose_z(const float* __restrict__ z, float* __restrict__ zt) {
    __shared__ float tile[32][33];
    int b = blockIdx.z;
    int l0 = blockIdx.x * 32, c0 = blockIdx.y * 32;
    int x = threadIdx.x, y = threadIdx.y;
    for (int i = y; i < 32; i += 8)
        tile[i][x] = z[b * CIN * SS + (c0 + i) * SS + l0 + x];
    __syncthreads();
    for (int i = y; i < 32; i += 8)
        zt[b * SS * CIN + (long long)(l0 + i) * CIN + c0 + x] = tile[x][i];
}

__global__ void ln_kernel(const float* __restrict__ x, float* __restrict__ y,
                          const float* __restrict__ g, const float* __restrict__ b) {
    int row = blockIdx.x;
    const float* xr = x + (long long)row * DD;
    __shared__ float sh[32];
    __shared__ float sh2[32];
    float s = 0.f, s2 = 0.f;
    for (int d = threadIdx.x; d < DD; d += 256) { float v = xr[d]; s += v; s2 += v * v; }
    int lane = threadIdx.x & 31, wid = threadIdx.x >> 5;
    for (int o = 16; o; o >>= 1) { s += __shfl_xor_sync(~0u, s, o); s2 += __shfl_xor_sync(~0u, s2, o); }
    if (lane == 0) { sh[wid] = s; sh2[wid] = s2; }
    __syncthreads();
    if (wid == 0) {
        s  = (lane < 8) ? sh[lane]  : 0.f;
        s2 = (lane < 8) ? sh2[lane] : 0.f;
        for (int o = 16; o; o >>= 1) { s += __shfl_xor_sync(~0u, s, o); s2 += __shfl_xor_sync(~0u, s2, o); }
        if (lane == 0) { sh[0] = s; sh2[0] = s2; }
    }
    __syncthreads();
    float mean = sh[0] / DD;
    float var  = sh2[0] / DD - mean * mean;
    float inv = rsqrtf(var + 1e-5f);
    float* yr = y + (long long)row * DD;
    for (int d = threadIdx.x; d < DD; d += 256)
        yr[d] = (xr[d] - mean) * inv * g[d] + b[d];
}

__global__ void rope_kernel(float* __restrict__ q, float* __restrict__ k) {
    int idx = blockIdx.x * blockDim.x + threadIdx.x;
    if (idx >= TOK * (DD / 2)) return;
    int t = idx / (DD / 2), j = idx - t * (DD / 2);
    int s = t & (SS - 1);
    float freq = __expf(-9.210340371976184f * ((float)j / 384.f));
    float ang = (float)s * freq;
    float c, sn; sincosf(ang, &sn, &c);
    {
        float* p = q + (long long)t * DD + 2 * j;
        float a = p[0], b = p[1];
        p[0] = a * c - b * sn; p[1] = a * sn + b * c;
    }
    {
        float* p = k + (long long)t * DD + 2 * j;
        float a = p[0], b = p[1];
        p[0] = a * c - b * sn; p[1] = a * sn + b * c;
    }
}

__global__ void softmax_causal(float* __restrict__ sc) {
    int z = blockIdx.y, r = blockIdx.x;
    float* row = sc + ((long long)z << 20) + (long long)r * 1024;
    int n = r + 1;
    __shared__ float sh[32];
    int lane = threadIdx.x & 31, wid = threadIdx.x >> 5;
    float mx = -1e30f;
    for (int j = threadIdx.x; j < n; j += 256) mx = fmaxf(mx, row[j]);
    for (int o = 16; o; o >>= 1) mx = fmaxf(mx, __shfl_xor_sync(~0u, mx, o));
    if (lane == 0) sh[wid] = mx;
    __syncthreads();
    if (wid == 0) {
        mx = (lane < 8) ? sh[lane] : -1e30f;
        for (int o = 16; o; o >>= 1) mx = fmaxf(mx, __shfl_xor_sync(~0u, mx, o));
        if (lane == 0) sh[0] = mx;
    }
    __syncthreads();
    mx = sh[0];
    __syncthreads();
    float s = 0.f;
    for (int j = threadIdx.x; j < n; j += 256) s += __expf(row[j] - mx);
    for (int o = 16; o; o >>= 1) s += __shfl_xor_sync(~0u, s, o);
    if (lane == 0) sh[wid] = s;
    __syncthreads();
    if (wid == 0) {
        s = (lane < 8) ? sh[lane] : 0.f;
        for (int o = 16; o; o >>= 1) s += __shfl_xor_sync(~0u, s, o);
        if (lane == 0) sh[0] = s;
    }
    __syncthreads();
    float inv = 1.f / sh[0];
    for (int j = threadIdx.x; j < 1024; j += 256)
        row[j] = (j < n) ? __expf(row[j] - mx) * inv : 0.f;
}

__global__ void zero_cnt(int* c) { if (threadIdx.x < EE) c[threadIdx.x] = 0; }

__global__ void route_kernel(const float* __restrict__ h, const float* __restrict__ gw,
                             int* cnt, int* etok, int* easn, float* wts) {
    int w = (blockIdx.x * blockDim.x + threadIdx.x) >> 5;
    int lane = threadIdx.x & 31;
    if (w >= TOK) return;
    const float* hr = h + (long long)w * DD;
    float lg[EE];
#pragma unroll
    for (int e = 0; e < EE; e++) {
        float s = 0.f;
        for (int d = lane; d < DD; d += 32) s += hr[d] * gw[d * EE + e];
        for (int o = 16; o; o >>= 1) s += __shfl_xor_sync(~0u, s, o);
        lg[e] = s;
    }
    if (lane == 0) {
        int e0 = 0;
        for (int e = 1; e < EE; e++) if (lg[e] > lg[e0]) e0 = e;
        int e1 = -1;
        for (int e = 0; e < EE; e++) { if (e == e0) continue; if (e1 < 0 || lg[e] > lg[e1]) e1 = e; }
        float x1 = __expf(lg[e1] - lg[e0]);
        float den = 1.f + x1;
        float w0 = 1.f / den, w1 = x1 / den;
        int s0 = atomicAdd(&cnt[e0], 1);
        etok[e0 * TOK + s0] = w; easn[e0 * TOK + s0] = 2 * w;
        int s1 = atomicAdd(&cnt[e1], 1);
        etok[e1 * TOK + s1] = w; easn[e1 * TOK + s1] = 2 * w + 1;
        wts[2 * w] = w0; wts[2 * w + 1] = w1;
    }
}

__global__ void combine_kernel(float* __restrict__ x, const float* __restrict__ ys,
                               const float* __restrict__ wts) {
    int idx = blockIdx.x * blockDim.x + threadIdx.x;
    if (idx >= TOK * DD) return;
    int t = idx / DD, d = idx - t * DD;
    x[idx] += wts[2 * t] * ys[(long long)(2 * t) * DD + d]
            + wts[2 * t + 1] * ys[(long long)(2 * t + 1) * DD + d];
}

__global__ void basis_kernel(float* __restrict__ Cb) {
    int idx = blockIdx.x * blockDim.x + threadIdx.x;
    if (idx >= 1026 * 1024) return;
    int j = idx >> 10, n = idx & 1023;
    const float invN = 1.f / 1024.f;
    float v;
    if (j == 0) v = invN;
    else if (j <= 511) { int m = (j * n) & 1023; v = 2.f * invN * cosf(m * TWO_PI_N); }
    else if (j == 512) v = invN * ((n & 1) ? -1.f : 1.f);
    else if (j == 513 || j == 1025) v = 0.f;
    else { int kk = j - 513; int m = (kk * n) & 1023; v = -2.f * invN * sinf(m * TWO_PI_N); }
    Cb[idx] = v;
}

__global__ void bf_kernel(const float* __restrict__ ob, const float* __restrict__ Cb,
                          float* __restrict__ bf) {
    int n = threadIdx.x;
    float s = 0.f;
    for (int j = 0; j < 1026; j++) s += ob[j] * Cb[j * 1024 + n];
    bf[n] = s;
}

__global__ void istft_kernel(const float* __restrict__ frames, float* __restrict__ out) {
    int idx = blockIdx.x * blockDim.x + threadIdx.x;
    if (idx >= BB * OUTL) return;
    int b = idx / OUTL, i = idx - b * OUTL;
    int ip = i + PADL;
    int tmin = (ip >= 1024) ? ((ip - 768) >> 8) : 0;
    int tmax = min(1023, ip >> 8);
    float acc = 0.f, env = 0.f;
    for (int t = tmin; t <= tmax; t++) {
        int n = ip - (t << 8);
        float w = 0.5f * (1.f - cosf(n * TWO_PI_N));
        acc += frames[((long long)(b * 1024 + t) << 10) + n] * w;
        env += w * w;
    }
    out[idx] = acc / env;
}

// ---------------- host side ----------------
static void* symaddr(const void* sym) {
    void* p = nullptr;
    cudaGetSymbolAddress(&p, sym);
    return p;
}

struct GemmArgs {
    const float* A; int lda; long long sAz, sAz2;
    const float* B; int ldb; long long sBz, sBz2;
    float* C; int ldc; long long sCz, sCz2;
    int zdiv;
    const float* bias; long long sbz; const float* res;
    int M, N, Kd; float alpha; int Z;
    const int* idxA; const int* idxC; const int* cnt;
    int causal; int gridM;
};

#define BPK_U32(TRB, BN) ((TRB) ? (2 * (BN) * APK_LD) : (2 * 8 * ((BN) + 8)))
#define SMEM_BYTES(TRB, BN) (4 * (STG * (ASTG + ((TRB) ? ((BN) * A_LD) : (16 * ((BN) + 8)))) \
                                  + 2 * 64 * APK_LD + BPK_U32(TRB, BN)))

static void gemm(int act, bool trb, int BN, const GemmArgs& a)
{
    dim3 grid((a.N + BN - 1) / BN, a.gridM ? a.gridM : (a.M + 63) / 64, a.Z);
    if (act == 1) {
        size_t shm = SMEM_BYTES(false, 128);
        cudaFuncSetAttribute(gemm_kernel<1, false, 128>, cudaFuncAttributeMaxDynamicSharedMemorySize, (int)shm);
        gemm_kernel<1, false, 128><<<grid, 256, shm>>>(a.A, a.lda, a.sAz, a.sAz2, a.B, a.ldb, a.sBz, a.sBz2,
            a.C, a.ldc, a.sCz, a.sCz2, a.zdiv, a.bias, a.sbz, a.res,
            a.M, a.N, a.Kd, a.alpha, a.idxA, a.idxC, a.cnt, a.causal);
    } else if (trb) {
        size_t shm = SMEM_BYTES(true, 128);
        cudaFuncSetAttribute(gemm_kernel<0, true, 128>, cudaFuncAttributeMaxDynamicSharedMemorySize, (int)shm);
        gemm_kernel<0, true, 128><<<grid, 256, shm>>>(a.A, a.lda, a.sAz, a.sAz2, a.B, a.ldb, a.sBz, a.sBz2,
            a.C, a.ldc, a.sCz, a.sCz2, a.zdiv, a.bias, a.sbz, a.res,
            a.M, a.N, a.Kd, a.alpha, a.idxA, a.idxC, a.cnt, a.causal);
    } else if (BN == 128) {
        size_t shm = SMEM_BYTES(false, 128);
        cudaFuncSetAttribute(gemm_kernel<0, false, 128>, cudaFuncAttributeMaxDynamicSharedMemorySize, (int)shm);
        gemm_kernel<0, false, 128><<<grid, 256, shm>>>(a.A, a.lda, a.sAz, a.sAz2, a.B, a.ldb, a.sBz, a.sBz2,
            a.C, a.ldc, a.sCz, a.sCz2, a.zdiv, a.bias, a.sbz, a.res,
            a.M, a.N, a.Kd, a.alpha, a.idxA, a.idxC, a.cnt, a.causal);
    } else {
        size_t shm = SMEM_BYTES(false, 64);
        cudaFuncSetAttribute(gemm_kernel<0, false, 64>, cudaFuncAttributeMaxDynamicSharedMemorySize, (int)shm);
        gemm_kernel<0, false, 64><<<grid, 256, shm>>>(a.A, a.lda, a.sAz, a.sAz2, a.B, a.ldb, a.sBz, a.sBz2,
            a.C, a.ldc, a.sCz, a.sCz2, a.zdiv, a.bias, a.sbz, a.res,
            a.M, a.N, a.Kd, a.alpha, a.idxA, a.idxC, a.cnt, a.causal);
    }
}

extern "C" void kernel_launch(void* const* d_in, const int* in_sizes, int n_in,
                              void* d_out, int out_size)
{
    const float* z_in  = (const float*)d_in[0];
    const float* in_w  = (const float*)d_in[1];
    const float* in_b  = (const float*)d_in[2];
    const float* ln1g  = (const float*)d_in[3];
    const float* ln1b  = (const float*)d_in[4];
    const float* wq    = (const float*)d_in[5];
    const float* bq    = (const float*)d_in[6];
    const float* wk    = (const float*)d_in[7];
    const float* bk    = (const float*)d_in[8];
    const float* wv    = (const float*)d_in[9];
    const float* bv    = (const float*)d_in[10];
    const float* wo    = (const float*)d_in[11];
    const float* bo    = (const float*)d_in[12];
    const float* ln2g  = (const float*)d_in[13];
    const float* ln2b  = (const float*)d_in[14];
    const float* gatew = (const float*)d_in[15];
    const float* ew1   = (const float*)d_in[16];
    const float* eb1   = (const float*)d_in[17];
    const float* ew2   = (const float*)d_in[18];
    const float* eb2   = (const float*)d_in[19];
    const float* outw  = (const float*)d_in[20];
    const float* outb  = (const float*)d_in[21];
    float* out = (float*)d_out;

    float* ZT = (float*)symaddr(g_zt);
    float* X  = (float*)symaddr(g_x);
    float* H  = (float*)symaddr(g_h);
    float* QKV = (float*)symaddr(g_qkv);
    float* WQKV = (float*)symaddr(g_wqkv);
    float* BQKV = (float*)symaddr(g_bqkv);
    float* Q  = QKV;
    float* Kb = QKV + (long long)TOK * DD;
    float* V  = QKV + 2LL * TOK * DD;
    float* AO = (float*)symaddr(g_ao);
    float* SC = (float*)symaddr(g_scores);
    float* HID = (float*)symaddr(g_hidden);
    float* YS = (float*)symaddr(g_yslot);
    float* CB = (float*)symaddr(g_Cb);
    float* MT = (float*)symaddr(g_Mt);
    float* BF = (float*)symaddr(g_bf);
    float* FR = (float*)symaddr(g_frames);
    int* CNT = (int*)symaddr(g_cnt);
    int* ETK = (int*)symaddr(g_etok);
    int* EAS = (int*)symaddr(g_easn);
    float* WTS = (float*)symaddr(g_wts);

    // in_projection: zt = z^T, x = zt @ in_w + in_b
    transpose_z<<<dim3(SS / 32, CIN / 32, BB), dim3(32, 8)>>>(z_in, ZT);
    {
        GemmArgs a = {ZT, CIN, 0, 0, in_w, DD, 0, 0, X, DD, 0, 0, 1,
                      in_b, 0, nullptr, TOK, DD, CIN, 1.f, 1, nullptr, nullptr, nullptr, 0, 0};
        gemm(0, false, 128, a);
    }

    for (int L = 0; L < 2; L++) {
        const size_t WSZ = (size_t)DD * DD * sizeof(float);
        cudaMemcpyAsync(WQKV,               wq + (long long)L * DD * DD, WSZ, cudaMemcpyDeviceToDevice);
        cudaMemcpyAsync(WQKV + DD * DD,     wk + (long long)L * DD * DD, WSZ, cudaMemcpyDeviceToDevice);
        cudaMemcpyAsync(WQKV + 2 * DD * DD, wv + (long long)L * DD * DD, WSZ, cudaMemcpyDeviceToDevice);
        cudaMemcpyAsync(BQKV,          bq + L * DD, DD * sizeof(float), cudaMemcpyDeviceToDevice);
        cudaMemcpyAsync(BQKV + DD,     bk + L * DD, DD * sizeof(float), cudaMemcpyDeviceToDevice);
        cudaMemcpyAsync(BQKV + 2 * DD, bv + L * DD, DD * sizeof(float), cudaMemcpyDeviceToDevice);

        ln_kernel<<<TOK, 256>>>(X, H, ln1g + L * DD, ln1b + L * DD);
        {
            GemmArgs a = {H, DD, 0, 0, WQKV, DD, (long long)DD * DD, 0,
                          QKV, DD, (long long)TOK * DD, 0, 3,
                          BQKV, DD, nullptr, TOK, DD, DD, 1.f, 3, 0, 0, 0, 0, 0};
            gemm(0, false, 128, a);
        }
        if (L == 0)
            rope_kernel<<<(TOK * (DD / 2) + 255) / 256, 256>>>(Q, Kb);

        {
            GemmArgs a = {Q, DD, HD, (long long)SS * DD,
                          Kb, DD, HD, (long long)SS * DD,
                          SC, SS, (long long)SS * SS, (long long)HH * SS * SS, HH,
                          nullptr, 0, nullptr, SS, SS, HD, 0.125f, BB * HH, 0, 0, 0, 1, 0};
            gemm(0, true, 128, a);
        }
        softmax_causal<<<dim3(SS, BB * HH), 256>>>(SC);
        {
            GemmArgs a = {SC, SS, (long long)SS * SS, (long long)HH * SS * SS,
                          V, DD, HD, (long long)SS * DD,
                          AO, DD, HD, (long long)SS * DD, HH,
                          nullptr, 0, nullptr, SS, HD, SS, 1.f, BB * HH, 0, 0, 0, 2, 0};
            gemm(0, false, 64, a);
        }
        {
            GemmArgs a = {AO, DD, 0, 0, wo + (long long)L * DD * DD, DD, 0, 0, X, DD, 0, 0, 1,
                          bo + L * DD, 0, X, TOK, DD, DD, 1.f, 1, 0, 0, 0, 0, 0};
            gemm(0, false, 128, a);
        }

        // MoE
        ln_kernel<<<TOK, 256>>>(X, H, ln2g + L * DD, ln2b + L * DD);
        zero_cnt<<<1, 32>>>(CNT);
        route_kernel<<<TOK / 8, 256>>>(H, gatew + (long long)L * DD * EE, CNT, ETK, EAS, WTS);
        {
            GemmArgs a = {H, DD, 0, 0,
                          ew1 + (long long)L * EE * DD * FF, FF, (long long)DD * FF, 0,
                          HID, FF, 0, 0, EE,
                          eb1 + (long long)L * EE * FF, FF, nullptr,
                          TOK, FF, DD, 1.f, EE, ETK, EAS, CNT, 0, TOK / 64};
            gemm(1, false, 128, a);
        }
        {
            GemmArgs a = {HID, FF, 0, 0,
                          ew2 + (long long)L * EE * FF * DD, DD, (long long)FF * DD, 0,
                          YS, DD, 0, 0, EE,
                          eb2 + (long long)L * EE * DD, DD, nullptr,
                          TOK, DD, FF, 1.f, EE, EAS, EAS, CNT, 0, TOK / 64};
            gemm(0, false, 128, a);
        }
        combine_kernel<<<(TOK * DD + 255) / 256, 256>>>(X, YS, WTS);
    }

    // out projection fused with irfft basis: frames = x @ (out_w @ Cb) + out_b @ Cb
    basis_kernel<<<(1026 * 1024 + 255) / 256, 256>>>(CB);
    {
        GemmArgs a = {outw, 2 * FB, 0, 0, CB, 1024, 0, 0, MT, 1024, 0, 0, 1,
                      nullptr, 0, nullptr, DD, 1024, 2 * FB, 1.f, 1, 0, 0, 0, 0, 0};
        gemm(0, false, 128, a);
    }
    bf_kernel<<<1, 1024>>>(outb, CB, BF);
    {
        GemmArgs a = {X, DD, 0, 0, MT, 1024, 0, 0, FR, 1024, 0, 0, 1,
                      BF, 0, nullptr, TOK, 1024, DD, 1.f, 1, 0, 0, 0, 0, 0};
        gemm(0, false, 128, a);
    }

    // windowed overlap-add + env normalize + trim
    istft_kernel<<<(BB * OUTL + 255) / 256, 256>>>(FR, out);
}

// round 9
// speedup vs baseline: 2.7350x; 1.1201x over previous
#include <cuda_runtime.h>
#include <math.h>
#include <stdint.h>

// ---------------- constants ----------------
#define BB 2
#define SS 1024
#define DD 768
#define HH 12
#define HD 64
#define EE 8
#define FF 2048
#define CIN 512
#define TOK (BB*SS)          // 2048
#define FB 513
#define PADL 384
#define OUTL 262144
#define TWO_PI_N 0.006135923151542565f   // 2*pi/1024

// ---------------- scratch (device globals; allocation-free) ----------------
__device__ float g_zt[TOK*CIN];
__device__ float g_x [TOK*DD];
__device__ float g_h [TOK*DD];
__device__ float g_qkv[3*TOK*DD];
__device__ float g_wqkv[3*DD*DD];
__device__ float g_bqkv[3*DD];
__device__ float g_ao[TOK*DD];
__device__ float g_scores[24u*1024u*1024u];
__device__ float g_hidden[4096*FF];
__device__ float g_yslot [4096*DD];
__device__ float g_Cb[1026*1024];
__device__ float g_Mt[DD*1024];
__device__ float g_bf[1024];
__device__ float g_frames[TOK*1024];
__device__ int   g_cnt[EE];
__device__ int   g_etok[EE*TOK];
__device__ int   g_easn[EE*TOK];
__device__ float g_wts[2*TOK];

// ---------------- bf16x3 helpers ----------------
// hi = bf16-truncate(f); lo = bf16-round(f - hi). Pack 2 consecutive-k into bf16x2.
__device__ __forceinline__ void pack_bf16pair(float f0, float f1, uint32_t& hi, uint32_t& lo) {
    uint32_t u0 = __float_as_uint(f0);
    uint32_t u1 = __float_as_uint(f1);
    uint32_t h;
    asm("prmt.b32 %0, %1, %2, 0x7632;" : "=r"(h) : "r"(u0), "r"(u1));
    hi = h;
    float l0 = f0 - __uint_as_float(u0 & 0xFFFF0000u);
    float l1 = f1 - __uint_as_float(u1 & 0xFFFF0000u);
    asm("cvt.rn.bf16x2.f32 %0, %1, %2;" : "=r"(lo) : "f"(l1), "f"(l0));
}
__device__ __forceinline__ void mma_bf16(float* c, const uint32_t* a, const uint32_t* b) {
    asm volatile(
        "mma.sync.aligned.m16n8k16.row.col.f32.bf16.bf16.f32 "
        "{%0,%1,%2,%3}, {%4,%5,%6,%7}, {%8,%9}, {%0,%1,%2,%3};"
        : "+f"(c[0]), "+f"(c[1]), "+f"(c[2]), "+f"(c[3])
        : "r"(a[0]), "r"(a[1]), "r"(a[2]), "r"(a[3]), "r"(b[0]), "r"(b[1]));
}

// ---------------- register-staged tensor-core GEMM (3xBF16, 2-stage) ----------------
// Tile: 64(M) x BN(N), K-step 16. 8 warps as 2(M) x 4(N); warp = 32 x BN/4.
#define APK_LD 12   // packed A row stride (uint32; 8 pairs + pad)
#define APK_SZ (64 * APK_LD)

template<int ACT, bool TRB, int BN>
__global__ __launch_bounds__(256, 2)
void gemm_kernel(const float* __restrict__ A, int lda, long long sAz, long long sAz2,
                 const float* __restrict__ B, int ldb, long long sBz, long long sBz2,
                 float* __restrict__ C, int ldc, long long sCz, long long sCz2,
                 int zdiv,
                 const float* __restrict__ bias, long long sbz,
                 const float* __restrict__ res,
                 int M, int N, int Kd, float alpha,
                 const int* __restrict__ idxA, const int* __restrict__ idxC,
                 const int* __restrict__ cnt, int causal)
{
    constexpr int BPK_LD = TRB ? APK_LD : (BN + 8);
    constexpr int BPK_SZ = TRB ? (BN * APK_LD) : (8 * (BN + 8));
    constexpr int STAGE  = 2 * APK_SZ + 2 * BPK_SZ;   // uint32 per stage
    constexpr int BJ = BN / 32;

    int z = blockIdx.z;
    int z1 = z / zdiv, z0 = z - z1 * zdiv;
    if (cnt) M = cnt[z];
    int m0 = blockIdx.y * 64, n0 = blockIdx.x * BN;
    if (m0 >= M) return;
    if (causal == 1 && n0 > m0 + 63) return;
    if (causal == 2) Kd = min(Kd, m0 + 64);   // AV: keys beyond row block are zero
    A += (long long)z0 * sAz + (long long)z1 * sAz2;
    B += (long long)z0 * sBz + (long long)z1 * sBz2;
    C += (long long)z0 * sCz + (long long)z1 * sCz2;
    if (bias) bias += (long long)z * sbz;
    if (res)  res  += (long long)z0 * sCz + (long long)z1 * sCz2;
    const int* iA = idxA ? idxA + z * TOK : nullptr;
    const int* iC = idxC ? idxC + z * TOK : nullptr;

    extern __shared__ uint32_t smem[];

    int tid = threadIdx.x;
    int lane = tid & 31, wid = tid >> 5;
    int wm = wid >> 2, wn = wid & 3;
    int lm = lane >> 2, lk = lane & 3;

    float acc[2][BJ][4];
#pragma unroll
    for (int i = 0; i < 2; i++)
#pragma unroll
        for (int j = 0; j < BJ; j++)
#pragma unroll
            for (int r = 0; r < 4; r++) acc[i][j][r] = 0.f;

    const bool fastA = ((lda & 3) == 0) && ((Kd & 15) == 0);
    const bool fastB = ((ldb & 3) == 0) && (TRB ? ((Kd & 15) == 0) : true);

    // per-thread register staging
    float rA[4];
    float rB[8];
    // A slice: row mmA = tid>>2, cols 4*qA .. 4*qA+3
    int mmA = tid >> 2, qA = tid & 3;
    int raA = -1;
    {
        int gm = m0 + mmA;
        if (gm < M) raA = iA ? iA[gm] : gm;
    }
    // B slice (non-TRB): slot covers rows 2p,2p+1 at col group nq (BN/4 groups)
    int pB = 0, nqB = 0;
    bool bAct = true;
    if (!TRB) {
        if (BN == 128) { pB = tid >> 5; nqB = tid & 31; }
        else { pB = tid >> 4; nqB = tid & 15; bAct = (tid < 128); }
    }

    auto load_regs = [&](int k0) {
        // ---- A ----
        if (raA >= 0) {
            if (fastA) {
                const float4 v = *(const float4*)(A + (long long)raA * lda + k0 + 4 * qA);
                rA[0] = v.x; rA[1] = v.y; rA[2] = v.z; rA[3] = v.w;
            } else {
#pragma unroll
                for (int j = 0; j < 4; j++) {
                    int gk = k0 + 4 * qA + j;
                    rA[j] = (gk < Kd) ? A[(long long)raA * lda + gk] : 0.f;
                }
            }
        } else {
            rA[0] = rA[1] = rA[2] = rA[3] = 0.f;
        }
        // ---- B ----
        if (!TRB) {
            if (bAct) {
                int gk0 = k0 + 2 * pB;
                int nb = n0 + 4 * nqB;
#pragma unroll
                for (int r = 0; r < 2; r++) {
                    int gk = gk0 + r;
                    if (gk < Kd) {
                        if (fastB) {
                            const float4 v = *(const float4*)(B + (long long)gk * ldb + nb);
                            rB[4 * r + 0] = v.x; rB[4 * r + 1] = v.y;
                            rB[4 * r + 2] = v.z; rB[4 * r + 3] = v.w;
                        } else {
#pragma unroll
                            for (int j = 0; j < 4; j++)
                                rB[4 * r + j] = B[(long long)gk * ldb + nb + j];
                        }
                    } else {
                        rB[4 * r + 0] = rB[4 * r + 1] = rB[4 * r + 2] = rB[4 * r + 3] = 0.f;
                    }
                }
            }
        } else {
#pragma unroll
            for (int it = 0; it < BN / 64; it++) {
                int lin = tid + it * 256;
                int nn = lin >> 2, q = lin & 3;
                int gn = n0 + nn;
                if (gn < N) {
                    if (fastB) {
                        const float4 v = *(const float4*)(B + (long long)gn * ldb + k0 + 4 * q);
                        rB[4 * it + 0] = v.x; rB[4 * it + 1] = v.y;
                        rB[4 * it + 2] = v.z; rB[4 * it + 3] = v.w;
                    } else {
#pragma unroll
                        for (int j = 0; j < 4; j++) {
                            int gk = k0 + 4 * q + j;
                            rB[4 * it + j] = (gk < Kd) ? B[(long long)gn * ldb + gk] : 0.f;
                        }
                    }
                } else {
                    rB[4 * it + 0] = rB[4 * it + 1] = rB[4 * it + 2] = rB[4 * it + 3] = 0.f;
                }
            }
        }
    };

    auto convert_stage = [&](int s) {
        uint32_t* Aph = smem + s * STAGE;
        uint32_t* Apl = Aph + APK_SZ;
        uint32_t* Bph = Apl + APK_SZ;
        uint32_t* Bpl = Bph + BPK_SZ;
        {
            uint32_t hi, lo;
            pack_bf16pair(rA[0], rA[1], hi, lo);
            Aph[mmA * APK_LD + 2 * qA] = hi;
            Apl[mmA * APK_LD + 2 * qA] = lo;
            pack_bf16pair(rA[2], rA[3], hi, lo);
            Aph[mmA * APK_LD + 2 * qA + 1] = hi;
            Apl[mmA * APK_LD + 2 * qA + 1] = lo;
        }
        if (!TRB) {
            if (bAct) {
#pragma unroll
                for (int j = 0; j < 4; j++) {
                    uint32_t hi, lo;
                    pack_bf16pair(rB[j], rB[4 + j], hi, lo);
                    Bph[pB * BPK_LD + 4 * nqB + j] = hi;
                    Bpl[pB * BPK_LD + 4 * nqB + j] = lo;
                }
            }
        } else {
#pragma unroll
            for (int it = 0; it < BN / 64; it++) {
                int lin = tid + it * 256;
                int nn = lin >> 2, q = lin & 3;
                uint32_t hi, lo;
                pack_bf16pair(rB[4 * it + 0], rB[4 * it + 1], hi, lo);
                Bph[nn * BPK_LD + 2 * q] = hi;
                Bpl[nn * BPK_LD + 2 * q] = lo;
                pack_bf16pair(rB[4 * it + 2], rB[4 * it + 3], hi, lo);
                Bph[nn * BPK_LD + 2 * q + 1] = hi;
                Bpl[nn * BPK_LD + 2 * q + 1] = lo;
            }
        }
    };

    auto compute = [&](int s) {
        const uint32_t* Aph = smem + s * STAGE;
        const uint32_t* Apl = Aph + APK_SZ;
        const uint32_t* Bph = Apl + APK_SZ;
        const uint32_t* Bpl = Bph + BPK_SZ;
        uint32_t ah[2][4], al[2][4];
#pragma unroll
        for (int i = 0; i < 2; i++) {
            int r0 = wm * 32 + i * 16 + lm;
            ah[i][0] = Aph[r0 * APK_LD + lk];
            ah[i][1] = Aph[(r0 + 8) * APK_LD + lk];
            ah[i][2] = Aph[r0 * APK_LD + lk + 4];
            ah[i][3] = Aph[(r0 + 8) * APK_LD + lk + 4];
            al[i][0] = Apl[r0 * APK_LD + lk];
            al[i][1] = Apl[(r0 + 8) * APK_LD + lk];
            al[i][2] = Apl[r0 * APK_LD + lk + 4];
            al[i][3] = Apl[(r0 + 8) * APK_LD + lk + 4];
        }
#pragma unroll
        for (int j = 0; j < BJ; j++) {
            int bn = wn * (BN / 4) + j * 8 + lm;
            uint32_t bh[2], bl[2];
            if (!TRB) {
                bh[0] = Bph[lk * BPK_LD + bn];
                bh[1] = Bph[(lk + 4) * BPK_LD + bn];
                bl[0] = Bpl[lk * BPK_LD + bn];
                bl[1] = Bpl[(lk + 4) * BPK_LD + bn];
            } else {
                bh[0] = Bph[bn * BPK_LD + lk];
                bh[1] = Bph[bn * BPK_LD + lk + 4];
                bl[0] = Bpl[bn * BPK_LD + lk];
                bl[1] = Bpl[bn * BPK_LD + lk + 4];
            }
            // hh + lh + hl (ll dropped, ~2^-16)
            mma_bf16(acc[0][j], ah[0], bh);
            mma_bf16(acc[1][j], ah[1], bh);
            mma_bf16(acc[0][j], al[0], bh);
            mma_bf16(acc[1][j], al[1], bh);
            mma_bf16(acc[0][j], ah[0], bl);
            mma_bf16(acc[1][j], ah[1], bl);
        }
    };

    int nk = (Kd + 15) >> 4;
    // prologue
    load_regs(0);
    convert_stage(0);
    if (nk > 1) load_regs(16);
    __syncthreads();
    for (int i = 0; i < nk; i++) {
        compute(i & 1);
        if (i + 1 < nk) {
            convert_stage((i + 1) & 1);
            if (i + 2 < nk) load_regs((i + 2) * 16);
        }
        __syncthreads();
    }

    // ---- epilogue ----
#pragma unroll
    for (int i = 0; i < 2; i++) {
#pragma unroll
        for (int r2 = 0; r2 < 2; r2++) {
            int gm = m0 + wm * 32 + i * 16 + lm + r2 * 8;
            if (gm >= M) continue;
            int rc = iC ? iC[gm] : gm;
            float* crow = C + (long long)rc * ldc;
            const float* rrow = res ? res + (long long)rc * ldc : nullptr;
#pragma unroll
            for (int j = 0; j < BJ; j++) {
#pragma unroll
                for (int c2 = 0; c2 < 2; c2++) {
                    int gn = n0 + wn * (BN / 4) + j * 8 + lk * 2 + c2;
                    if (gn >= N) continue;
                    float v = acc[i][j][r2 * 2 + c2] * alpha;
                    if (bias) v += bias[gn];
                    if (ACT == 1) {
                        float x = v;
                        float t = tanhf(0.7978845608028654f * (x + 0.044715f * x * x * x));
                        v = 0.5f * x * (1.f + t);
                    }
                    if (rrow) v += rrow[gn];
                    crow[gn] = v;
                }
            }
        }
    }
}

// ---------------- small kernels ----------------
__global__ void transpose_z(const float* __restrict__ z, float* __restrict__ zt) {
    __shared__ float tile[32][33];
    int b = blockIdx.z;
    int l0 = blockIdx.x * 32, c0 = blockIdx.y * 32;
    int x = threadIdx.x, y = threadIdx.y;
    for (int i = y; i < 32; i += 8)
        tile[i][x] = z[b * CIN * SS + (c0 + i) * SS + l0 + x];
    __syncthreads();
    for (int i = y; i < 32; i += 8)
        zt[b * SS * CIN + (long long)(l0 + i) * CIN + c0 + x] = tile[x][i];
}

__global__ void ln_kernel(const float* __restrict__ x, float* __restrict__ y,
                          const float* __restrict__ g, const float* __restrict__ b) {
    int row = blockIdx.x;
    const float* xr = x + (long long)row * DD;
    __shared__ float sh[32];
    __shared__ float sh2[32];
    float s = 0.f, s2 = 0.f;
    for (int d = threadIdx.x; d < DD; d += 256) { float v = xr[d]; s += v; s2 += v * v; }
    int lane = threadIdx.x & 31, wid = threadIdx.x >> 5;
    for (int o = 16; o; o >>= 1) { s += __shfl_xor_sync(~0u, s, o); s2 += __shfl_xor_sync(~0u, s2, o); }
    if (lane == 0) { sh[wid] = s; sh2[wid] = s2; }
    __syncthreads();
    if (wid == 0) {
        s  = (lane < 8) ? sh[lane]  : 0.f;
        s2 = (lane < 8) ? sh2[lane] : 0.f;
        for (int o = 16; o; o >>= 1) { s += __shfl_xor_sync(~0u, s, o); s2 += __shfl_xor_sync(~0u, s2, o); }
        if (lane == 0) { sh[0] = s; sh2[0] = s2; }
    }
    __syncthreads();
    float mean = sh[0] / DD;
    float var  = sh2[0] / DD - mean * mean;
    float inv = rsqrtf(var + 1e-5f);
    float* yr = y + (long long)row * DD;
    for (int d = threadIdx.x; d < DD; d += 256)
        yr[d] = (xr[d] - mean) * inv * g[d] + b[d];
}

__global__ void rope_kernel(float* __restrict__ q, float* __restrict__ k) {
    int idx = blockIdx.x * blockDim.x + threadIdx.x;
    if (idx >= TOK * (DD / 2)) return;
    int t = idx / (DD / 2), j = idx - t * (DD / 2);
    int s = t & (SS - 1);
    float freq = __expf(-9.210340371976184f * ((float)j / 384.f));
    float ang = (float)s * freq;
    float c, sn; sincosf(ang, &sn, &c);
    {
        float* p = q + (long long)t * DD + 2 * j;
        float a = p[0], b = p[1];
        p[0] = a * c - b * sn; p[1] = a * sn + b * c;
    }
    {
        float* p = k + (long long)t * DD + 2 * j;
        float a = p[0], b = p[1];
        p[0] = a * c - b * sn; p[1] = a * sn + b * c;
    }
}

__global__ void softmax_causal(float* __restrict__ sc) {
    int z = blockIdx.y, r = blockIdx.x;
    float* row = sc + ((long long)z << 20) + (long long)r * 1024;
    int n = r + 1;
    __shared__ float sh[32];
    int lane = threadIdx.x & 31, wid = threadIdx.x >> 5;
    float mx = -1e30f;
    for (int j = threadIdx.x; j < n; j += 256) mx = fmaxf(mx, row[j]);
    for (int o = 16; o; o >>= 1) mx = fmaxf(mx, __shfl_xor_sync(~0u, mx, o));
    if (lane == 0) sh[wid] = mx;
    __syncthreads();
    if (wid == 0) {
        mx = (lane < 8) ? sh[lane] : -1e30f;
        for (int o = 16; o; o >>= 1) mx = fmaxf(mx, __shfl_xor_sync(~0u, mx, o));
        if (lane == 0) sh[0] = mx;
    }
    __syncthreads();
    mx = sh[0];
    __syncthreads();
    float s = 0.f;
    for (int j = threadIdx.x; j < n; j += 256) s += __expf(row[j] - mx);
    for (int o = 16; o; o >>= 1) s += __shfl_xor_sync(~0u, s, o);
    if (lane == 0) sh[wid] = s;
    __syncthreads();
    if (wid == 0) {
        s = (lane < 8) ? sh[lane] : 0.f;
        for (int o = 16; o; o >>= 1) s += __shfl_xor_sync(~0u, s, o);
        if (lane == 0) sh[0] = s;
    }
    __syncthreads();
    float inv = 1.f / sh[0];
    for (int j = threadIdx.x; j < 1024; j += 256)
        row[j] = (j < n) ? __expf(row[j] - mx) * inv : 0.f;
}

__global__ void zero_cnt(int* c) { if (threadIdx.x < EE) c[threadIdx.x] = 0; }

__global__ void route_kernel(const float* __restrict__ h, const float* __restrict__ gw,
                             int* cnt, int* etok, int* easn, float* wts) {
    int w = (blockIdx.x * blockDim.x + threadIdx.x) >> 5;
    int lane = threadIdx.x & 31;
    if (w >= TOK) return;
    const float* hr = h + (long long)w * DD;
    float lg[EE];
#pragma unroll
    for (int e = 0; e < EE; e++) {
        float s = 0.f;
        for (int d = lane; d < DD; d += 32) s += hr[d] * gw[d * EE + e];
        for (int o = 16; o; o >>= 1) s += __shfl_xor_sync(~0u, s, o);
        lg[e] = s;
    }
    if (lane == 0) {
        int e0 = 0;
        for (int e = 1; e < EE; e++) if (lg[e] > lg[e0]) e0 = e;
        int e1 = -1;
        for (int e = 0; e < EE; e++) { if (e == e0) continue; if (e1 < 0 || lg[e] > lg[e1]) e1 = e; }
        float x1 = __expf(lg[e1] - lg[e0]);
        float den = 1.f + x1;
        float w0 = 1.f / den, w1 = x1 / den;
        int s0 = atomicAdd(&cnt[e0], 1);
        etok[e0 * TOK + s0] = w; easn[e0 * TOK + s0] = 2 * w;
        int s1 = atomicAdd(&cnt[e1], 1);
        etok[e1 * TOK + s1] = w; easn[e1 * TOK + s1] = 2 * w + 1;
        wts[2 * w] = w0; wts[2 * w + 1] = w1;
    }
}

__global__ void combine_kernel(float* __restrict__ x, const float* __restrict__ ys,
                               const float* __restrict__ wts) {
    int idx = blockIdx.x * blockDim.x + threadIdx.x;
    if (idx >= TOK * DD) return;
    int t = idx / DD, d = idx - t * DD;
    x[idx] += wts[2 * t] * ys[(long long)(2 * t) * DD + d]
            + wts[2 * t + 1] * ys[(long long)(2 * t + 1) * DD + d];
}

__global__ void basis_kernel(float* __restrict__ Cb) {
    int idx = blockIdx.x * blockDim.x + threadIdx.x;
    if (idx >= 1026 * 1024) return;
    int j = idx >> 10, n = idx & 1023;
    const float invN = 1.f / 1024.f;
    float v;
    if (j == 0) v = invN;
    else if (j <= 511) { int m = (j * n) & 1023; v = 2.f * invN * cosf(m * TWO_PI_N); }
    else if (j == 512) v = invN * ((n & 1) ? -1.f : 1.f);
    else if (j == 513 || j == 1025) v = 0.f;
    else { int kk = j - 513; int m = (kk * n) & 1023; v = -2.f * invN * sinf(m * TWO_PI_N); }
    Cb[idx] = v;
}

__global__ void bf_kernel(const float* __restrict__ ob, const float* __restrict__ Cb,
                          float* __restrict__ bf) {
    int n = threadIdx.x;
    float s = 0.f;
    for (int j = 0; j < 1026; j++) s += ob[j] * Cb[j * 1024 + n];
    bf[n] = s;
}

__global__ void istft_kernel(const float* __restrict__ frames, float* __restrict__ out) {
    int idx = blockIdx.x * blockDim.x + threadIdx.x;
    if (idx >= BB * OUTL) return;
    int b = idx / OUTL, i = idx - b * OUTL;
    int ip = i + PADL;
    int tmin = (ip >= 1024) ? ((ip - 768) >> 8) : 0;
    int tmax = min(1023, ip >> 8);
    float acc = 0.f, env = 0.f;
    for (int t = tmin; t <= tmax; t++) {
        int n = ip - (t << 8);
        float w = 0.5f * (1.f - cosf(n * TWO_PI_N));
        acc += frames[((long long)(b * 1024 + t) << 10) + n] * w;
        env += w * w;
    }
    out[idx] = acc / env;
}

// ---------------- host side ----------------
static void* symaddr(const void* sym) {
    void* p = nullptr;
    cudaGetSymbolAddress(&p, sym);
    return p;
}

struct GemmArgs {
    const float* A; int lda; long long sAz, sAz2;
    const float* B; int ldb; long long sBz, sBz2;
    float* C; int ldc; long long sCz, sCz2;
    int zdiv;
    const float* bias; long long sbz; const float* res;
    int M, N, Kd; float alpha; int Z;
    const int* idxA; const int* idxC; const int* cnt;
    int causal; int gridM;
};

#define BPK_SZH(TRB, BN) ((TRB) ? ((BN) * APK_LD) : (8 * ((BN) + 8)))
#define SMEM_BYTES(TRB, BN) (4 * 2 * (2 * APK_SZ + 2 * BPK_SZH(TRB, BN)))

static void gemm(int act, bool trb, int BN, const GemmArgs& a)
{
    dim3 grid((a.N + BN - 1) / BN, a.gridM ? a.gridM : (a.M + 63) / 64, a.Z);
    if (act == 1) {
        size_t shm = SMEM_BYTES(false, 128);
        cudaFuncSetAttribute(gemm_kernel<1, false, 128>, cudaFuncAttributeMaxDynamicSharedMemorySize, (int)shm);
        gemm_kernel<1, false, 128><<<grid, 256, shm>>>(a.A, a.lda, a.sAz, a.sAz2, a.B, a.ldb, a.sBz, a.sBz2,
            a.C, a.ldc, a.sCz, a.sCz2, a.zdiv, a.bias, a.sbz, a.res,
            a.M, a.N, a.Kd, a.alpha, a.idxA, a.idxC, a.cnt, a.causal);
    } else if (trb) {
        size_t shm = SMEM_BYTES(true, 128);
        cudaFuncSetAttribute(gemm_kernel<0, true, 128>, cudaFuncAttributeMaxDynamicSharedMemorySize, (int)shm);
        gemm_kernel<0, true, 128><<<grid, 256, shm>>>(a.A, a.lda, a.sAz, a.sAz2, a.B, a.ldb, a.sBz, a.sBz2,
            a.C, a.ldc, a.sCz, a.sCz2, a.zdiv, a.bias, a.sbz, a.res,
            a.M, a.N, a.Kd, a.alpha, a.idxA, a.idxC, a.cnt, a.causal);
    } else if (BN == 128) {
        size_t shm = SMEM_BYTES(false, 128);
        cudaFuncSetAttribute(gemm_kernel<0, false, 128>, cudaFuncAttributeMaxDynamicSharedMemorySize, (int)shm);
        gemm_kernel<0, false, 128><<<grid, 256, shm>>>(a.A, a.lda, a.sAz, a.sAz2, a.B, a.ldb, a.sBz, a.sBz2,
            a.C, a.ldc, a.sCz, a.sCz2, a.zdiv, a.bias, a.sbz, a.res,
            a.M, a.N, a.Kd, a.alpha, a.idxA, a.idxC, a.cnt, a.causal);
    } else {
        size_t shm = SMEM_BYTES(false, 64);
        cudaFuncSetAttribute(gemm_kernel<0, false, 64>, cudaFuncAttributeMaxDynamicSharedMemorySize, (int)shm);
        gemm_kernel<0, false, 64><<<grid, 256, shm>>>(a.A, a.lda, a.sAz, a.sAz2, a.B, a.ldb, a.sBz, a.sBz2,
            a.C, a.ldc, a.sCz, a.sCz2, a.zdiv, a.bias, a.sbz, a.res,
            a.M, a.N, a.Kd, a.alpha, a.idxA, a.idxC, a.cnt, a.causal);
    }
}

extern "C" void kernel_launch(void* const* d_in, const int* in_sizes, int n_in,
                              void* d_out, int out_size)
{
    const float* z_in  = (const float*)d_in[0];
    const float* in_w  = (const float*)d_in[1];
    const float* in_b  = (const float*)d_in[2];
    const float* ln1g  = (const float*)d_in[3];
    const float* ln1b  = (const float*)d_in[4];
    const float* wq    = (const float*)d_in[5];
    const float* bq    = (const float*)d_in[6];
    const float* wk    = (const float*)d_in[7];
    const float* bk    = (const float*)d_in[8];
    const float* wv    = (const float*)d_in[9];
    const float* bv    = (const float*)d_in[10];
    const float* wo    = (const float*)d_in[11];
    const float* bo    = (const float*)d_in[12];
    const float* ln2g  = (const float*)d_in[13];
    const float* ln2b  = (const float*)d_in[14];
    const float* gatew = (const float*)d_in[15];
    const float* ew1   = (const float*)d_in[16];
    const float* eb1   = (const float*)d_in[17];
    const float* ew2   = (const float*)d_in[18];
    const float* eb2   = (const float*)d_in[19];
    const float* outw  = (const float*)d_in[20];
    const float* outb  = (const float*)d_in[21];
    float* out = (float*)d_out;

    float* ZT = (float*)symaddr(g_zt);
    float* X  = (float*)symaddr(g_x);
    float* H  = (float*)symaddr(g_h);
    float* QKV = (float*)symaddr(g_qkv);
    float* WQKV = (float*)symaddr(g_wqkv);
    float* BQKV = (float*)symaddr(g_bqkv);
    float* Q  = QKV;
    float* Kb = QKV + (long long)TOK * DD;
    float* V  = QKV + 2LL * TOK * DD;
    float* AO = (float*)symaddr(g_ao);
    float* SC = (float*)symaddr(g_scores);
    float* HID = (float*)symaddr(g_hidden);
    float* YS = (float*)symaddr(g_yslot);
    float* CB = (float*)symaddr(g_Cb);
    float* MT = (float*)symaddr(g_Mt);
    float* BF = (float*)symaddr(g_bf);
    float* FR = (float*)symaddr(g_frames);
    int* CNT = (int*)symaddr(g_cnt);
    int* ETK = (int*)symaddr(g_etok);
    int* EAS = (int*)symaddr(g_easn);
    float* WTS = (float*)symaddr(g_wts);

    // in_projection: zt = z^T, x = zt @ in_w + in_b
    transpose_z<<<dim3(SS / 32, CIN / 32, BB), dim3(32, 8)>>>(z_in, ZT);
    {
        GemmArgs a = {ZT, CIN, 0, 0, in_w, DD, 0, 0, X, DD, 0, 0, 1,
                      in_b, 0, nullptr, TOK, DD, CIN, 1.f, 1, nullptr, nullptr, nullptr, 0, 0};
        gemm(0, false, 128, a);
    }

    for (int L = 0; L < 2; L++) {
        const size_t WSZ = (size_t)DD * DD * sizeof(float);
        cudaMemcpyAsync(WQKV,               wq + (long long)L * DD * DD, WSZ, cudaMemcpyDeviceToDevice);
        cudaMemcpyAsync(WQKV + DD * DD,     wk + (long long)L * DD * DD, WSZ, cudaMemcpyDeviceToDevice);
        cudaMemcpyAsync(WQKV + 2 * DD * DD, wv + (long long)L * DD * DD, WSZ, cudaMemcpyDeviceToDevice);
        cudaMemcpyAsync(BQKV,          bq + L * DD, DD * sizeof(float), cudaMemcpyDeviceToDevice);
        cudaMemcpyAsync(BQKV + DD,     bk + L * DD, DD * sizeof(float), cudaMemcpyDeviceToDevice);
        cudaMemcpyAsync(BQKV + 2 * DD, bv + L * DD, DD * sizeof(float), cudaMemcpyDeviceToDevice);

        ln_kernel<<<TOK, 256>>>(X, H, ln1g + L * DD, ln1b + L * DD);
        {
            GemmArgs a = {H, DD, 0, 0, WQKV, DD, (long long)DD * DD, 0,
                          QKV, DD, (long long)TOK * DD, 0, 3,
                          BQKV, DD, nullptr, TOK, DD, DD, 1.f, 3, 0, 0, 0, 0, 0};
            gemm(0, false, 128, a);
        }
        if (L == 0)
            rope_kernel<<<(TOK * (DD / 2) + 255) / 256, 256>>>(Q, Kb);

        {
            GemmArgs a = {Q, DD, HD, (long long)SS * DD,
                          Kb, DD, HD, (long long)SS * DD,
                          SC, SS, (long long)SS * SS, (long long)HH * SS * SS, HH,
                          nullptr, 0, nullptr, SS, SS, HD, 0.125f, BB * HH, 0, 0, 0, 1, 0};
            gemm(0, true, 128, a);
        }
        softmax_causal<<<dim3(SS, BB * HH), 256>>>(SC);
        {
            GemmArgs a = {SC, SS, (long long)SS * SS, (long long)HH * SS * SS,
                          V, DD, HD, (long long)SS * DD,
                          AO, DD, HD, (long long)SS * DD, HH,
                          nullptr, 0, nullptr, SS, HD, SS, 1.f, BB * HH, 0, 0, 0, 2, 0};
            gemm(0, false, 64, a);
        }
        {
            GemmArgs a = {AO, DD, 0, 0, wo + (long long)L * DD * DD, DD, 0, 0, X, DD, 0, 0, 1,
                          bo + L * DD, 0, X, TOK, DD, DD, 1.f, 1, 0, 0, 0, 0, 0};
            gemm(0, false, 128, a);
        }

        // MoE
        ln_kernel<<<TOK, 256>>>(X, H, ln2g + L * DD, ln2b + L * DD);
        zero_cnt<<<1, 32>>>(CNT);
        route_kernel<<<TOK / 8, 256>>>(H, gatew + (long long)L * DD * EE, CNT, ETK, EAS, WTS);
        {
            GemmArgs a = {H, DD, 0, 0,
                          ew1 + (long long)L * EE * DD * FF, FF, (long long)DD * FF, 0,
                          HID, FF, 0, 0, EE,
                          eb1 + (long long)L * EE * FF, FF, nullptr,
                          TOK, FF, DD, 1.f, EE, ETK, EAS, CNT, 0, TOK / 64};
            gemm(1, false, 128, a);
        }
        {
            GemmArgs a = {HID, FF, 0, 0,
                          ew2 + (long long)L * EE * FF * DD, DD, (long long)FF * DD, 0,
                          YS, DD, 0, 0, EE,
                          eb2 + (long long)L * EE * DD, DD, nullptr,
                          TOK, DD, FF, 1.f, EE, EAS, EAS, CNT, 0, TOK / 64};
            gemm(0, false, 128, a);
        }
        combine_kernel<<<(TOK * DD + 255) / 256, 256>>>(X, YS, WTS);
    }

    // out projection fused with irfft basis: frames = x @ (out_w @ Cb) + out_b @ Cb
    basis_kernel<<<(1026 * 1024 + 255) / 256, 256>>>(CB);
    {
        GemmArgs a = {outw, 2 * FB, 0, 0, CB, 1024, 0, 0, MT, 1024, 0, 0, 1,
                      nullptr, 0, nullptr, DD, 1024, 2 * FB, 1.f, 1, 0, 0, 0, 0, 0};
        gemm(0, false, 128, a);
    }
    bf_kernel<<<1, 1024>>>(outb, CB, BF);
    {
        GemmArgs a = {X, DD, 0, 0, MT, 1024, 0, 0, FR, 1024, 0, 0, 1,
                      BF, 0, nullptr, TOK, 1024, DD, 1.f, 1, 0, 0, 0, 0, 0};
        gemm(0, false, 128, a);
    }

    // windowed overlap-add + env normalize + trim
    istft_kernel<<<(BB * OUTL + 255) / 256, 256>>>(FR, out);
}